// round 7
// baseline (speedup 1.0000x reference)
#include <cuda_runtime.h>
#include <cuda_bf16.h>
#include <cstdint>

// ---------------------------------------------------------------------------
// LightweightSelfAttention  (B=2, C=512, H=W=64, heads=8, dh=64)
// All-tcgen05, bf16 2-way split, software-pipelined.
// R7: GEMM double-buffer uses TWO mbarriers (parity-overrun deadlock fix).
// ---------------------------------------------------------------------------

#if defined(__CUDA_ARCH_FEAT_SM103_ALL) || defined(__CUDA_ARCH_FEAT_SM100_ALL)
#define HAS_TC 1
#else
#define HAS_TC 0
#endif

#define BATCH 2
#define CDIM 512
#define HEADS 8
#define DH 64
#define NPIX 4096
#define TOTAL (BATCH*CDIM*NPIX)
#define QKD 1024

typedef unsigned short u16;
typedef unsigned long long u64;

__device__ float g_y[BATCH * CDIM * NPIX];
__device__ u16 g_ythi[BATCH * NPIX * CDIM];
__device__ u16 g_ytlo[BATCH * NPIX * CDIM];
__device__ u16 g_whi[3 * CDIM * CDIM];
__device__ u16 g_wlo[3 * CDIM * CDIM];
__device__ u16 g_pwhi[CDIM * CDIM];
__device__ u16 g_pwlo[CDIM * CDIM];
__device__ u16 g_qkthi[BATCH * NPIX * QKD];
__device__ u16 g_qktlo[BATCH * NPIX * QKD];
__device__ u16 g_vthi[BATCH * CDIM * NPIX];
__device__ u16 g_vtlo[BATCH * CDIM * NPIX];
__device__ u16 g_othi[BATCH * NPIX * CDIM];
__device__ u16 g_otlo[BATCH * NPIX * CDIM];

#define ATT_SCALE_L2E 0.18033688f   /* 0.125 * log2(e) */

// ---------------- helpers --------------------------------------------------
__device__ __forceinline__ uint32_t smem_u32(const void* p) {
    uint32_t a;
    asm("{ .reg .u64 t; cvta.to.shared.u64 t, %1; cvt.u32.u64 %0, t; }"
        : "=r"(a) : "l"(p));
    return a;
}
__device__ __forceinline__ u16 f2bf(float x) {
    return __bfloat16_as_ushort(__float2bfloat16_rn(x));
}
__device__ __forceinline__ float bf2f(u16 u) {
    return __bfloat162float(__ushort_as_bfloat16(u));
}
__device__ __forceinline__ float ex2f(float x) {
    float y; asm("ex2.approx.ftz.f32 %0, %1;" : "=f"(y) : "f"(x)); return y;
}
#define SWZ(o) ((o) ^ (((o) >> 3) & 0x70))

#if HAS_TC
__device__ __forceinline__ unsigned elect1() {
    unsigned p;
    asm volatile("{\n\t.reg .pred p;\n\telect.sync _|p, 0xFFFFFFFF;\n\t"
                 "selp.b32 %0, 1, 0, p;\n\t}" : "=r"(p));
    return p;
}
__device__ __forceinline__ void mma_ss(uint32_t d, u64 a, u64 b, uint32_t id, uint32_t en) {
    asm volatile("{\n\t.reg .pred p;\n\tsetp.ne.u32 p, %5, 0;\n\t"
        "tcgen05.mma.cta_group::1.kind::f16 [%0], %1, %2, %3, {%4,%4,%4,%4}, p;\n\t}"
        :: "r"(d), "l"(a), "l"(b), "r"(id), "r"(0u), "r"(en) : "memory");
}
__device__ __forceinline__ void tc_commit(uint32_t mbar) {
    asm volatile("tcgen05.commit.cta_group::1.mbarrier::arrive::one.shared::cluster.b64 [%0];"
                 :: "r"(mbar) : "memory");
}
__device__ __forceinline__ void mbar_init1(uint32_t mbar) {
    asm volatile("mbarrier.init.shared.b64 [%0], %1;" :: "r"(mbar), "r"(1u) : "memory");
}
__device__ __forceinline__ void mbar_wait(uint32_t mbar, uint32_t ph) {
    asm volatile("{\n\t.reg .pred P1;\n\tLAB1_%=:\n\t"
        "mbarrier.try_wait.parity.acquire.cta.shared::cta.b64 P1, [%0], %1, 0x989680;\n\t"
        "@P1 bra.uni LAB2_%=;\n\tbra.uni LAB1_%=;\n\tLAB2_%=:\n\t}"
        :: "r"(mbar), "r"(ph) : "memory");
}
#define TCF_AFTER()  asm volatile("tcgen05.fence::after_thread_sync;" ::: "memory")
#define FPROXY()     asm volatile("fence.proxy.async.shared::cta;" ::: "memory")
#define TC_WAIT_LD() asm volatile("tcgen05.wait::ld.sync.aligned;" ::: "memory")

#define LDX32(r, ta) \
    asm volatile("tcgen05.ld.sync.aligned.32x32b.x32.b32 " \
        "{%0, %1, %2, %3, %4, %5, %6, %7, %8, %9, %10, %11, %12, %13, %14, %15, " \
        " %16, %17, %18, %19, %20, %21, %22, %23, %24, %25, %26, %27, %28, %29, %30, %31}, [%32];" \
        : "=r"((r)[0]),  "=r"((r)[1]),  "=r"((r)[2]),  "=r"((r)[3]), \
          "=r"((r)[4]),  "=r"((r)[5]),  "=r"((r)[6]),  "=r"((r)[7]), \
          "=r"((r)[8]),  "=r"((r)[9]),  "=r"((r)[10]), "=r"((r)[11]), \
          "=r"((r)[12]), "=r"((r)[13]), "=r"((r)[14]), "=r"((r)[15]), \
          "=r"((r)[16]), "=r"((r)[17]), "=r"((r)[18]), "=r"((r)[19]), \
          "=r"((r)[20]), "=r"((r)[21]), "=r"((r)[22]), "=r"((r)[23]), \
          "=r"((r)[24]), "=r"((r)[25]), "=r"((r)[26]), "=r"((r)[27]), \
          "=r"((r)[28]), "=r"((r)[29]), "=r"((r)[30]), "=r"((r)[31]) \
        : "r"(ta))

#define DESC_K  ((2ull<<61)|(1ull<<46)|(64ull<<32)|(1ull<<16))
__device__ __forceinline__ u64 mkdesc(uint32_t addr) {
    return DESC_K | ((u64)(addr >> 4) & 0x3FFF);
}
#define IDESC64  ((1u<<4)|(1u<<7)|(1u<<10)|(8u<<17)|(8u<<24))    /* M=128 N=64 */
#define IDESC128 ((1u<<4)|(1u<<7)|(1u<<10)|(16u<<17)|(8u<<24))   /* M=128 N=128 */
#endif  // HAS_TC

// ---------------- 1) depthwise 3x3 ----------------------------------------
__global__ void k_dwconv(const float* __restrict__ x,
                         const float* __restrict__ w,
                         float* __restrict__ y) {
    int idx = blockIdx.x * blockDim.x + threadIdx.x;
    if (idx >= TOTAL) return;
    int n = idx & (NPIX - 1);
    int c = (idx >> 12) & (CDIM - 1);
    int hh = n >> 6, ww = n & 63;
    const float* xb = x + (long long)(idx >> 12) * NPIX;
    const float* wc = w + c * 9;
    float s = 0.f;
#pragma unroll
    for (int i = 0; i < 3; i++) {
        int h2 = hh + i - 1;
        if ((unsigned)h2 < 64u) {
#pragma unroll
            for (int j = 0; j < 3; j++) {
                int w2 = ww + j - 1;
                if ((unsigned)w2 < 64u) s += xb[h2 * 64 + w2] * wc[i * 3 + j];
            }
        }
    }
    y[idx] = s;
}

// ---------------- 2) fp32 -> bf16 hi/lo ------------------------------------
__global__ void k_cvt(const float* __restrict__ src, u16* __restrict__ hi,
                      u16* __restrict__ lo, int n) {
    int i = blockIdx.x * blockDim.x + threadIdx.x;
    if (i >= n) return;
    float v = src[i];
    u16 h = f2bf(v);
    hi[i] = h;
    lo[i] = f2bf(v - bf2f(h));
}

// ---------------- 3) transpose+split ---------------------------------------
__global__ void k_t2bf(const float* __restrict__ y, u16* __restrict__ thi,
                       u16* __restrict__ tlo) {
    __shared__ float t[32][33];
    long long zo = (long long)blockIdx.z * CDIM * NPIX;
    long long zt = (long long)blockIdx.z * NPIX * CDIM;
    int c0 = blockIdx.y * 32, n0 = blockIdx.x * 32;
#pragma unroll
    for (int j = 0; j < 4; j++) {
        int c = c0 + threadIdx.y + j * 8;
        t[threadIdx.y + j * 8][threadIdx.x] = y[zo + (long long)c * NPIX + n0 + threadIdx.x];
    }
    __syncthreads();
#pragma unroll
    for (int j = 0; j < 4; j++) {
        int n = n0 + threadIdx.y + j * 8;
        float v = t[threadIdx.x][threadIdx.y + j * 8];
        u16 h = f2bf(v);
        thi[zt + (long long)n * CDIM + c0 + threadIdx.x] = h;
        tlo[zt + (long long)n * CDIM + c0 + threadIdx.x] = f2bf(v - bf2f(h));
    }
}

// ---------------- 4/5/7) tcgen05 GEMM, 128x128 tiles, double-buffered ------
// Two mbarriers: commit(kc) -> mbar[kc&1]; wait for commit(kc-2) on the
// same barrier at per-barrier phase (kc-2)>>1. Lag per barrier is 1 -> safe.
#define GM_TMEMPTR 0
#define GM_MBAR0 8
#define GM_MBAR1 16
#define GM_BUF(b) (1024 + (b) * 65536)
#define GM_AHI 0
#define GM_ALO 16384
#define GM_BHI 32768
#define GM_BLO 49152
#define GM_SMEM (1024 + 2 * 65536)

__global__ void __launch_bounds__(256) k_gemm_tc(
    const uint4* __restrict__ Ahi, const uint4* __restrict__ Alo, long long sA,
    const uint4* __restrict__ Bhi, const uint4* __restrict__ Blo, long long sB,
    u16* __restrict__ Ohi, u16* __restrict__ Olo,
    float* __restrict__ Ofp, const float* __restrict__ bias,
    long long sO, int ldo, float scale_q, int qcols) {
#if HAS_TC
    extern __shared__ char sm[];
    uint32_t sb = smem_u32(sm);
    int tid = threadIdx.x, wid = tid >> 5;
    int mrow0 = blockIdx.x * 128;
    int brow0 = blockIdx.y * 128;
    const uint4* Ah = Ahi + blockIdx.z * sA + (long long)mrow0 * 64;
    const uint4* Al = Alo + blockIdx.z * sA + (long long)mrow0 * 64;
    const uint4* Bh = Bhi + blockIdx.z * sB + (long long)brow0 * 64;
    const uint4* Bl = Blo + blockIdx.z * sB + (long long)brow0 * 64;

    if (wid == 0) {
        asm volatile("tcgen05.alloc.cta_group::1.sync.aligned.shared::cta.b32 [%0], %1;"
                     :: "r"(sb + GM_TMEMPTR), "r"(128u) : "memory");
    }
    if (tid == 0) { mbar_init1(sb + GM_MBAR0); mbar_init1(sb + GM_MBAR1); }
    __syncthreads();
    uint32_t tb;
    asm volatile("ld.shared.b32 %0, [%1];" : "=r"(tb) : "r"(sb + GM_TMEMPTR));

#pragma unroll 1
    for (int kc = 0; kc < 8; kc++) {
        int buf = kc & 1;
        uint32_t mb = sb + (buf ? GM_MBAR1 : GM_MBAR0);
        if (kc >= 2) mbar_wait(mb, ((kc - 2) >> 1) & 1);   // buffer free
        uint32_t base = GM_BUF(buf);
        int k8 = kc * 8;
#pragma unroll
        for (int l = 0; l < 4; l++) {
            int idx = tid + l * 256;
            int r = idx >> 3, j = idx & 7;
            uint32_t off = SWZ((uint32_t)(r * 128 + j * 16));
            *(uint4*)(sm + base + GM_AHI + off) = Ah[r * 64 + k8 + j];
            *(uint4*)(sm + base + GM_ALO + off) = Al[r * 64 + k8 + j];
        }
#pragma unroll
        for (int l = 0; l < 4; l++) {
            int idx = tid + l * 256;
            int r = idx >> 3, j = idx & 7;
            uint32_t off = SWZ((uint32_t)(r * 128 + j * 16));
            *(uint4*)(sm + base + GM_BHI + off) = Bh[r * 64 + k8 + j];
            *(uint4*)(sm + base + GM_BLO + off) = Bl[r * 64 + k8 + j];
        }
        FPROXY();
        __syncthreads();
        if (wid == 0) {
            if (elect1()) {
                u64 dAhi = mkdesc(sb + base + GM_AHI);
                u64 dAlo = mkdesc(sb + base + GM_ALO);
                u64 dBhi = mkdesc(sb + base + GM_BHI);
                u64 dBlo = mkdesc(sb + base + GM_BLO);
#pragma unroll
                for (int ks = 0; ks < 4; ks++)
                    mma_ss(tb, dAhi + ks * 2, dBhi + ks * 2, IDESC128, !(kc == 0 && ks == 0));
#pragma unroll
                for (int ks = 0; ks < 4; ks++)
                    mma_ss(tb, dAhi + ks * 2, dBlo + ks * 2, IDESC128, 1u);
#pragma unroll
                for (int ks = 0; ks < 4; ks++)
                    mma_ss(tb, dAlo + ks * 2, dBhi + ks * 2, IDESC128, 1u);
                tc_commit(mb);
            }
        }
    }
    // drain: commit kc=6 is phase 3 on mbar0, kc=7 is phase 3 on mbar1
    mbar_wait(sb + GM_MBAR0, 1);
    mbar_wait(sb + GM_MBAR1, 1);

    if (tid < 128) {
        TCF_AFTER();
        uint32_t d[128];
        LDX32(d, tb);
        LDX32(d + 32, tb + 32);
        LDX32(d + 64, tb + 64);
        LDX32(d + 96, tb + 96);
        TC_WAIT_LD();
        int m = mrow0 + tid;
        long long obase = blockIdx.z * sO + (long long)m * ldo + brow0;
        if (Ofp) {
            float bv = bias ? bias[m] : 0.f;
#pragma unroll
            for (int j = 0; j < 32; j++) {
                float4 v = make_float4(__uint_as_float(d[4 * j]) + bv,
                                       __uint_as_float(d[4 * j + 1]) + bv,
                                       __uint_as_float(d[4 * j + 2]) + bv,
                                       __uint_as_float(d[4 * j + 3]) + bv);
                *(float4*)(Ofp + obase + 4 * j) = v;
            }
        } else {
            float sc = (brow0 < qcols) ? scale_q : 1.0f;
            uint32_t whi[64], wlo[64];
#pragma unroll
            for (int j = 0; j < 64; j++) {
                float a = __uint_as_float(d[2 * j]) * sc;
                float b = __uint_as_float(d[2 * j + 1]) * sc;
                u16 ah = f2bf(a), bh = f2bf(b);
                whi[j] = (uint32_t)ah | ((uint32_t)bh << 16);
                u16 al = f2bf(a - bf2f(ah)), bl = f2bf(b - bf2f(bh));
                wlo[j] = (uint32_t)al | ((uint32_t)bl << 16);
            }
#pragma unroll
            for (int j = 0; j < 16; j++) {
                *(uint4*)(Ohi + obase + 8 * j) = *(uint4*)&whi[4 * j];
                *(uint4*)(Olo + obase + 8 * j) = *(uint4*)&wlo[4 * j];
            }
        }
    }
    __syncthreads();
    if (wid == 0) {
        asm volatile("tcgen05.dealloc.cta_group::1.sync.aligned.b32 %0, %1;"
                     :: "r"(tb), "r"(128u));
    }
#else
    // compile-only fallback
    int tid = threadIdx.x;
    const u16* Ah = (const u16*)(Ahi + blockIdx.z * sA) + (long long)blockIdx.x * 128 * 512;
    const u16* Al = (const u16*)(Alo + blockIdx.z * sA) + (long long)blockIdx.x * 128 * 512;
    const u16* Bh = (const u16*)(Bhi + blockIdx.z * sB) + (long long)blockIdx.y * 128 * 512;
    const u16* Bl = (const u16*)(Blo + blockIdx.z * sB) + (long long)blockIdx.y * 128 * 512;
    for (int e = tid; e < 128 * 128; e += 256) {
        int r = e >> 7, j = e & 127;
        float s = 0.f;
        for (int k = 0; k < 512; k++)
            s += (bf2f(Ah[r * 512 + k]) + bf2f(Al[r * 512 + k])) *
                 (bf2f(Bh[j * 512 + k]) + bf2f(Bl[j * 512 + k]));
        int m = blockIdx.x * 128 + r;
        long long obase = blockIdx.z * sO + (long long)m * ldo + blockIdx.y * 128 + j;
        if (Ofp) {
            Ofp[obase] = s + (bias ? bias[m] : 0.f);
        } else {
            float sc = (blockIdx.y * 128 < qcols) ? scale_q : 1.0f;
            s *= sc;
            u16 h = f2bf(s);
            Ohi[obase] = h;
            Olo[obase] = f2bf(s - bf2f(h));
        }
    }
#endif
}

// ---------------- 6) attention (pipelined, strict alternation -> safe) -----
#define SM_TMEMPTR 0
#define SM_MBAR 8
#define SM_QHI 1024
#define SM_QLO (SM_QHI + 16384)
#define SM_KHI(b) (33792 + (b) * 16384)
#define SM_KLO(b) (33792 + (b) * 16384 + 8192)
#define SM_VHI(b) (66560 + (b) * 16384)
#define SM_VLO(b) (66560 + (b) * 16384 + 8192)
#define SM_PHI 99328
#define SM_PLO (SM_PHI + 16384)
#define ATT_SMEM (SM_PLO + 16384)

#define TM_S 0
#define TM_O 64

__global__ void __launch_bounds__(256) k_attn(
    const u16* __restrict__ qkthi, const u16* __restrict__ qktlo,
    const u16* __restrict__ vthi,  const u16* __restrict__ vtlo,
    u16* __restrict__ othi, u16* __restrict__ otlo) {
#if HAS_TC
    extern __shared__ char sm[];
    uint32_t sb = smem_u32(sm);
    int tid = threadIdx.x, wid = tid >> 5;
    int n0 = blockIdx.x * 128;
    int h = blockIdx.y, b = blockIdx.z;
    const uint4* qh4 = (const uint4*)qkthi + (long long)b * NPIX * 128;
    const uint4* ql4 = (const uint4*)qktlo + (long long)b * NPIX * 128;
    const uint4* vh4 = (const uint4*)vthi + ((long long)b * CDIM + h * DH) * 512;
    const uint4* vl4 = (const uint4*)vtlo + ((long long)b * CDIM + h * DH) * 512;

    if (wid == 0) {
        asm volatile("tcgen05.alloc.cta_group::1.sync.aligned.shared::cta.b32 [%0], %1;"
                     :: "r"(sb + SM_TMEMPTR), "r"(128u) : "memory");
    }
    if (tid == 0) mbar_init1(sb + SM_MBAR);
    __syncthreads();
    uint32_t tb;
    asm volatile("ld.shared.b32 %0, [%1];" : "=r"(tb) : "r"(sb + SM_TMEMPTR));

    // ---- Q tile ----
#pragma unroll
    for (int l = 0; l < 4; l++) {
        int idx = tid + l * 256;
        int r = idx >> 3, j = idx & 7;
        uint32_t off = SWZ((uint32_t)(r * 128 + j * 16));
        *(uint4*)(sm + SM_QHI + off) = qh4[(long long)(n0 + r) * 128 + h * 8 + j];
        *(uint4*)(sm + SM_QLO + off) = ql4[(long long)(n0 + r) * 128 + h * 8 + j];
    }
    // ---- K/V tile 0 ----
#pragma unroll
    for (int l = 0; l < 2; l++) {
        int idx = tid + l * 256;
        int r = idx >> 3, j = idx & 7;
        uint32_t off = SWZ((uint32_t)(r * 128 + j * 16));
        *(uint4*)(sm + SM_KHI(0) + off) = qh4[(long long)r * 128 + 64 + h * 8 + j];
        *(uint4*)(sm + SM_KLO(0) + off) = ql4[(long long)r * 128 + 64 + h * 8 + j];
        *(uint4*)(sm + SM_VHI(0) + off) = vh4[(long long)r * 512 + j];
        *(uint4*)(sm + SM_VLO(0) + off) = vl4[(long long)r * 512 + j];
    }
    FPROXY();
    __syncthreads();

    u64 aQhi = mkdesc(sb + SM_QHI);
    u64 aQlo = mkdesc(sb + SM_QLO);
    u64 aPhi = mkdesc(sb + SM_PHI);
    u64 aPlo = mkdesc(sb + SM_PLO);

    // prologue: S(0)
    if (wid == 0) {
        if (elect1()) {
            u64 bKhi = mkdesc(sb + SM_KHI(0));
            u64 bKlo = mkdesc(sb + SM_KLO(0));
#pragma unroll
            for (int ks = 0; ks < 4; ks++)
                mma_ss(tb + TM_S, aQhi + ks * 2, bKhi + ks * 2, IDESC64, ks > 0);
#pragma unroll
            for (int ks = 0; ks < 4; ks++)
                mma_ss(tb + TM_S, aQhi + ks * 2, bKlo + ks * 2, IDESC64, 1u);
#pragma unroll
            for (int ks = 0; ks < 4; ks++)
                mma_ss(tb + TM_S, aQlo + ks * 2, bKhi + ks * 2, IDESC64, 1u);
            tc_commit(sb + SM_MBAR);
        }
    }

    float den = 0.f;
    uint32_t ph = 0;

#pragma unroll 1
    for (int t = 0; t < 64; t++) {
        mbar_wait(sb + SM_MBAR, ph); ph ^= 1;   // AV(t-1)+S(t) done
        TCF_AFTER();

        // prefetch K/V(t+1) (overlaps softmax)
        if (t < 63) {
            int m1 = (t + 1) * 64;
            int nb = (t + 1) & 1;
#pragma unroll
            for (int l = 0; l < 2; l++) {
                int idx = tid + l * 256;
                int r = idx >> 3, j = idx & 7;
                uint32_t off = SWZ((uint32_t)(r * 128 + j * 16));
                *(uint4*)(sm + SM_KHI(nb) + off) = qh4[(long long)(m1 + r) * 128 + 64 + h * 8 + j];
                *(uint4*)(sm + SM_KLO(nb) + off) = ql4[(long long)(m1 + r) * 128 + 64 + h * 8 + j];
                *(uint4*)(sm + SM_VHI(nb) + off) = vh4[(long long)r * 512 + m1 / 8 + j];
                *(uint4*)(sm + SM_VLO(nb) + off) = vl4[(long long)r * 512 + m1 / 8 + j];
            }
        }

        // softmax: thread owns q-row tid (warps 0-3)
        if (tid < 128) {
            uint32_t sr[64];
            LDX32(sr, tb + TM_S);
            LDX32(sr + 32, tb + TM_S + 32);
            TC_WAIT_LD();
            float p[64];
#pragma unroll
            for (int c = 0; c < 64; c++) p[c] = ex2f(__uint_as_float(sr[c]));
            float dsum = 0.f;
#pragma unroll
            for (int c = 0; c < 64; c++) dsum += p[c];
            den += dsum;

            uint32_t rbase = (uint32_t)(tid * 128);
#pragma unroll
            for (int j = 0; j < 32; j++) {
                u16 a = f2bf(p[2 * j]), c = f2bf(p[2 * j + 1]);
                *(uint32_t*)(sm + SM_PHI + SWZ(rbase + j * 4)) =
                    (uint32_t)a | ((uint32_t)c << 16);
            }
#pragma unroll
            for (int j = 0; j < 32; j++) {
                u16 a = f2bf(p[2 * j] - bf2f(f2bf(p[2 * j])));
                u16 c = f2bf(p[2 * j + 1] - bf2f(f2bf(p[2 * j + 1])));
                *(uint32_t*)(sm + SM_PLO + SWZ(rbase + j * 4)) =
                    (uint32_t)a | ((uint32_t)c << 16);
            }
        }
        FPROXY();
        __syncthreads();

        // issue AV(t) [+ S(t+1)], single commit
        if (wid == 0) {
            if (elect1()) {
                int cb = t & 1;
                u64 bVhi = mkdesc(sb + SM_VHI(cb));
                u64 bVlo = mkdesc(sb + SM_VLO(cb));
#pragma unroll
                for (int ks = 0; ks < 4; ks++)
                    mma_ss(tb + TM_O, aPhi + ks * 2, bVhi + ks * 2, IDESC64,
                           (t > 0 || ks > 0) ? 1u : 0u);
#pragma unroll
                for (int ks = 0; ks < 4; ks++)
                    mma_ss(tb + TM_O, aPhi + ks * 2, bVlo + ks * 2, IDESC64, 1u);
#pragma unroll
                for (int ks = 0; ks < 4; ks++)
                    mma_ss(tb + TM_O, aPlo + ks * 2, bVhi + ks * 2, IDESC64, 1u);
                if (t < 63) {
                    int nb = (t + 1) & 1;
                    u64 bKhi = mkdesc(sb + SM_KHI(nb));
                    u64 bKlo = mkdesc(sb + SM_KLO(nb));
#pragma unroll
                    for (int ks = 0; ks < 4; ks++)
                        mma_ss(tb + TM_S, aQhi + ks * 2, bKhi + ks * 2, IDESC64, ks > 0);
#pragma unroll
                    for (int ks = 0; ks < 4; ks++)
                        mma_ss(tb + TM_S, aQhi + ks * 2, bKlo + ks * 2, IDESC64, 1u);
#pragma unroll
                    for (int ks = 0; ks < 4; ks++)
                        mma_ss(tb + TM_S, aQlo + ks * 2, bKhi + ks * 2, IDESC64, 1u);
                }
                tc_commit(sb + SM_MBAR);
            }
        }
    }
    mbar_wait(sb + SM_MBAR, ph); ph ^= 1;   // final AV done

    // epilogue
    if (tid < 128) {
        TCF_AFTER();
        uint32_t orr[64];
        LDX32(orr, tb + TM_O);
        LDX32(orr + 32, tb + TM_O + 32);
        TC_WAIT_LD();
        float inv = 1.0f / den;
        long long obase = ((long long)b * NPIX + n0 + tid) * CDIM + h * DH;
        uint32_t whi[32], wlo[32];
#pragma unroll
        for (int j = 0; j < 32; j++) {
            float a = __uint_as_float(orr[2 * j]) * inv;
            float c = __uint_as_float(orr[2 * j + 1]) * inv;
            u16 ah = f2bf(a), ch = f2bf(c);
            whi[j] = (uint32_t)ah | ((uint32_t)ch << 16);
            u16 al = f2bf(a - bf2f(ah)), cl = f2bf(c - bf2f(ch));
            wlo[j] = (uint32_t)al | ((uint32_t)cl << 16);
        }
#pragma unroll
        for (int j = 0; j < 8; j++) {
            *(uint4*)(othi + obase + 8 * j) = *(uint4*)&whi[4 * j];
            *(uint4*)(otlo + obase + 8 * j) = *(uint4*)&wlo[4 * j];
        }
    }
    __syncthreads();
    if (wid == 0) {
        asm volatile("tcgen05.dealloc.cta_group::1.sync.aligned.b32 %0, %1;"
                     :: "r"(tb), "r"(128u));
    }
#else
    // compile-only fallback
    int tid = threadIdx.x;
    if (tid >= 128) return;
    int n0 = blockIdx.x * 128;
    int h = blockIdx.y, b = blockIdx.z;
    long long qb = (long long)b * NPIX * QKD;
    int r = n0 + tid;
    float q[64], o[64], den = 0.f;
#pragma unroll
    for (int d = 0; d < 64; d++) {
        q[d] = bf2f(qkthi[qb + (long long)r * QKD + h * 64 + d]) +
               bf2f(qktlo[qb + (long long)r * QKD + h * 64 + d]);
        o[d] = 0.f;
    }
    for (int key = 0; key < NPIX; key++) {
        float s = 0.f;
        for (int d = 0; d < 64; d++)
            s += q[d] * (bf2f(qkthi[qb + (long long)key * QKD + 512 + h * 64 + d]) +
                         bf2f(qktlo[qb + (long long)key * QKD + 512 + h * 64 + d]));
        float p = ex2f(s);
        den += p;
        for (int d = 0; d < 64; d++) {
            long long vi = ((long long)b * CDIM + h * 64 + d) * NPIX + key;
            o[d] += p * (bf2f(vthi[vi]) + bf2f(vtlo[vi]));
        }
    }
    long long ob = ((long long)b * NPIX + r) * CDIM + h * 64;
    for (int d = 0; d < 64; d++) {
        float v = o[d] / den;
        u16 hh = f2bf(v);
        othi[ob + d] = hh;
        otlo[ob + d] = f2bf(v - bf2f(hh));
    }
#endif
}

// ---------------------------------------------------------------------------
extern "C" void kernel_launch(void* const* d_in, const int* in_sizes, int n_in,
                              void* d_out, int out_size) {
    const float* x      = (const float*)d_in[0];
    const float* dw_w   = (const float*)d_in[1];
    const float* qkv_w  = (const float*)d_in[2];
    const float* proj_w = (const float*)d_in[3];
    const float* proj_b = (const float*)d_in[4];
    float* out = (float*)d_out;

    float* py;
    u16 *pythi, *pytlo, *pwhi, *pwlo, *ppwhi, *ppwlo;
    u16 *pqkthi, *pqktlo, *pvthi, *pvtlo, *pothi, *potlo;
    cudaGetSymbolAddress((void**)&py,     g_y);
    cudaGetSymbolAddress((void**)&pythi,  g_ythi);
    cudaGetSymbolAddress((void**)&pytlo,  g_ytlo);
    cudaGetSymbolAddress((void**)&pwhi,   g_whi);
    cudaGetSymbolAddress((void**)&pwlo,   g_wlo);
    cudaGetSymbolAddress((void**)&ppwhi,  g_pwhi);
    cudaGetSymbolAddress((void**)&ppwlo,  g_pwlo);
    cudaGetSymbolAddress((void**)&pqkthi, g_qkthi);
    cudaGetSymbolAddress((void**)&pqktlo, g_qktlo);
    cudaGetSymbolAddress((void**)&pvthi,  g_vthi);
    cudaGetSymbolAddress((void**)&pvtlo,  g_vtlo);
    cudaGetSymbolAddress((void**)&pothi,  g_othi);
    cudaGetSymbolAddress((void**)&potlo,  g_otlo);

    cudaFuncSetAttribute(k_attn, cudaFuncAttributeMaxDynamicSharedMemorySize, ATT_SMEM);
    cudaFuncSetAttribute(k_gemm_tc, cudaFuncAttributeMaxDynamicSharedMemorySize, GM_SMEM);

    k_dwconv<<<(TOTAL + 255) / 256, 256>>>(x, dw_w, py);
    k_cvt<<<(3 * CDIM * CDIM + 255) / 256, 256>>>(qkv_w, pwhi, pwlo, 3 * CDIM * CDIM);
    k_cvt<<<(CDIM * CDIM + 255) / 256, 256>>>(proj_w, ppwhi, ppwlo, CDIM * CDIM);
    {
        dim3 grid(NPIX / 32, CDIM / 32, BATCH);
        k_t2bf<<<grid, dim3(32, 8)>>>(py, pythi, pytlo);
    }

    long long sYT = (long long)NPIX * CDIM / 8;

    // qk GEMM: qkt[n][1024]
    {
        dim3 grid(NPIX / 128, QKD / 128, BATCH);
        k_gemm_tc<<<grid, 256, GM_SMEM>>>(
            (const uint4*)pythi, (const uint4*)pytlo, sYT,
            (const uint4*)pwhi, (const uint4*)pwlo, 0,
            pqkthi, pqktlo, nullptr, nullptr,
            (long long)NPIX * QKD, QKD, ATT_SCALE_L2E, 512);
    }
    // V GEMM: vt[c][n]
    {
        dim3 grid(CDIM / 128, NPIX / 128, BATCH);
        k_gemm_tc<<<grid, 256, GM_SMEM>>>(
            (const uint4*)(pwhi + 1024 * CDIM), (const uint4*)(pwlo + 1024 * CDIM), 0,
            (const uint4*)pythi, (const uint4*)pytlo, sYT,
            pvthi, pvtlo, nullptr, nullptr,
            (long long)CDIM * NPIX, NPIX, 1.0f, 0);
    }
    // attention
    {
        dim3 grid(NPIX / 128, HEADS, BATCH);
        k_attn<<<grid, 256, ATT_SMEM>>>(pqkthi, pqktlo, pvthi, pvtlo, pothi, potlo);
    }
    // proj GEMM + bias
    {
        dim3 grid(CDIM / 128, NPIX / 128, BATCH);
        k_gemm_tc<<<grid, 256, GM_SMEM>>>(
            (const uint4*)ppwhi, (const uint4*)ppwlo, 0,
            (const uint4*)pothi, (const uint4*)potlo, sYT,
            nullptr, nullptr, out, proj_b,
            (long long)CDIM * NPIX, NPIX, 1.0f, 0);
    }
}

// round 8
// speedup vs baseline: 1.1711x; 1.1711x over previous
#include <cuda_runtime.h>
#include <cuda_bf16.h>
#include <cstdint>

// ---------------------------------------------------------------------------
// LightweightSelfAttention  (B=2, C=512, H=W=64, heads=8, dh=64)
// All-tcgen05, bf16 2-way split.
// R8: attention P lives in TMEM (TS-mode AV) -> 100KB smem -> occ 2 with
//     the double-buffered pipeline; 8-warp softmax (col-split).
//     GEMM = R5-exact (66KB, occ 3, serial commits).
// ---------------------------------------------------------------------------

#if defined(__CUDA_ARCH_FEAT_SM103_ALL) || defined(__CUDA_ARCH_FEAT_SM100_ALL)
#define HAS_TC 1
#else
#define HAS_TC 0
#endif

#define BATCH 2
#define CDIM 512
#define HEADS 8
#define DH 64
#define NPIX 4096
#define TOTAL (BATCH*CDIM*NPIX)
#define QKD 1024

typedef unsigned short u16;
typedef unsigned long long u64;

__device__ float g_y[BATCH * CDIM * NPIX];
__device__ u16 g_ythi[BATCH * NPIX * CDIM];
__device__ u16 g_ytlo[BATCH * NPIX * CDIM];
__device__ u16 g_whi[3 * CDIM * CDIM];
__device__ u16 g_wlo[3 * CDIM * CDIM];
__device__ u16 g_pwhi[CDIM * CDIM];
__device__ u16 g_pwlo[CDIM * CDIM];
__device__ u16 g_qkthi[BATCH * NPIX * QKD];
__device__ u16 g_qktlo[BATCH * NPIX * QKD];
__device__ u16 g_vthi[BATCH * CDIM * NPIX];
__device__ u16 g_vtlo[BATCH * CDIM * NPIX];
__device__ u16 g_othi[BATCH * NPIX * CDIM];
__device__ u16 g_otlo[BATCH * NPIX * CDIM];

#define ATT_SCALE_L2E 0.18033688f   /* 0.125 * log2(e) */

// ---------------- helpers --------------------------------------------------
__device__ __forceinline__ uint32_t smem_u32(const void* p) {
    uint32_t a;
    asm("{ .reg .u64 t; cvta.to.shared.u64 t, %1; cvt.u32.u64 %0, t; }"
        : "=r"(a) : "l"(p));
    return a;
}
__device__ __forceinline__ u16 f2bf(float x) {
    return __bfloat16_as_ushort(__float2bfloat16_rn(x));
}
__device__ __forceinline__ float bf2f(u16 u) {
    return __bfloat162float(__ushort_as_bfloat16(u));
}
__device__ __forceinline__ float ex2f(float x) {
    float y; asm("ex2.approx.ftz.f32 %0, %1;" : "=f"(y) : "f"(x)); return y;
}
#define SWZ(o) ((o) ^ (((o) >> 3) & 0x70))

#if HAS_TC
__device__ __forceinline__ unsigned elect1() {
    unsigned p;
    asm volatile("{\n\t.reg .pred p;\n\telect.sync _|p, 0xFFFFFFFF;\n\t"
                 "selp.b32 %0, 1, 0, p;\n\t}" : "=r"(p));
    return p;
}
__device__ __forceinline__ void mma_ss(uint32_t d, u64 a, u64 b, uint32_t id, uint32_t en) {
    asm volatile("{\n\t.reg .pred p;\n\tsetp.ne.u32 p, %5, 0;\n\t"
        "tcgen05.mma.cta_group::1.kind::f16 [%0], %1, %2, %3, {%4,%4,%4,%4}, p;\n\t}"
        :: "r"(d), "l"(a), "l"(b), "r"(id), "r"(0u), "r"(en) : "memory");
}
__device__ __forceinline__ void mma_ts(uint32_t d, uint32_t a, u64 b, uint32_t id, uint32_t en) {
    asm volatile("{\n\t.reg .pred p;\n\tsetp.ne.u32 p, %5, 0;\n\t"
        "tcgen05.mma.cta_group::1.kind::f16 [%0], [%1], %2, %3, {%4,%4,%4,%4}, p;\n\t}"
        :: "r"(d), "r"(a), "l"(b), "r"(id), "r"(0u), "r"(en) : "memory");
}
__device__ __forceinline__ void tc_commit(uint32_t mbar) {
    asm volatile("tcgen05.commit.cta_group::1.mbarrier::arrive::one.shared::cluster.b64 [%0];"
                 :: "r"(mbar) : "memory");
}
__device__ __forceinline__ void mbar_init1(uint32_t mbar) {
    asm volatile("mbarrier.init.shared.b64 [%0], %1;" :: "r"(mbar), "r"(1u) : "memory");
}
__device__ __forceinline__ void mbar_wait(uint32_t mbar, uint32_t ph) {
    asm volatile("{\n\t.reg .pred P1;\n\tLAB1_%=:\n\t"
        "mbarrier.try_wait.parity.acquire.cta.shared::cta.b64 P1, [%0], %1, 0x989680;\n\t"
        "@P1 bra.uni LAB2_%=;\n\tbra.uni LAB1_%=;\n\tLAB2_%=:\n\t}"
        :: "r"(mbar), "r"(ph) : "memory");
}
#define TCF_AFTER()  asm volatile("tcgen05.fence::after_thread_sync;" ::: "memory")
#define TCF_BEFORE() asm volatile("tcgen05.fence::before_thread_sync;" ::: "memory")
#define FPROXY()     asm volatile("fence.proxy.async.shared::cta;" ::: "memory")
#define TC_WAIT_LD() asm volatile("tcgen05.wait::ld.sync.aligned;" ::: "memory")
#define TC_WAIT_ST() asm volatile("tcgen05.wait::st.sync.aligned;" ::: "memory")

#define LDX32(r, ta) \
    asm volatile("tcgen05.ld.sync.aligned.32x32b.x32.b32 " \
        "{%0, %1, %2, %3, %4, %5, %6, %7, %8, %9, %10, %11, %12, %13, %14, %15, " \
        " %16, %17, %18, %19, %20, %21, %22, %23, %24, %25, %26, %27, %28, %29, %30, %31}, [%32];" \
        : "=r"((r)[0]),  "=r"((r)[1]),  "=r"((r)[2]),  "=r"((r)[3]), \
          "=r"((r)[4]),  "=r"((r)[5]),  "=r"((r)[6]),  "=r"((r)[7]), \
          "=r"((r)[8]),  "=r"((r)[9]),  "=r"((r)[10]), "=r"((r)[11]), \
          "=r"((r)[12]), "=r"((r)[13]), "=r"((r)[14]), "=r"((r)[15]), \
          "=r"((r)[16]), "=r"((r)[17]), "=r"((r)[18]), "=r"((r)[19]), \
          "=r"((r)[20]), "=r"((r)[21]), "=r"((r)[22]), "=r"((r)[23]), \
          "=r"((r)[24]), "=r"((r)[25]), "=r"((r)[26]), "=r"((r)[27]), \
          "=r"((r)[28]), "=r"((r)[29]), "=r"((r)[30]), "=r"((r)[31]) \
        : "r"(ta))

#define STX16(ta, r) \
    asm volatile("tcgen05.st.sync.aligned.32x32b.x16.b32 [%0], " \
        "{%1, %2, %3, %4, %5, %6, %7, %8, %9, %10, %11, %12, %13, %14, %15, %16};" \
        :: "r"(ta), \
           "r"((r)[0]),  "r"((r)[1]),  "r"((r)[2]),  "r"((r)[3]), \
           "r"((r)[4]),  "r"((r)[5]),  "r"((r)[6]),  "r"((r)[7]), \
           "r"((r)[8]),  "r"((r)[9]),  "r"((r)[10]), "r"((r)[11]), \
           "r"((r)[12]), "r"((r)[13]), "r"((r)[14]), "r"((r)[15]) \
        : "memory")

#define DESC_K  ((2ull<<61)|(1ull<<46)|(64ull<<32)|(1ull<<16))
__device__ __forceinline__ u64 mkdesc(uint32_t addr) {
    return DESC_K | ((u64)(addr >> 4) & 0x3FFF);
}
#define IDESC64  ((1u<<4)|(1u<<7)|(1u<<10)|(8u<<17)|(8u<<24))    /* M=128 N=64 */
#endif  // HAS_TC

// ---------------- 1) depthwise 3x3 ----------------------------------------
__global__ void k_dwconv(const float* __restrict__ x,
                         const float* __restrict__ w,
                         float* __restrict__ y) {
    int idx = blockIdx.x * blockDim.x + threadIdx.x;
    if (idx >= TOTAL) return;
    int n = idx & (NPIX - 1);
    int c = (idx >> 12) & (CDIM - 1);
    int hh = n >> 6, ww = n & 63;
    const float* xb = x + (long long)(idx >> 12) * NPIX;
    const float* wc = w + c * 9;
    float s = 0.f;
#pragma unroll
    for (int i = 0; i < 3; i++) {
        int h2 = hh + i - 1;
        if ((unsigned)h2 < 64u) {
#pragma unroll
            for (int j = 0; j < 3; j++) {
                int w2 = ww + j - 1;
                if ((unsigned)w2 < 64u) s += xb[h2 * 64 + w2] * wc[i * 3 + j];
            }
        }
    }
    y[idx] = s;
}

// ---------------- 2) fp32 -> bf16 hi/lo ------------------------------------
__global__ void k_cvt(const float* __restrict__ src, u16* __restrict__ hi,
                      u16* __restrict__ lo, int n) {
    int i = blockIdx.x * blockDim.x + threadIdx.x;
    if (i >= n) return;
    float v = src[i];
    u16 h = f2bf(v);
    hi[i] = h;
    lo[i] = f2bf(v - bf2f(h));
}

// ---------------- 3) transpose+split ---------------------------------------
__global__ void k_t2bf(const float* __restrict__ y, u16* __restrict__ thi,
                       u16* __restrict__ tlo) {
    __shared__ float t[32][33];
    long long zo = (long long)blockIdx.z * CDIM * NPIX;
    long long zt = (long long)blockIdx.z * NPIX * CDIM;
    int c0 = blockIdx.y * 32, n0 = blockIdx.x * 32;
#pragma unroll
    for (int j = 0; j < 4; j++) {
        int c = c0 + threadIdx.y + j * 8;
        t[threadIdx.y + j * 8][threadIdx.x] = y[zo + (long long)c * NPIX + n0 + threadIdx.x];
    }
    __syncthreads();
#pragma unroll
    for (int j = 0; j < 4; j++) {
        int n = n0 + threadIdx.y + j * 8;
        float v = t[threadIdx.x][threadIdx.y + j * 8];
        u16 h = f2bf(v);
        thi[zt + (long long)n * CDIM + c0 + threadIdx.x] = h;
        tlo[zt + (long long)n * CDIM + c0 + threadIdx.x] = f2bf(v - bf2f(h));
    }
}

// ---------------- 4/5/7) tcgen05 GEMM (R5-exact: 128x64, serial) -----------
#define GM_TMEMPTR 0
#define GM_MBAR 8
#define GM_AHI 1024
#define GM_ALO (GM_AHI + 16384)
#define GM_BHI (GM_ALO + 16384)
#define GM_BLO (GM_BHI + 8192)
#define GM_SMEM (GM_BLO + 8192)

__global__ void __launch_bounds__(256) k_gemm_tc(
    const uint4* __restrict__ Ahi, const uint4* __restrict__ Alo, long long sA,
    const uint4* __restrict__ Bhi, const uint4* __restrict__ Blo, long long sB,
    u16* __restrict__ Ohi, u16* __restrict__ Olo,
    float* __restrict__ Ofp, const float* __restrict__ bias,
    long long sO, int ldo, float scale_q, int qcols) {
#if HAS_TC
    extern __shared__ char sm[];
    uint32_t sb = smem_u32(sm);
    int tid = threadIdx.x, wid = tid >> 5;
    int mrow0 = blockIdx.x * 128;
    int brow0 = blockIdx.y * 64;
    const uint4* Ah = Ahi + blockIdx.z * sA + (long long)mrow0 * 64;
    const uint4* Al = Alo + blockIdx.z * sA + (long long)mrow0 * 64;
    const uint4* Bh = Bhi + blockIdx.z * sB + (long long)brow0 * 64;
    const uint4* Bl = Blo + blockIdx.z * sB + (long long)brow0 * 64;

    if (wid == 0) {
        asm volatile("tcgen05.alloc.cta_group::1.sync.aligned.shared::cta.b32 [%0], %1;"
                     :: "r"(sb + GM_TMEMPTR), "r"(128u) : "memory");
    }
    if (tid == 0) mbar_init1(sb + GM_MBAR);
    __syncthreads();
    uint32_t tb;
    asm volatile("ld.shared.b32 %0, [%1];" : "=r"(tb) : "r"(sb + GM_TMEMPTR));

    u64 dAhi = mkdesc(sb + GM_AHI);
    u64 dAlo = mkdesc(sb + GM_ALO);
    u64 dBhi = mkdesc(sb + GM_BHI);
    u64 dBlo = mkdesc(sb + GM_BLO);

    uint32_t ph = 0;
#pragma unroll 1
    for (int kc = 0; kc < 8; kc++) {
        if (kc) { mbar_wait(sb + GM_MBAR, ph); ph ^= 1; }
        int k8 = kc * 8;
#pragma unroll
        for (int l = 0; l < 4; l++) {
            int idx = tid + l * 256;
            int r = idx >> 3, j = idx & 7;
            uint32_t off = SWZ((uint32_t)(r * 128 + j * 16));
            *(uint4*)(sm + GM_AHI + off) = Ah[r * 64 + k8 + j];
            *(uint4*)(sm + GM_ALO + off) = Al[r * 64 + k8 + j];
        }
#pragma unroll
        for (int l = 0; l < 2; l++) {
            int idx = tid + l * 256;
            int r = idx >> 3, j = idx & 7;
            uint32_t off = SWZ((uint32_t)(r * 128 + j * 16));
            *(uint4*)(sm + GM_BHI + off) = Bh[r * 64 + k8 + j];
            *(uint4*)(sm + GM_BLO + off) = Bl[r * 64 + k8 + j];
        }
        FPROXY();
        __syncthreads();
        if (wid == 0) {
            if (elect1()) {
#pragma unroll
                for (int ks = 0; ks < 4; ks++)
                    mma_ss(tb, dAhi + ks * 2, dBhi + ks * 2, IDESC64, !(kc == 0 && ks == 0));
#pragma unroll
                for (int ks = 0; ks < 4; ks++)
                    mma_ss(tb, dAhi + ks * 2, dBlo + ks * 2, IDESC64, 1u);
#pragma unroll
                for (int ks = 0; ks < 4; ks++)
                    mma_ss(tb, dAlo + ks * 2, dBhi + ks * 2, IDESC64, 1u);
                tc_commit(sb + GM_MBAR);
            }
        }
    }
    mbar_wait(sb + GM_MBAR, ph); ph ^= 1;

    if (tid < 128) {
        TCF_AFTER();
        uint32_t d[64];
        LDX32(d, tb);
        LDX32(d + 32, tb + 32);
        TC_WAIT_LD();
        int m = mrow0 + tid;
        long long obase = blockIdx.z * sO + (long long)m * ldo + brow0;
        if (Ofp) {
            float bv = bias ? bias[m] : 0.f;
#pragma unroll
            for (int j = 0; j < 16; j++) {
                float4 v = make_float4(__uint_as_float(d[4 * j]) + bv,
                                       __uint_as_float(d[4 * j + 1]) + bv,
                                       __uint_as_float(d[4 * j + 2]) + bv,
                                       __uint_as_float(d[4 * j + 3]) + bv);
                *(float4*)(Ofp + obase + 4 * j) = v;
            }
        } else {
            float sc = (brow0 < qcols) ? scale_q : 1.0f;
            uint32_t whi[32], wlo[32];
#pragma unroll
            for (int j = 0; j < 32; j++) {
                float a = __uint_as_float(d[2 * j]) * sc;
                float b = __uint_as_float(d[2 * j + 1]) * sc;
                u16 ah = f2bf(a), bh = f2bf(b);
                whi[j] = (uint32_t)ah | ((uint32_t)bh << 16);
                u16 al = f2bf(a - bf2f(ah)), bl = f2bf(b - bf2f(bh));
                wlo[j] = (uint32_t)al | ((uint32_t)bl << 16);
            }
#pragma unroll
            for (int j = 0; j < 8; j++) {
                *(uint4*)(Ohi + obase + 8 * j) = *(uint4*)&whi[4 * j];
                *(uint4*)(Olo + obase + 8 * j) = *(uint4*)&wlo[4 * j];
            }
        }
    }
    __syncthreads();
    if (wid == 0) {
        asm volatile("tcgen05.dealloc.cta_group::1.sync.aligned.b32 %0, %1;"
                     :: "r"(tb), "r"(128u));
    }
#else
    // compile-only fallback
    int tid = threadIdx.x;
    const u16* Ah = (const u16*)(Ahi + blockIdx.z * sA) + (long long)blockIdx.x * 128 * 512;
    const u16* Al = (const u16*)(Alo + blockIdx.z * sA) + (long long)blockIdx.x * 128 * 512;
    const u16* Bh = (const u16*)(Bhi + blockIdx.z * sB) + (long long)blockIdx.y * 64 * 512;
    const u16* Bl = (const u16*)(Blo + blockIdx.z * sB) + (long long)blockIdx.y * 64 * 512;
    for (int e = tid; e < 128 * 64; e += 256) {
        int r = e >> 6, j = e & 63;
        float s = 0.f;
        for (int k = 0; k < 512; k++)
            s += (bf2f(Ah[r * 512 + k]) + bf2f(Al[r * 512 + k])) *
                 (bf2f(Bh[j * 512 + k]) + bf2f(Bl[j * 512 + k]));
        int m = blockIdx.x * 128 + r;
        long long obase = blockIdx.z * sO + (long long)m * ldo + blockIdx.y * 64 + j;
        if (Ofp) {
            Ofp[obase] = s + (bias ? bias[m] : 0.f);
        } else {
            float sc = (blockIdx.y * 64 < qcols) ? scale_q : 1.0f;
            s *= sc;
            u16 h = f2bf(s);
            Ohi[obase] = h;
            Olo[obase] = f2bf(s - bf2f(h));
        }
    }
#endif
}

// ---------------- 6) attention: pipelined, P in TMEM, occ 2 ----------------
#define SM_TMEMPTR 0
#define SM_MBAR 8
#define SM_DEN 1024                    /* 256 floats */
#define SM_QHI 2048
#define SM_QLO (SM_QHI + 16384)
#define SM_KHI(b) (34816 + (b) * 16384)
#define SM_KLO(b) (34816 + (b) * 16384 + 8192)
#define SM_VHI(b) (67584 + (b) * 16384)
#define SM_VLO(b) (67584 + (b) * 16384 + 8192)
#define ATT_SMEM 100352

#define TM_S 0
#define TM_O 64
#define TM_PHI 128
#define TM_PLO 160
#define ATT_TMCOLS 256

__global__ void __launch_bounds__(256) k_attn(
    const u16* __restrict__ qkthi, const u16* __restrict__ qktlo,
    const u16* __restrict__ vthi,  const u16* __restrict__ vtlo,
    u16* __restrict__ othi, u16* __restrict__ otlo) {
#if HAS_TC
    extern __shared__ char sm[];
    uint32_t sb = smem_u32(sm);
    int tid = threadIdx.x, wid = tid >> 5;
    int half = wid >> 2;               // 0: cols 0-31, 1: cols 32-63
    uint32_t lofs = (uint32_t)(wid & 3) << 21;   // TMEM lane offset for ST
    int n0 = blockIdx.x * 128;
    int h = blockIdx.y, b = blockIdx.z;
    const uint4* qh4 = (const uint4*)qkthi + (long long)b * NPIX * 128;
    const uint4* ql4 = (const uint4*)qktlo + (long long)b * NPIX * 128;
    const uint4* vh4 = (const uint4*)vthi + ((long long)b * CDIM + h * DH) * 512;
    const uint4* vl4 = (const uint4*)vtlo + ((long long)b * CDIM + h * DH) * 512;

    if (wid == 0) {
        asm volatile("tcgen05.alloc.cta_group::1.sync.aligned.shared::cta.b32 [%0], %1;"
                     :: "r"(sb + SM_TMEMPTR), "r"((uint32_t)ATT_TMCOLS) : "memory");
    }
    if (tid == 0) mbar_init1(sb + SM_MBAR);
    __syncthreads();
    uint32_t tb;
    asm volatile("ld.shared.b32 %0, [%1];" : "=r"(tb) : "r"(sb + SM_TMEMPTR));

    // ---- Q tile ----
#pragma unroll
    for (int l = 0; l < 4; l++) {
        int idx = tid + l * 256;
        int r = idx >> 3, j = idx & 7;
        uint32_t off = SWZ((uint32_t)(r * 128 + j * 16));
        *(uint4*)(sm + SM_QHI + off) = qh4[(long long)(n0 + r) * 128 + h * 8 + j];
        *(uint4*)(sm + SM_QLO + off) = ql4[(long long)(n0 + r) * 128 + h * 8 + j];
    }
    // ---- K/V tile 0 ----
#pragma unroll
    for (int l = 0; l < 2; l++) {
        int idx = tid + l * 256;
        int r = idx >> 3, j = idx & 7;
        uint32_t off = SWZ((uint32_t)(r * 128 + j * 16));
        *(uint4*)(sm + SM_KHI(0) + off) = qh4[(long long)r * 128 + 64 + h * 8 + j];
        *(uint4*)(sm + SM_KLO(0) + off) = ql4[(long long)r * 128 + 64 + h * 8 + j];
        *(uint4*)(sm + SM_VHI(0) + off) = vh4[(long long)r * 512 + j];
        *(uint4*)(sm + SM_VLO(0) + off) = vl4[(long long)r * 512 + j];
    }
    FPROXY();
    __syncthreads();

    u64 aQhi = mkdesc(sb + SM_QHI);
    u64 aQlo = mkdesc(sb + SM_QLO);

    // prologue: S(0)
    if (wid == 0) {
        if (elect1()) {
            u64 bKhi = mkdesc(sb + SM_KHI(0));
            u64 bKlo = mkdesc(sb + SM_KLO(0));
#pragma unroll
            for (int ks = 0; ks < 4; ks++)
                mma_ss(tb + TM_S, aQhi + ks * 2, bKhi + ks * 2, IDESC64, ks > 0);
#pragma unroll
            for (int ks = 0; ks < 4; ks++)
                mma_ss(tb + TM_S, aQhi + ks * 2, bKlo + ks * 2, IDESC64, 1u);
#pragma unroll
            for (int ks = 0; ks < 4; ks++)
                mma_ss(tb + TM_S, aQlo + ks * 2, bKhi + ks * 2, IDESC64, 1u);
            tc_commit(sb + SM_MBAR);
        }
    }

    float den = 0.f;
    uint32_t ph = 0;

#pragma unroll 1
    for (int t = 0; t < 64; t++) {
        mbar_wait(sb + SM_MBAR, ph); ph ^= 1;   // AV(t-1)+S(t) done
        TCF_AFTER();

        // prefetch K/V(t+1) (overlaps softmax)
        if (t < 63) {
            int m1 = (t + 1) * 64;
            int nb = (t + 1) & 1;
#pragma unroll
            for (int l = 0; l < 2; l++) {
                int idx = tid + l * 256;
                int r = idx >> 3, j = idx & 7;
                uint32_t off = SWZ((uint32_t)(r * 128 + j * 16));
                *(uint4*)(sm + SM_KHI(nb) + off) = qh4[(long long)(m1 + r) * 128 + 64 + h * 8 + j];
                *(uint4*)(sm + SM_KLO(nb) + off) = ql4[(long long)(m1 + r) * 128 + 64 + h * 8 + j];
                *(uint4*)(sm + SM_VHI(nb) + off) = vh4[(long long)r * 512 + m1 / 8 + j];
                *(uint4*)(sm + SM_VLO(nb) + off) = vl4[(long long)r * 512 + m1 / 8 + j];
            }
        }

        // softmax: ALL 8 warps; warp handles its subpartition rows x 32 cols
        {
            uint32_t sr[32];
            LDX32(sr, tb + TM_S + half * 32);
            TC_WAIT_LD();
            float p[32];
#pragma unroll
            for (int c = 0; c < 32; c++) p[c] = ex2f(__uint_as_float(sr[c]));
            float dsum = 0.f;
#pragma unroll
            for (int c = 0; c < 32; c++) dsum += p[c];
            den += dsum;

            uint32_t whi[16], wlo[16];
#pragma unroll
            for (int j = 0; j < 16; j++) {
                u16 ah = f2bf(p[2 * j]), ch = f2bf(p[2 * j + 1]);
                whi[j] = (uint32_t)ah | ((uint32_t)ch << 16);
                u16 al = f2bf(p[2 * j] - bf2f(ah)), cl = f2bf(p[2 * j + 1] - bf2f(ch));
                wlo[j] = (uint32_t)al | ((uint32_t)cl << 16);
            }
            STX16(tb + TM_PHI + half * 16 + lofs, whi);
            STX16(tb + TM_PLO + half * 16 + lofs, wlo);
            TC_WAIT_ST();
        }
        TCF_BEFORE();
        FPROXY();
        __syncthreads();

        // issue AV(t) (TS: P from TMEM) [+ S(t+1)], single commit
        if (wid == 0) {
            if (elect1()) {
                TCF_AFTER();
                int cb = t & 1;
                u64 bVhi = mkdesc(sb + SM_VHI(cb));
                u64 bVlo = mkdesc(sb + SM_VLO(cb));
#pragma unroll
                for (int ks = 0; ks < 4; ks++)
                    mma_ts(tb + TM_O, tb + TM_PHI + ks * 8, bVhi + ks * 2, IDESC64,
                           (t > 0 || ks > 0) ? 1u : 0u);
#pragma unroll
                for (int ks = 0; ks < 4; ks++)
                    mma_ts(tb + TM_O, tb + TM_PHI + ks * 8, bVlo + ks * 2, IDESC64, 1u);
#pragma unroll
                for (int ks = 0; ks < 4; ks++)
                    mma_ts(tb + TM_O, tb + TM_PLO + ks * 8, bVhi + ks * 2, IDESC64, 1u);
                if (t < 63) {
                    int nb = (t + 1) & 1;
                    u64 bKhi = mkdesc(sb + SM_KHI(nb));
                    u64 bKlo = mkdesc(sb + SM_KLO(nb));
#pragma unroll
                    for (int ks = 0; ks < 4; ks++)
                        mma_ss(tb + TM_S, aQhi + ks * 2, bKhi + ks * 2, IDESC64, ks > 0);
#pragma unroll
                    for (int ks = 0; ks < 4; ks++)
                        mma_ss(tb + TM_S, aQhi + ks * 2, bKlo + ks * 2, IDESC64, 1u);
#pragma unroll
                    for (int ks = 0; ks < 4; ks++)
                        mma_ss(tb + TM_S, aQlo + ks * 2, bKhi + ks * 2, IDESC64, 1u);
                }
                tc_commit(sb + SM_MBAR);
            }
        }
    }
    mbar_wait(sb + SM_MBAR, ph); ph ^= 1;   // final AV done

    // combine den halves: row r total = den[r] + den[r+128]
    *(float*)(sm + SM_DEN + tid * 4) = den;
    __syncthreads();

    // epilogue
    if (tid < 128) {
        TCF_AFTER();
        uint32_t orr[64];
        LDX32(orr, tb + TM_O);
        LDX32(orr + 32, tb + TM_O + 32);
        TC_WAIT_LD();
        float dtot = *(float*)(sm + SM_DEN + tid * 4) +
                     *(float*)(sm + SM_DEN + (tid + 128) * 4);
        float inv = 1.0f / dtot;
        long long obase = ((long long)b * NPIX + n0 + tid) * CDIM + h * DH;
        uint32_t whi[32], wlo[32];
#pragma unroll
        for (int j = 0; j < 32; j++) {
            float a = __uint_as_float(orr[2 * j]) * inv;
            float c = __uint_as_float(orr[2 * j + 1]) * inv;
            u16 ah = f2bf(a), ch = f2bf(c);
            whi[j] = (uint32_t)ah | ((uint32_t)ch << 16);
            u16 al = f2bf(a - bf2f(ah)), cl = f2bf(c - bf2f(ch));
            wlo[j] = (uint32_t)al | ((uint32_t)cl << 16);
        }
#pragma unroll
        for (int j = 0; j < 8; j++) {
            *(uint4*)(othi + obase + 8 * j) = *(uint4*)&whi[4 * j];
            *(uint4*)(otlo + obase + 8 * j) = *(uint4*)&wlo[4 * j];
        }
    }
    __syncthreads();
    if (wid == 0) {
        asm volatile("tcgen05.dealloc.cta_group::1.sync.aligned.b32 %0, %1;"
                     :: "r"(tb), "r"((uint32_t)ATT_TMCOLS));
    }
#else
    // compile-only fallback
    int tid = threadIdx.x;
    if (tid >= 128) return;
    int n0 = blockIdx.x * 128;
    int h = blockIdx.y, b = blockIdx.z;
    long long qb = (long long)b * NPIX * QKD;
    int r = n0 + tid;
    float q[64], o[64], den = 0.f;
#pragma unroll
    for (int d = 0; d < 64; d++) {
        q[d] = bf2f(qkthi[qb + (long long)r * QKD + h * 64 + d]) +
               bf2f(qktlo[qb + (long long)r * QKD + h * 64 + d]);
        o[d] = 0.f;
    }
    for (int key = 0; key < NPIX; key++) {
        float s = 0.f;
        for (int d = 0; d < 64; d++)
            s += q[d] * (bf2f(qkthi[qb + (long long)key * QKD + 512 + h * 64 + d]) +
                         bf2f(qktlo[qb + (long long)key * QKD + 512 + h * 64 + d]));
        float p = ex2f(s);
        den += p;
        for (int d = 0; d < 64; d++) {
            long long vi = ((long long)b * CDIM + h * 64 + d) * NPIX + key;
            o[d] += p * (bf2f(vthi[vi]) + bf2f(vtlo[vi]));
        }
    }
    long long ob = ((long long)b * NPIX + r) * CDIM + h * 64;
    for (int d = 0; d < 64; d++) {
        float v = o[d] / den;
        u16 hh = f2bf(v);
        othi[ob + d] = hh;
        otlo[ob + d] = f2bf(v - bf2f(hh));
    }
#endif
}

// ---------------------------------------------------------------------------
extern "C" void kernel_launch(void* const* d_in, const int* in_sizes, int n_in,
                              void* d_out, int out_size) {
    const float* x      = (const float*)d_in[0];
    const float* dw_w   = (const float*)d_in[1];
    const float* qkv_w  = (const float*)d_in[2];
    const float* proj_w = (const float*)d_in[3];
    const float* proj_b = (const float*)d_in[4];
    float* out = (float*)d_out;

    float* py;
    u16 *pythi, *pytlo, *pwhi, *pwlo, *ppwhi, *ppwlo;
    u16 *pqkthi, *pqktlo, *pvthi, *pvtlo, *pothi, *potlo;
    cudaGetSymbolAddress((void**)&py,     g_y);
    cudaGetSymbolAddress((void**)&pythi,  g_ythi);
    cudaGetSymbolAddress((void**)&pytlo,  g_ytlo);
    cudaGetSymbolAddress((void**)&pwhi,   g_whi);
    cudaGetSymbolAddress((void**)&pwlo,   g_wlo);
    cudaGetSymbolAddress((void**)&ppwhi,  g_pwhi);
    cudaGetSymbolAddress((void**)&ppwlo,  g_pwlo);
    cudaGetSymbolAddress((void**)&pqkthi, g_qkthi);
    cudaGetSymbolAddress((void**)&pqktlo, g_qktlo);
    cudaGetSymbolAddress((void**)&pvthi,  g_vthi);
    cudaGetSymbolAddress((void**)&pvtlo,  g_vtlo);
    cudaGetSymbolAddress((void**)&pothi,  g_othi);
    cudaGetSymbolAddress((void**)&potlo,  g_otlo);

    cudaFuncSetAttribute(k_attn, cudaFuncAttributeMaxDynamicSharedMemorySize, ATT_SMEM);
    cudaFuncSetAttribute(k_gemm_tc, cudaFuncAttributeMaxDynamicSharedMemorySize, GM_SMEM);

    k_dwconv<<<(TOTAL + 255) / 256, 256>>>(x, dw_w, py);
    k_cvt<<<(3 * CDIM * CDIM + 255) / 256, 256>>>(qkv_w, pwhi, pwlo, 3 * CDIM * CDIM);
    k_cvt<<<(CDIM * CDIM + 255) / 256, 256>>>(proj_w, ppwhi, ppwlo, CDIM * CDIM);
    {
        dim3 grid(NPIX / 32, CDIM / 32, BATCH);
        k_t2bf<<<grid, dim3(32, 8)>>>(py, pythi, pytlo);
    }

    long long sYT = (long long)NPIX * CDIM / 8;

    // qk GEMM: qkt[n][1024]
    {
        dim3 grid(NPIX / 128, QKD / 64, BATCH);
        k_gemm_tc<<<grid, 256, GM_SMEM>>>(
            (const uint4*)pythi, (const uint4*)pytlo, sYT,
            (const uint4*)pwhi, (const uint4*)pwlo, 0,
            pqkthi, pqktlo, nullptr, nullptr,
            (long long)NPIX * QKD, QKD, ATT_SCALE_L2E, 512);
    }
    // V GEMM: vt[c][n]
    {
        dim3 grid(CDIM / 128, NPIX / 64, BATCH);
        k_gemm_tc<<<grid, 256, GM_SMEM>>>(
            (const uint4*)(pwhi + 1024 * CDIM), (const uint4*)(pwlo + 1024 * CDIM), 0,
            (const uint4*)pythi, (const uint4*)pytlo, sYT,
            pvthi, pvtlo, nullptr, nullptr,
            (long long)CDIM * NPIX, NPIX, 1.0f, 0);
    }
    // attention
    {
        dim3 grid(NPIX / 128, HEADS, BATCH);
        k_attn<<<grid, 256, ATT_SMEM>>>(pqkthi, pqktlo, pvthi, pvtlo, pothi, potlo);
    }
    // proj GEMM + bias
    {
        dim3 grid(CDIM / 128, NPIX / 64, BATCH);
        k_gemm_tc<<<grid, 256, GM_SMEM>>>(
            (const uint4*)ppwhi, (const uint4*)ppwlo, 0,
            (const uint4*)pothi, (const uint4*)potlo, sYT,
            nullptr, nullptr, out, proj_b,
            (long long)CDIM * NPIX, NPIX, 1.0f, 0);
    }
}

// round 9
// speedup vs baseline: 1.4011x; 1.1964x over previous
#include <cuda_runtime.h>
#include <cuda_bf16.h>
#include <cstdint>

// ---------------------------------------------------------------------------
// LightweightSelfAttention  (B=2, C=512, H=W=64, heads=8, dh=64)
// All-tcgen05, bf16 2-way split.
// R9: attention loop reordered — S(t+1) issued BEFORE softmax(t) (overlap,
//     S double-buffered in TMEM, single in-order commit per iter);
//     Plo split product dropped (P stored bf16-only).
// ---------------------------------------------------------------------------

#if defined(__CUDA_ARCH_FEAT_SM103_ALL) || defined(__CUDA_ARCH_FEAT_SM100_ALL)
#define HAS_TC 1
#else
#define HAS_TC 0
#endif

#define BATCH 2
#define CDIM 512
#define HEADS 8
#define DH 64
#define NPIX 4096
#define TOTAL (BATCH*CDIM*NPIX)
#define QKD 1024

typedef unsigned short u16;
typedef unsigned long long u64;

__device__ float g_y[BATCH * CDIM * NPIX];
__device__ u16 g_ythi[BATCH * NPIX * CDIM];
__device__ u16 g_ytlo[BATCH * NPIX * CDIM];
__device__ u16 g_whi[3 * CDIM * CDIM];
__device__ u16 g_wlo[3 * CDIM * CDIM];
__device__ u16 g_pwhi[CDIM * CDIM];
__device__ u16 g_pwlo[CDIM * CDIM];
__device__ u16 g_qkthi[BATCH * NPIX * QKD];
__device__ u16 g_qktlo[BATCH * NPIX * QKD];
__device__ u16 g_vthi[BATCH * CDIM * NPIX];
__device__ u16 g_vtlo[BATCH * CDIM * NPIX];
__device__ u16 g_othi[BATCH * NPIX * CDIM];
__device__ u16 g_otlo[BATCH * NPIX * CDIM];

#define ATT_SCALE_L2E 0.18033688f   /* 0.125 * log2(e) */

// ---------------- helpers --------------------------------------------------
__device__ __forceinline__ uint32_t smem_u32(const void* p) {
    uint32_t a;
    asm("{ .reg .u64 t; cvta.to.shared.u64 t, %1; cvt.u32.u64 %0, t; }"
        : "=r"(a) : "l"(p));
    return a;
}
__device__ __forceinline__ u16 f2bf(float x) {
    return __bfloat16_as_ushort(__float2bfloat16_rn(x));
}
__device__ __forceinline__ float bf2f(u16 u) {
    return __bfloat162float(__ushort_as_bfloat16(u));
}
__device__ __forceinline__ float ex2f(float x) {
    float y; asm("ex2.approx.ftz.f32 %0, %1;" : "=f"(y) : "f"(x)); return y;
}
#define SWZ(o) ((o) ^ (((o) >> 3) & 0x70))

#if HAS_TC
__device__ __forceinline__ unsigned elect1() {
    unsigned p;
    asm volatile("{\n\t.reg .pred p;\n\telect.sync _|p, 0xFFFFFFFF;\n\t"
                 "selp.b32 %0, 1, 0, p;\n\t}" : "=r"(p));
    return p;
}
__device__ __forceinline__ void mma_ss(uint32_t d, u64 a, u64 b, uint32_t id, uint32_t en) {
    asm volatile("{\n\t.reg .pred p;\n\tsetp.ne.u32 p, %5, 0;\n\t"
        "tcgen05.mma.cta_group::1.kind::f16 [%0], %1, %2, %3, {%4,%4,%4,%4}, p;\n\t}"
        :: "r"(d), "l"(a), "l"(b), "r"(id), "r"(0u), "r"(en) : "memory");
}
__device__ __forceinline__ void mma_ts(uint32_t d, uint32_t a, u64 b, uint32_t id, uint32_t en) {
    asm volatile("{\n\t.reg .pred p;\n\tsetp.ne.u32 p, %5, 0;\n\t"
        "tcgen05.mma.cta_group::1.kind::f16 [%0], [%1], %2, %3, {%4,%4,%4,%4}, p;\n\t}"
        :: "r"(d), "r"(a), "l"(b), "r"(id), "r"(0u), "r"(en) : "memory");
}
__device__ __forceinline__ void tc_commit(uint32_t mbar) {
    asm volatile("tcgen05.commit.cta_group::1.mbarrier::arrive::one.shared::cluster.b64 [%0];"
                 :: "r"(mbar) : "memory");
}
__device__ __forceinline__ void mbar_init1(uint32_t mbar) {
    asm volatile("mbarrier.init.shared.b64 [%0], %1;" :: "r"(mbar), "r"(1u) : "memory");
}
__device__ __forceinline__ void mbar_wait(uint32_t mbar, uint32_t ph) {
    asm volatile("{\n\t.reg .pred P1;\n\tLAB1_%=:\n\t"
        "mbarrier.try_wait.parity.acquire.cta.shared::cta.b64 P1, [%0], %1, 0x989680;\n\t"
        "@P1 bra.uni LAB2_%=;\n\tbra.uni LAB1_%=;\n\tLAB2_%=:\n\t}"
        :: "r"(mbar), "r"(ph) : "memory");
}
#define TCF_AFTER()  asm volatile("tcgen05.fence::after_thread_sync;" ::: "memory")
#define TCF_BEFORE() asm volatile("tcgen05.fence::before_thread_sync;" ::: "memory")
#define FPROXY()     asm volatile("fence.proxy.async.shared::cta;" ::: "memory")
#define TC_WAIT_LD() asm volatile("tcgen05.wait::ld.sync.aligned;" ::: "memory")
#define TC_WAIT_ST() asm volatile("tcgen05.wait::st.sync.aligned;" ::: "memory")

#define LDX32(r, ta) \
    asm volatile("tcgen05.ld.sync.aligned.32x32b.x32.b32 " \
        "{%0, %1, %2, %3, %4, %5, %6, %7, %8, %9, %10, %11, %12, %13, %14, %15, " \
        " %16, %17, %18, %19, %20, %21, %22, %23, %24, %25, %26, %27, %28, %29, %30, %31}, [%32];" \
        : "=r"((r)[0]),  "=r"((r)[1]),  "=r"((r)[2]),  "=r"((r)[3]), \
          "=r"((r)[4]),  "=r"((r)[5]),  "=r"((r)[6]),  "=r"((r)[7]), \
          "=r"((r)[8]),  "=r"((r)[9]),  "=r"((r)[10]), "=r"((r)[11]), \
          "=r"((r)[12]), "=r"((r)[13]), "=r"((r)[14]), "=r"((r)[15]), \
          "=r"((r)[16]), "=r"((r)[17]), "=r"((r)[18]), "=r"((r)[19]), \
          "=r"((r)[20]), "=r"((r)[21]), "=r"((r)[22]), "=r"((r)[23]), \
          "=r"((r)[24]), "=r"((r)[25]), "=r"((r)[26]), "=r"((r)[27]), \
          "=r"((r)[28]), "=r"((r)[29]), "=r"((r)[30]), "=r"((r)[31]) \
        : "r"(ta))

#define STX16(ta, r) \
    asm volatile("tcgen05.st.sync.aligned.32x32b.x16.b32 [%0], " \
        "{%1, %2, %3, %4, %5, %6, %7, %8, %9, %10, %11, %12, %13, %14, %15, %16};" \
        :: "r"(ta), \
           "r"((r)[0]),  "r"((r)[1]),  "r"((r)[2]),  "r"((r)[3]), \
           "r"((r)[4]),  "r"((r)[5]),  "r"((r)[6]),  "r"((r)[7]), \
           "r"((r)[8]),  "r"((r)[9]),  "r"((r)[10]), "r"((r)[11]), \
           "r"((r)[12]), "r"((r)[13]), "r"((r)[14]), "r"((r)[15]) \
        : "memory")

#define DESC_K  ((2ull<<61)|(1ull<<46)|(64ull<<32)|(1ull<<16))
__device__ __forceinline__ u64 mkdesc(uint32_t addr) {
    return DESC_K | ((u64)(addr >> 4) & 0x3FFF);
}
#define IDESC64  ((1u<<4)|(1u<<7)|(1u<<10)|(8u<<17)|(8u<<24))    /* M=128 N=64 */
#endif  // HAS_TC

// ---------------- 1) depthwise 3x3 ----------------------------------------
__global__ void k_dwconv(const float* __restrict__ x,
                         const float* __restrict__ w,
                         float* __restrict__ y) {
    int idx = blockIdx.x * blockDim.x + threadIdx.x;
    if (idx >= TOTAL) return;
    int n = idx & (NPIX - 1);
    int c = (idx >> 12) & (CDIM - 1);
    int hh = n >> 6, ww = n & 63;
    const float* xb = x + (long long)(idx >> 12) * NPIX;
    const float* wc = w + c * 9;
    float s = 0.f;
#pragma unroll
    for (int i = 0; i < 3; i++) {
        int h2 = hh + i - 1;
        if ((unsigned)h2 < 64u) {
#pragma unroll
            for (int j = 0; j < 3; j++) {
                int w2 = ww + j - 1;
                if ((unsigned)w2 < 64u) s += xb[h2 * 64 + w2] * wc[i * 3 + j];
            }
        }
    }
    y[idx] = s;
}

// ---------------- 2) fp32 -> bf16 hi/lo ------------------------------------
__global__ void k_cvt(const float* __restrict__ src, u16* __restrict__ hi,
                      u16* __restrict__ lo, int n) {
    int i = blockIdx.x * blockDim.x + threadIdx.x;
    if (i >= n) return;
    float v = src[i];
    u16 h = f2bf(v);
    hi[i] = h;
    lo[i] = f2bf(v - bf2f(h));
}

// ---------------- 3) transpose+split ---------------------------------------
__global__ void k_t2bf(const float* __restrict__ y, u16* __restrict__ thi,
                       u16* __restrict__ tlo) {
    __shared__ float t[32][33];
    long long zo = (long long)blockIdx.z * CDIM * NPIX;
    long long zt = (long long)blockIdx.z * NPIX * CDIM;
    int c0 = blockIdx.y * 32, n0 = blockIdx.x * 32;
#pragma unroll
    for (int j = 0; j < 4; j++) {
        int c = c0 + threadIdx.y + j * 8;
        t[threadIdx.y + j * 8][threadIdx.x] = y[zo + (long long)c * NPIX + n0 + threadIdx.x];
    }
    __syncthreads();
#pragma unroll
    for (int j = 0; j < 4; j++) {
        int n = n0 + threadIdx.y + j * 8;
        float v = t[threadIdx.x][threadIdx.y + j * 8];
        u16 h = f2bf(v);
        thi[zt + (long long)n * CDIM + c0 + threadIdx.x] = h;
        tlo[zt + (long long)n * CDIM + c0 + threadIdx.x] = f2bf(v - bf2f(h));
    }
}

// ---------------- 4/5/7) tcgen05 GEMM (R8-exact: 128x64, serial) -----------
#define GM_TMEMPTR 0
#define GM_MBAR 8
#define GM_AHI 1024
#define GM_ALO (GM_AHI + 16384)
#define GM_BHI (GM_ALO + 16384)
#define GM_BLO (GM_BHI + 8192)
#define GM_SMEM (GM_BLO + 8192)

__global__ void __launch_bounds__(256) k_gemm_tc(
    const uint4* __restrict__ Ahi, const uint4* __restrict__ Alo, long long sA,
    const uint4* __restrict__ Bhi, const uint4* __restrict__ Blo, long long sB,
    u16* __restrict__ Ohi, u16* __restrict__ Olo,
    float* __restrict__ Ofp, const float* __restrict__ bias,
    long long sO, int ldo, float scale_q, int qcols) {
#if HAS_TC
    extern __shared__ char sm[];
    uint32_t sb = smem_u32(sm);
    int tid = threadIdx.x, wid = tid >> 5;
    int mrow0 = blockIdx.x * 128;
    int brow0 = blockIdx.y * 64;
    const uint4* Ah = Ahi + blockIdx.z * sA + (long long)mrow0 * 64;
    const uint4* Al = Alo + blockIdx.z * sA + (long long)mrow0 * 64;
    const uint4* Bh = Bhi + blockIdx.z * sB + (long long)brow0 * 64;
    const uint4* Bl = Blo + blockIdx.z * sB + (long long)brow0 * 64;

    if (wid == 0) {
        asm volatile("tcgen05.alloc.cta_group::1.sync.aligned.shared::cta.b32 [%0], %1;"
                     :: "r"(sb + GM_TMEMPTR), "r"(128u) : "memory");
    }
    if (tid == 0) mbar_init1(sb + GM_MBAR);
    __syncthreads();
    uint32_t tb;
    asm volatile("ld.shared.b32 %0, [%1];" : "=r"(tb) : "r"(sb + GM_TMEMPTR));

    u64 dAhi = mkdesc(sb + GM_AHI);
    u64 dAlo = mkdesc(sb + GM_ALO);
    u64 dBhi = mkdesc(sb + GM_BHI);
    u64 dBlo = mkdesc(sb + GM_BLO);

    uint32_t ph = 0;
#pragma unroll 1
    for (int kc = 0; kc < 8; kc++) {
        if (kc) { mbar_wait(sb + GM_MBAR, ph); ph ^= 1; }
        int k8 = kc * 8;
#pragma unroll
        for (int l = 0; l < 4; l++) {
            int idx = tid + l * 256;
            int r = idx >> 3, j = idx & 7;
            uint32_t off = SWZ((uint32_t)(r * 128 + j * 16));
            *(uint4*)(sm + GM_AHI + off) = Ah[r * 64 + k8 + j];
            *(uint4*)(sm + GM_ALO + off) = Al[r * 64 + k8 + j];
        }
#pragma unroll
        for (int l = 0; l < 2; l++) {
            int idx = tid + l * 256;
            int r = idx >> 3, j = idx & 7;
            uint32_t off = SWZ((uint32_t)(r * 128 + j * 16));
            *(uint4*)(sm + GM_BHI + off) = Bh[r * 64 + k8 + j];
            *(uint4*)(sm + GM_BLO + off) = Bl[r * 64 + k8 + j];
        }
        FPROXY();
        __syncthreads();
        if (wid == 0) {
            if (elect1()) {
#pragma unroll
                for (int ks = 0; ks < 4; ks++)
                    mma_ss(tb, dAhi + ks * 2, dBhi + ks * 2, IDESC64, !(kc == 0 && ks == 0));
#pragma unroll
                for (int ks = 0; ks < 4; ks++)
                    mma_ss(tb, dAhi + ks * 2, dBlo + ks * 2, IDESC64, 1u);
#pragma unroll
                for (int ks = 0; ks < 4; ks++)
                    mma_ss(tb, dAlo + ks * 2, dBhi + ks * 2, IDESC64, 1u);
                tc_commit(sb + GM_MBAR);
            }
        }
    }
    mbar_wait(sb + GM_MBAR, ph); ph ^= 1;

    if (tid < 128) {
        TCF_AFTER();
        uint32_t d[64];
        LDX32(d, tb);
        LDX32(d + 32, tb + 32);
        TC_WAIT_LD();
        int m = mrow0 + tid;
        long long obase = blockIdx.z * sO + (long long)m * ldo + brow0;
        if (Ofp) {
            float bv = bias ? bias[m] : 0.f;
#pragma unroll
            for (int j = 0; j < 16; j++) {
                float4 v = make_float4(__uint_as_float(d[4 * j]) + bv,
                                       __uint_as_float(d[4 * j + 1]) + bv,
                                       __uint_as_float(d[4 * j + 2]) + bv,
                                       __uint_as_float(d[4 * j + 3]) + bv);
                *(float4*)(Ofp + obase + 4 * j) = v;
            }
        } else {
            float sc = (brow0 < qcols) ? scale_q : 1.0f;
            uint32_t whi[32], wlo[32];
#pragma unroll
            for (int j = 0; j < 32; j++) {
                float a = __uint_as_float(d[2 * j]) * sc;
                float b = __uint_as_float(d[2 * j + 1]) * sc;
                u16 ah = f2bf(a), bh = f2bf(b);
                whi[j] = (uint32_t)ah | ((uint32_t)bh << 16);
                u16 al = f2bf(a - bf2f(ah)), bl = f2bf(b - bf2f(bh));
                wlo[j] = (uint32_t)al | ((uint32_t)bl << 16);
            }
#pragma unroll
            for (int j = 0; j < 8; j++) {
                *(uint4*)(Ohi + obase + 8 * j) = *(uint4*)&whi[4 * j];
                *(uint4*)(Olo + obase + 8 * j) = *(uint4*)&wlo[4 * j];
            }
        }
    }
    __syncthreads();
    if (wid == 0) {
        asm volatile("tcgen05.dealloc.cta_group::1.sync.aligned.b32 %0, %1;"
                     :: "r"(tb), "r"(128u));
    }
#else
    // compile-only fallback
    int tid = threadIdx.x;
    const u16* Ah = (const u16*)(Ahi + blockIdx.z * sA) + (long long)blockIdx.x * 128 * 512;
    const u16* Al = (const u16*)(Alo + blockIdx.z * sA) + (long long)blockIdx.x * 128 * 512;
    const u16* Bh = (const u16*)(Bhi + blockIdx.z * sB) + (long long)blockIdx.y * 64 * 512;
    const u16* Bl = (const u16*)(Blo + blockIdx.z * sB) + (long long)blockIdx.y * 64 * 512;
    for (int e = tid; e < 128 * 64; e += 256) {
        int r = e >> 6, j = e & 63;
        float s = 0.f;
        for (int k = 0; k < 512; k++)
            s += (bf2f(Ah[r * 512 + k]) + bf2f(Al[r * 512 + k])) *
                 (bf2f(Bh[j * 512 + k]) + bf2f(Bl[j * 512 + k]));
        int m = blockIdx.x * 128 + r;
        long long obase = blockIdx.z * sO + (long long)m * ldo + blockIdx.y * 64 + j;
        if (Ofp) {
            Ofp[obase] = s + (bias ? bias[m] : 0.f);
        } else {
            float sc = (blockIdx.y * 64 < qcols) ? scale_q : 1.0f;
            s *= sc;
            u16 h = f2bf(s);
            Ohi[obase] = h;
            Olo[obase] = f2bf(s - bf2f(h));
        }
    }
#endif
}

// ---------------- 6) attention: overlapped S / softmax, occ 2 --------------
#define SM_TMEMPTR 0
#define SM_MBAR 8
#define SM_DEN 1024
#define SM_QHI 2048
#define SM_QLO (SM_QHI + 16384)
#define SM_KHI(b) (34816 + (b) * 16384)
#define SM_KLO(b) (34816 + (b) * 16384 + 8192)
#define SM_VHI(b) (67584 + (b) * 16384)
#define SM_VLO(b) (67584 + (b) * 16384 + 8192)
#define ATT_SMEM 100352

#define TM_S(b) ((b) * 64)
#define TM_O 128
#define TM_PHI 192
#define ATT_TMCOLS 256

__global__ void __launch_bounds__(256) k_attn(
    const u16* __restrict__ qkthi, const u16* __restrict__ qktlo,
    const u16* __restrict__ vthi,  const u16* __restrict__ vtlo,
    u16* __restrict__ othi, u16* __restrict__ otlo) {
#if HAS_TC
    extern __shared__ char sm[];
    uint32_t sb = smem_u32(sm);
    int tid = threadIdx.x, wid = tid >> 5;
    int half = wid >> 2;               // 0: S cols 0-31, 1: cols 32-63
    uint32_t lofs = (uint32_t)(wid & 3) << 21;
    int n0 = blockIdx.x * 128;
    int h = blockIdx.y, b = blockIdx.z;
    const uint4* qh4 = (const uint4*)qkthi + (long long)b * NPIX * 128;
    const uint4* ql4 = (const uint4*)qktlo + (long long)b * NPIX * 128;
    const uint4* vh4 = (const uint4*)vthi + ((long long)b * CDIM + h * DH) * 512;
    const uint4* vl4 = (const uint4*)vtlo + ((long long)b * CDIM + h * DH) * 512;

    if (wid == 0) {
        asm volatile("tcgen05.alloc.cta_group::1.sync.aligned.shared::cta.b32 [%0], %1;"
                     :: "r"(sb + SM_TMEMPTR), "r"((uint32_t)ATT_TMCOLS) : "memory");
    }
    if (tid == 0) mbar_init1(sb + SM_MBAR);
    __syncthreads();
    uint32_t tb;
    asm volatile("ld.shared.b32 %0, [%1];" : "=r"(tb) : "r"(sb + SM_TMEMPTR));

    // ---- Q tile ----
#pragma unroll
    for (int l = 0; l < 4; l++) {
        int idx = tid + l * 256;
        int r = idx >> 3, j = idx & 7;
        uint32_t off = SWZ((uint32_t)(r * 128 + j * 16));
        *(uint4*)(sm + SM_QHI + off) = qh4[(long long)(n0 + r) * 128 + h * 8 + j];
        *(uint4*)(sm + SM_QLO + off) = ql4[(long long)(n0 + r) * 128 + h * 8 + j];
    }
    // ---- K(0), K(1), V(0) ----
#pragma unroll
    for (int l = 0; l < 2; l++) {
        int idx = tid + l * 256;
        int r = idx >> 3, j = idx & 7;
        uint32_t off = SWZ((uint32_t)(r * 128 + j * 16));
        *(uint4*)(sm + SM_KHI(0) + off) = qh4[(long long)r * 128 + 64 + h * 8 + j];
        *(uint4*)(sm + SM_KLO(0) + off) = ql4[(long long)r * 128 + 64 + h * 8 + j];
        *(uint4*)(sm + SM_KHI(1) + off) = qh4[(long long)(64 + r) * 128 + 64 + h * 8 + j];
        *(uint4*)(sm + SM_KLO(1) + off) = ql4[(long long)(64 + r) * 128 + 64 + h * 8 + j];
        *(uint4*)(sm + SM_VHI(0) + off) = vh4[(long long)r * 512 + j];
        *(uint4*)(sm + SM_VLO(0) + off) = vl4[(long long)r * 512 + j];
    }
    FPROXY();
    __syncthreads();

    u64 aQhi = mkdesc(sb + SM_QHI);
    u64 aQlo = mkdesc(sb + SM_QLO);

    // prologue: S(0), commit C(-1)
    if (wid == 0) {
        if (elect1()) {
            u64 bKhi = mkdesc(sb + SM_KHI(0));
            u64 bKlo = mkdesc(sb + SM_KLO(0));
#pragma unroll
            for (int ks = 0; ks < 4; ks++)
                mma_ss(tb + TM_S(0), aQhi + ks * 2, bKhi + ks * 2, IDESC64, ks > 0);
#pragma unroll
            for (int ks = 0; ks < 4; ks++)
                mma_ss(tb + TM_S(0), aQhi + ks * 2, bKlo + ks * 2, IDESC64, 1u);
#pragma unroll
            for (int ks = 0; ks < 4; ks++)
                mma_ss(tb + TM_S(0), aQlo + ks * 2, bKhi + ks * 2, IDESC64, 1u);
            tc_commit(sb + SM_MBAR);
        }
    }

    float den = 0.f;
    uint32_t ph = 0;

#pragma unroll 1
    for (int t = 0; t < 64; t++) {
        mbar_wait(sb + SM_MBAR, ph); ph ^= 1;   // S(t) + AV(t-1) done (in-order)
        TCF_AFTER();

        // issue S(t+1) NOW (overlaps softmax(t) below), no commit yet
        if (t < 63 && wid == 0) {
            if (elect1()) {
                int nb = (t + 1) & 1;
                u64 bKhi = mkdesc(sb + SM_KHI(nb));
                u64 bKlo = mkdesc(sb + SM_KLO(nb));
#pragma unroll
                for (int ks = 0; ks < 4; ks++)
                    mma_ss(tb + TM_S(nb), aQhi + ks * 2, bKhi + ks * 2, IDESC64, ks > 0);
#pragma unroll
                for (int ks = 0; ks < 4; ks++)
                    mma_ss(tb + TM_S(nb), aQhi + ks * 2, bKlo + ks * 2, IDESC64, 1u);
#pragma unroll
                for (int ks = 0; ks < 4; ks++)
                    mma_ss(tb + TM_S(nb), aQlo + ks * 2, bKhi + ks * 2, IDESC64, 1u);
            }
        }

        // prefetch K(t+2) into buf t&1 (K(t) consumed by S(t): done)
        if (t <= 61) {
            int m2 = (t + 2) * 64;
#pragma unroll
            for (int l = 0; l < 2; l++) {
                int idx = tid + l * 256;
                int r = idx >> 3, j = idx & 7;
                uint32_t off = SWZ((uint32_t)(r * 128 + j * 16));
                *(uint4*)(sm + SM_KHI(t & 1) + off) = qh4[(long long)(m2 + r) * 128 + 64 + h * 8 + j];
                *(uint4*)(sm + SM_KLO(t & 1) + off) = ql4[(long long)(m2 + r) * 128 + 64 + h * 8 + j];
            }
        }
        // prefetch V(t+1) into buf (t+1)&1 (V(t-1) consumed by AV(t-1): done)
        if (t <= 62) {
            int m1 = (t + 1) * 8;
#pragma unroll
            for (int l = 0; l < 2; l++) {
                int idx = tid + l * 256;
                int r = idx >> 3, j = idx & 7;
                uint32_t off = SWZ((uint32_t)(r * 128 + j * 16));
                *(uint4*)(sm + SM_VHI((t + 1) & 1) + off) = vh4[(long long)r * 512 + m1 + j];
                *(uint4*)(sm + SM_VLO((t + 1) & 1) + off) = vl4[(long long)r * 512 + m1 + j];
            }
        }

        // softmax(t): 8 warps, S buf t&1; P stored bf16-only (no lo split)
        {
            uint32_t sr[32];
            LDX32(sr, tb + TM_S(t & 1) + half * 32);
            TC_WAIT_LD();
            float p[32];
#pragma unroll
            for (int c = 0; c < 32; c++) p[c] = ex2f(__uint_as_float(sr[c]));
            float dsum = 0.f;
#pragma unroll
            for (int c = 0; c < 32; c++) dsum += p[c];
            den += dsum;

            uint32_t whi[16];
#pragma unroll
            for (int j = 0; j < 16; j++) {
                u16 ah = f2bf(p[2 * j]), ch = f2bf(p[2 * j + 1]);
                whi[j] = (uint32_t)ah | ((uint32_t)ch << 16);
            }
            STX16(tb + TM_PHI + half * 16 + lofs, whi);
            TC_WAIT_ST();
        }
        TCF_BEFORE();
        FPROXY();
        __syncthreads();

        // issue AV(t): Phi x (Vhi + Vlo), commit covers S(t+1)+AV(t)
        if (wid == 0) {
            if (elect1()) {
                TCF_AFTER();
                u64 dVhi = mkdesc(sb + SM_VHI(t & 1));
                u64 dVlo = mkdesc(sb + SM_VLO(t & 1));
#pragma unroll
                for (int ks = 0; ks < 4; ks++)
                    mma_ts(tb + TM_O, tb + TM_PHI + ks * 8, dVhi + ks * 2, IDESC64,
                           (t > 0 || ks > 0) ? 1u : 0u);
#pragma unroll
                for (int ks = 0; ks < 4; ks++)
                    mma_ts(tb + TM_O, tb + TM_PHI + ks * 8, dVlo + ks * 2, IDESC64, 1u);
                tc_commit(sb + SM_MBAR);
            }
        }
    }
    mbar_wait(sb + SM_MBAR, ph); ph ^= 1;   // final AV done

    // combine den halves
    *(float*)(sm + SM_DEN + tid * 4) = den;
    __syncthreads();

    // epilogue
    if (tid < 128) {
        TCF_AFTER();
        uint32_t orr[64];
        LDX32(orr, tb + TM_O);
        LDX32(orr + 32, tb + TM_O + 32);
        TC_WAIT_LD();
        float dtot = *(float*)(sm + SM_DEN + tid * 4) +
                     *(float*)(sm + SM_DEN + (tid + 128) * 4);
        float inv = 1.0f / dtot;
        long long obase = ((long long)b * NPIX + n0 + tid) * CDIM + h * DH;
        uint32_t whi[32], wlo[32];
#pragma unroll
        for (int j = 0; j < 32; j++) {
            float a = __uint_as_float(orr[2 * j]) * inv;
            float c = __uint_as_float(orr[2 * j + 1]) * inv;
            u16 ah = f2bf(a), ch = f2bf(c);
            whi[j] = (uint32_t)ah | ((uint32_t)ch << 16);
            u16 al = f2bf(a - bf2f(ah)), cl = f2bf(c - bf2f(ch));
            wlo[j] = (uint32_t)al | ((uint32_t)cl << 16);
        }
#pragma unroll
        for (int j = 0; j < 8; j++) {
            *(uint4*)(othi + obase + 8 * j) = *(uint4*)&whi[4 * j];
            *(uint4*)(otlo + obase + 8 * j) = *(uint4*)&wlo[4 * j];
        }
    }
    __syncthreads();
    if (wid == 0) {
        asm volatile("tcgen05.dealloc.cta_group::1.sync.aligned.b32 %0, %1;"
                     :: "r"(tb), "r"((uint32_t)ATT_TMCOLS));
    }
#else
    // compile-only fallback
    int tid = threadIdx.x;
    if (tid >= 128) return;
    int n0 = blockIdx.x * 128;
    int h = blockIdx.y, b = blockIdx.z;
    long long qb = (long long)b * NPIX * QKD;
    int r = n0 + tid;
    float q[64], o[64], den = 0.f;
#pragma unroll
    for (int d = 0; d < 64; d++) {
        q[d] = bf2f(qkthi[qb + (long long)r * QKD + h * 64 + d]) +
               bf2f(qktlo[qb + (long long)r * QKD + h * 64 + d]);
        o[d] = 0.f;
    }
    for (int key = 0; key < NPIX; key++) {
        float s = 0.f;
        for (int d = 0; d < 64; d++)
            s += q[d] * (bf2f(qkthi[qb + (long long)key * QKD + 512 + h * 64 + d]) +
                         bf2f(qktlo[qb + (long long)key * QKD + 512 + h * 64 + d]));
        float p = ex2f(s);
        den += p;
        for (int d = 0; d < 64; d++) {
            long long vi = ((long long)b * CDIM + h * 64 + d) * NPIX + key;
            o[d] += p * (bf2f(vthi[vi]) + bf2f(vtlo[vi]));
        }
    }
    long long ob = ((long long)b * NPIX + r) * CDIM + h * 64;
    for (int d = 0; d < 64; d++) {
        float v = o[d] / den;
        u16 hh = f2bf(v);
        othi[ob + d] = hh;
        otlo[ob + d] = f2bf(v - bf2f(hh));
    }
#endif
}

// ---------------------------------------------------------------------------
extern "C" void kernel_launch(void* const* d_in, const int* in_sizes, int n_in,
                              void* d_out, int out_size) {
    const float* x      = (const float*)d_in[0];
    const float* dw_w   = (const float*)d_in[1];
    const float* qkv_w  = (const float*)d_in[2];
    const float* proj_w = (const float*)d_in[3];
    const float* proj_b = (const float*)d_in[4];
    float* out = (float*)d_out;

    float* py;
    u16 *pythi, *pytlo, *pwhi, *pwlo, *ppwhi, *ppwlo;
    u16 *pqkthi, *pqktlo, *pvthi, *pvtlo, *pothi, *potlo;
    cudaGetSymbolAddress((void**)&py,     g_y);
    cudaGetSymbolAddress((void**)&pythi,  g_ythi);
    cudaGetSymbolAddress((void**)&pytlo,  g_ytlo);
    cudaGetSymbolAddress((void**)&pwhi,   g_whi);
    cudaGetSymbolAddress((void**)&pwlo,   g_wlo);
    cudaGetSymbolAddress((void**)&ppwhi,  g_pwhi);
    cudaGetSymbolAddress((void**)&ppwlo,  g_pwlo);
    cudaGetSymbolAddress((void**)&pqkthi, g_qkthi);
    cudaGetSymbolAddress((void**)&pqktlo, g_qktlo);
    cudaGetSymbolAddress((void**)&pvthi,  g_vthi);
    cudaGetSymbolAddress((void**)&pvtlo,  g_vtlo);
    cudaGetSymbolAddress((void**)&pothi,  g_othi);
    cudaGetSymbolAddress((void**)&potlo,  g_otlo);

    cudaFuncSetAttribute(k_attn, cudaFuncAttributeMaxDynamicSharedMemorySize, ATT_SMEM);
    cudaFuncSetAttribute(k_gemm_tc, cudaFuncAttributeMaxDynamicSharedMemorySize, GM_SMEM);

    k_dwconv<<<(TOTAL + 255) / 256, 256>>>(x, dw_w, py);
    k_cvt<<<(3 * CDIM * CDIM + 255) / 256, 256>>>(qkv_w, pwhi, pwlo, 3 * CDIM * CDIM);
    k_cvt<<<(CDIM * CDIM + 255) / 256, 256>>>(proj_w, ppwhi, ppwlo, CDIM * CDIM);
    {
        dim3 grid(NPIX / 32, CDIM / 32, BATCH);
        k_t2bf<<<grid, dim3(32, 8)>>>(py, pythi, pytlo);
    }

    long long sYT = (long long)NPIX * CDIM / 8;

    // qk GEMM: qkt[n][1024]
    {
        dim3 grid(NPIX / 128, QKD / 64, BATCH);
        k_gemm_tc<<<grid, 256, GM_SMEM>>>(
            (const uint4*)pythi, (const uint4*)pytlo, sYT,
            (const uint4*)pwhi, (const uint4*)pwlo, 0,
            pqkthi, pqktlo, nullptr, nullptr,
            (long long)NPIX * QKD, QKD, ATT_SCALE_L2E, 512);
    }
    // V GEMM: vt[c][n]
    {
        dim3 grid(CDIM / 128, NPIX / 64, BATCH);
        k_gemm_tc<<<grid, 256, GM_SMEM>>>(
            (const uint4*)(pwhi + 1024 * CDIM), (const uint4*)(pwlo + 1024 * CDIM), 0,
            (const uint4*)pythi, (const uint4*)pytlo, sYT,
            pvthi, pvtlo, nullptr, nullptr,
            (long long)CDIM * NPIX, NPIX, 1.0f, 0);
    }
    // attention
    {
        dim3 grid(NPIX / 128, HEADS, BATCH);
        k_attn<<<grid, 256, ATT_SMEM>>>(pqkthi, pqktlo, pvthi, pvtlo, pothi, potlo);
    }
    // proj GEMM + bias
    {
        dim3 grid(CDIM / 128, NPIX / 64, BATCH);
        k_gemm_tc<<<grid, 256, GM_SMEM>>>(
            (const uint4*)ppwhi, (const uint4*)ppwlo, 0,
            (const uint4*)pothi, (const uint4*)potlo, sYT,
            nullptr, nullptr, out, proj_b,
            (long long)CDIM * NPIX, NPIX, 1.0f, 0);
    }
}

// round 11
// speedup vs baseline: 1.6165x; 1.1537x over previous
#include <cuda_runtime.h>
#include <cuda_bf16.h>
#include <cuda_fp16.h>
#include <cstdint>

// ---------------------------------------------------------------------------
// LightweightSelfAttention  (B=2, C=512, H=W=64, heads=8, dh=64)
// All-tcgen05. Q/K: bf16 2-way split (3-product S). P and V: fp16 single.
// R11: fix R10 prologue bug — V(0) tile fully loaded (all 512 uint4; the
//      `if (l==0)` guard left rows 32-63 uninitialized -> NaN).
// ---------------------------------------------------------------------------

#if defined(__CUDA_ARCH_FEAT_SM103_ALL) || defined(__CUDA_ARCH_FEAT_SM100_ALL)
#define HAS_TC 1
#else
#define HAS_TC 0
#endif

#define BATCH 2
#define CDIM 512
#define HEADS 8
#define DH 64
#define NPIX 4096
#define TOTAL (BATCH*CDIM*NPIX)
#define QKD 1024

typedef unsigned short u16;
typedef unsigned long long u64;

__device__ float g_y[BATCH * CDIM * NPIX];
__device__ u16 g_ythi[BATCH * NPIX * CDIM];
__device__ u16 g_ytlo[BATCH * NPIX * CDIM];
__device__ u16 g_whi[3 * CDIM * CDIM];
__device__ u16 g_wlo[3 * CDIM * CDIM];
__device__ u16 g_pwhi[CDIM * CDIM];
__device__ u16 g_pwlo[CDIM * CDIM];
__device__ u16 g_qkthi[BATCH * NPIX * QKD];
__device__ u16 g_qktlo[BATCH * NPIX * QKD];
__device__ u16 g_vth[BATCH * CDIM * NPIX];     // fp16 V^T
__device__ u16 g_othi[BATCH * NPIX * CDIM];
__device__ u16 g_otlo[BATCH * NPIX * CDIM];

#define ATT_SCALE_L2E 0.18033688f   /* 0.125 * log2(e) */

// ---------------- helpers --------------------------------------------------
__device__ __forceinline__ uint32_t smem_u32(const void* p) {
    uint32_t a;
    asm("{ .reg .u64 t; cvta.to.shared.u64 t, %1; cvt.u32.u64 %0, t; }"
        : "=r"(a) : "l"(p));
    return a;
}
__device__ __forceinline__ u16 f2bf(float x) {
    return __bfloat16_as_ushort(__float2bfloat16_rn(x));
}
__device__ __forceinline__ float bf2f(u16 u) {
    return __bfloat162float(__ushort_as_bfloat16(u));
}
__device__ __forceinline__ u16 f2h(float x) {
    return __half_as_ushort(__float2half_rn(x));
}
__device__ __forceinline__ float h2f(u16 u) {
    return __half2float(__ushort_as_half(u));
}
__device__ __forceinline__ float ex2f(float x) {
    float y; asm("ex2.approx.ftz.f32 %0, %1;" : "=f"(y) : "f"(x)); return y;
}
#define SWZ(o) ((o) ^ (((o) >> 3) & 0x70))

#if HAS_TC
__device__ __forceinline__ unsigned elect1() {
    unsigned p;
    asm volatile("{\n\t.reg .pred p;\n\telect.sync _|p, 0xFFFFFFFF;\n\t"
                 "selp.b32 %0, 1, 0, p;\n\t}" : "=r"(p));
    return p;
}
__device__ __forceinline__ void mma_ss(uint32_t d, u64 a, u64 b, uint32_t id, uint32_t en) {
    asm volatile("{\n\t.reg .pred p;\n\tsetp.ne.u32 p, %5, 0;\n\t"
        "tcgen05.mma.cta_group::1.kind::f16 [%0], %1, %2, %3, {%4,%4,%4,%4}, p;\n\t}"
        :: "r"(d), "l"(a), "l"(b), "r"(id), "r"(0u), "r"(en) : "memory");
}
__device__ __forceinline__ void mma_ts(uint32_t d, uint32_t a, u64 b, uint32_t id, uint32_t en) {
    asm volatile("{\n\t.reg .pred p;\n\tsetp.ne.u32 p, %5, 0;\n\t"
        "tcgen05.mma.cta_group::1.kind::f16 [%0], [%1], %2, %3, {%4,%4,%4,%4}, p;\n\t}"
        :: "r"(d), "r"(a), "l"(b), "r"(id), "r"(0u), "r"(en) : "memory");
}
__device__ __forceinline__ void tc_commit(uint32_t mbar) {
    asm volatile("tcgen05.commit.cta_group::1.mbarrier::arrive::one.shared::cluster.b64 [%0];"
                 :: "r"(mbar) : "memory");
}
__device__ __forceinline__ void mbar_init1(uint32_t mbar) {
    asm volatile("mbarrier.init.shared.b64 [%0], %1;" :: "r"(mbar), "r"(1u) : "memory");
}
__device__ __forceinline__ void mbar_wait(uint32_t mbar, uint32_t ph) {
    asm volatile("{\n\t.reg .pred P1;\n\tLAB1_%=:\n\t"
        "mbarrier.try_wait.parity.acquire.cta.shared::cta.b64 P1, [%0], %1, 0x989680;\n\t"
        "@P1 bra.uni LAB2_%=;\n\tbra.uni LAB1_%=;\n\tLAB2_%=:\n\t}"
        :: "r"(mbar), "r"(ph) : "memory");
}
#define TCF_AFTER()  asm volatile("tcgen05.fence::after_thread_sync;" ::: "memory")
#define TCF_BEFORE() asm volatile("tcgen05.fence::before_thread_sync;" ::: "memory")
#define FPROXY()     asm volatile("fence.proxy.async.shared::cta;" ::: "memory")
#define TC_WAIT_LD() asm volatile("tcgen05.wait::ld.sync.aligned;" ::: "memory")
#define TC_WAIT_ST() asm volatile("tcgen05.wait::st.sync.aligned;" ::: "memory")

#define LDX32(r, ta) \
    asm volatile("tcgen05.ld.sync.aligned.32x32b.x32.b32 " \
        "{%0, %1, %2, %3, %4, %5, %6, %7, %8, %9, %10, %11, %12, %13, %14, %15, " \
        " %16, %17, %18, %19, %20, %21, %22, %23, %24, %25, %26, %27, %28, %29, %30, %31}, [%32];" \
        : "=r"((r)[0]),  "=r"((r)[1]),  "=r"((r)[2]),  "=r"((r)[3]), \
          "=r"((r)[4]),  "=r"((r)[5]),  "=r"((r)[6]),  "=r"((r)[7]), \
          "=r"((r)[8]),  "=r"((r)[9]),  "=r"((r)[10]), "=r"((r)[11]), \
          "=r"((r)[12]), "=r"((r)[13]), "=r"((r)[14]), "=r"((r)[15]), \
          "=r"((r)[16]), "=r"((r)[17]), "=r"((r)[18]), "=r"((r)[19]), \
          "=r"((r)[20]), "=r"((r)[21]), "=r"((r)[22]), "=r"((r)[23]), \
          "=r"((r)[24]), "=r"((r)[25]), "=r"((r)[26]), "=r"((r)[27]), \
          "=r"((r)[28]), "=r"((r)[29]), "=r"((r)[30]), "=r"((r)[31]) \
        : "r"(ta))

#define STX16(ta, r) \
    asm volatile("tcgen05.st.sync.aligned.32x32b.x16.b32 [%0], " \
        "{%1, %2, %3, %4, %5, %6, %7, %8, %9, %10, %11, %12, %13, %14, %15, %16};" \
        :: "r"(ta), \
           "r"((r)[0]),  "r"((r)[1]),  "r"((r)[2]),  "r"((r)[3]), \
           "r"((r)[4]),  "r"((r)[5]),  "r"((r)[6]),  "r"((r)[7]), \
           "r"((r)[8]),  "r"((r)[9]),  "r"((r)[10]), "r"((r)[11]), \
           "r"((r)[12]), "r"((r)[13]), "r"((r)[14]), "r"((r)[15]) \
        : "memory")

#define DESC_K  ((2ull<<61)|(1ull<<46)|(64ull<<32)|(1ull<<16))
__device__ __forceinline__ u64 mkdesc(uint32_t addr) {
    return DESC_K | ((u64)(addr >> 4) & 0x3FFF);
}
#define IDESC64   ((1u<<4)|(1u<<7)|(1u<<10)|(8u<<17)|(8u<<24))  /* bf16 x bf16 */
#define IDESC64H  ((1u<<4)|(8u<<17)|(8u<<24))                   /* fp16 x fp16 */
#endif  // HAS_TC

// ---------------- 1) depthwise 3x3 ----------------------------------------
__global__ void k_dwconv(const float* __restrict__ x,
                         const float* __restrict__ w,
                         float* __restrict__ y) {
    int idx = blockIdx.x * blockDim.x + threadIdx.x;
    if (idx >= TOTAL) return;
    int n = idx & (NPIX - 1);
    int c = (idx >> 12) & (CDIM - 1);
    int hh = n >> 6, ww = n & 63;
    const float* xb = x + (long long)(idx >> 12) * NPIX;
    const float* wc = w + c * 9;
    float s = 0.f;
#pragma unroll
    for (int i = 0; i < 3; i++) {
        int h2 = hh + i - 1;
        if ((unsigned)h2 < 64u) {
#pragma unroll
            for (int j = 0; j < 3; j++) {
                int w2 = ww + j - 1;
                if ((unsigned)w2 < 64u) s += xb[h2 * 64 + w2] * wc[i * 3 + j];
            }
        }
    }
    y[idx] = s;
}

// ---------------- 2) fp32 -> bf16 hi/lo ------------------------------------
__global__ void k_cvt(const float* __restrict__ src, u16* __restrict__ hi,
                      u16* __restrict__ lo, int n) {
    int i = blockIdx.x * blockDim.x + threadIdx.x;
    if (i >= n) return;
    float v = src[i];
    u16 h = f2bf(v);
    hi[i] = h;
    lo[i] = f2bf(v - bf2f(h));
}

// ---------------- 3) transpose+split ---------------------------------------
__global__ void k_t2bf(const float* __restrict__ y, u16* __restrict__ thi,
                       u16* __restrict__ tlo) {
    __shared__ float t[32][33];
    long long zo = (long long)blockIdx.z * CDIM * NPIX;
    long long zt = (long long)blockIdx.z * NPIX * CDIM;
    int c0 = blockIdx.y * 32, n0 = blockIdx.x * 32;
#pragma unroll
    for (int j = 0; j < 4; j++) {
        int c = c0 + threadIdx.y + j * 8;
        t[threadIdx.y + j * 8][threadIdx.x] = y[zo + (long long)c * NPIX + n0 + threadIdx.x];
    }
    __syncthreads();
#pragma unroll
    for (int j = 0; j < 4; j++) {
        int n = n0 + threadIdx.y + j * 8;
        float v = t[threadIdx.x][threadIdx.y + j * 8];
        u16 h = f2bf(v);
        thi[zt + (long long)n * CDIM + c0 + threadIdx.x] = h;
        tlo[zt + (long long)n * CDIM + c0 + threadIdx.x] = f2bf(v - bf2f(h));
    }
}

// ---------------- 4/5/7) tcgen05 GEMM (128x64, serial commits) -------------
#define GM_TMEMPTR 0
#define GM_MBAR 8
#define GM_AHI 1024
#define GM_ALO (GM_AHI + 16384)
#define GM_BHI (GM_ALO + 16384)
#define GM_BLO (GM_BHI + 8192)
#define GM_SMEM (GM_BLO + 8192)

__global__ void __launch_bounds__(256) k_gemm_tc(
    const uint4* __restrict__ Ahi, const uint4* __restrict__ Alo, long long sA,
    const uint4* __restrict__ Bhi, const uint4* __restrict__ Blo, long long sB,
    u16* __restrict__ Ohi, u16* __restrict__ Olo,
    float* __restrict__ Ofp, const float* __restrict__ bias,
    long long sO, int ldo, float scale_q, int qcols, int out_half) {
#if HAS_TC
    extern __shared__ char sm[];
    uint32_t sb = smem_u32(sm);
    int tid = threadIdx.x, wid = tid >> 5;
    int mrow0 = blockIdx.x * 128;
    int brow0 = blockIdx.y * 64;
    const uint4* Ah = Ahi + blockIdx.z * sA + (long long)mrow0 * 64;
    const uint4* Al = Alo + blockIdx.z * sA + (long long)mrow0 * 64;
    const uint4* Bh = Bhi + blockIdx.z * sB + (long long)brow0 * 64;
    const uint4* Bl = Blo + blockIdx.z * sB + (long long)brow0 * 64;

    if (wid == 0) {
        asm volatile("tcgen05.alloc.cta_group::1.sync.aligned.shared::cta.b32 [%0], %1;"
                     :: "r"(sb + GM_TMEMPTR), "r"(128u) : "memory");
    }
    if (tid == 0) mbar_init1(sb + GM_MBAR);
    __syncthreads();
    uint32_t tb;
    asm volatile("ld.shared.b32 %0, [%1];" : "=r"(tb) : "r"(sb + GM_TMEMPTR));

    u64 dAhi = mkdesc(sb + GM_AHI);
    u64 dAlo = mkdesc(sb + GM_ALO);
    u64 dBhi = mkdesc(sb + GM_BHI);
    u64 dBlo = mkdesc(sb + GM_BLO);

    uint32_t ph = 0;
#pragma unroll 1
    for (int kc = 0; kc < 8; kc++) {
        if (kc) { mbar_wait(sb + GM_MBAR, ph); ph ^= 1; }
        int k8 = kc * 8;
#pragma unroll
        for (int l = 0; l < 4; l++) {
            int idx = tid + l * 256;
            int r = idx >> 3, j = idx & 7;
            uint32_t off = SWZ((uint32_t)(r * 128 + j * 16));
            *(uint4*)(sm + GM_AHI + off) = Ah[r * 64 + k8 + j];
            *(uint4*)(sm + GM_ALO + off) = Al[r * 64 + k8 + j];
        }
#pragma unroll
        for (int l = 0; l < 2; l++) {
            int idx = tid + l * 256;
            int r = idx >> 3, j = idx & 7;
            uint32_t off = SWZ((uint32_t)(r * 128 + j * 16));
            *(uint4*)(sm + GM_BHI + off) = Bh[r * 64 + k8 + j];
            *(uint4*)(sm + GM_BLO + off) = Bl[r * 64 + k8 + j];
        }
        FPROXY();
        __syncthreads();
        if (wid == 0) {
            if (elect1()) {
#pragma unroll
                for (int ks = 0; ks < 4; ks++)
                    mma_ss(tb, dAhi + ks * 2, dBhi + ks * 2, IDESC64, !(kc == 0 && ks == 0));
#pragma unroll
                for (int ks = 0; ks < 4; ks++)
                    mma_ss(tb, dAhi + ks * 2, dBlo + ks * 2, IDESC64, 1u);
#pragma unroll
                for (int ks = 0; ks < 4; ks++)
                    mma_ss(tb, dAlo + ks * 2, dBhi + ks * 2, IDESC64, 1u);
                tc_commit(sb + GM_MBAR);
            }
        }
    }
    mbar_wait(sb + GM_MBAR, ph); ph ^= 1;

    if (tid < 128) {
        TCF_AFTER();
        uint32_t d[64];
        LDX32(d, tb);
        LDX32(d + 32, tb + 32);
        TC_WAIT_LD();
        int m = mrow0 + tid;
        long long obase = blockIdx.z * sO + (long long)m * ldo + brow0;
        if (Ofp) {
            float bv = bias ? bias[m] : 0.f;
#pragma unroll
            for (int j = 0; j < 16; j++) {
                float4 v = make_float4(__uint_as_float(d[4 * j]) + bv,
                                       __uint_as_float(d[4 * j + 1]) + bv,
                                       __uint_as_float(d[4 * j + 2]) + bv,
                                       __uint_as_float(d[4 * j + 3]) + bv);
                *(float4*)(Ofp + obase + 4 * j) = v;
            }
        } else if (out_half) {
            uint32_t w[32];
#pragma unroll
            for (int j = 0; j < 32; j++) {
                u16 a = f2h(__uint_as_float(d[2 * j]));
                u16 c = f2h(__uint_as_float(d[2 * j + 1]));
                w[j] = (uint32_t)a | ((uint32_t)c << 16);
            }
#pragma unroll
            for (int j = 0; j < 8; j++)
                *(uint4*)(Ohi + obase + 8 * j) = *(uint4*)&w[4 * j];
        } else {
            float sc = (brow0 < qcols) ? scale_q : 1.0f;
            uint32_t whi[32], wlo[32];
#pragma unroll
            for (int j = 0; j < 32; j++) {
                float a = __uint_as_float(d[2 * j]) * sc;
                float b = __uint_as_float(d[2 * j + 1]) * sc;
                u16 ah = f2bf(a), bh = f2bf(b);
                whi[j] = (uint32_t)ah | ((uint32_t)bh << 16);
                u16 al = f2bf(a - bf2f(ah)), bl = f2bf(b - bf2f(bh));
                wlo[j] = (uint32_t)al | ((uint32_t)bl << 16);
            }
#pragma unroll
            for (int j = 0; j < 8; j++) {
                *(uint4*)(Ohi + obase + 8 * j) = *(uint4*)&whi[4 * j];
                *(uint4*)(Olo + obase + 8 * j) = *(uint4*)&wlo[4 * j];
            }
        }
    }
    __syncthreads();
    if (wid == 0) {
        asm volatile("tcgen05.dealloc.cta_group::1.sync.aligned.b32 %0, %1;"
                     :: "r"(tb), "r"(128u));
    }
#else
    // compile-only fallback
    int tid = threadIdx.x;
    const u16* Ah = (const u16*)(Ahi + blockIdx.z * sA) + (long long)blockIdx.x * 128 * 512;
    const u16* Al = (const u16*)(Alo + blockIdx.z * sA) + (long long)blockIdx.x * 128 * 512;
    const u16* Bh = (const u16*)(Bhi + blockIdx.z * sB) + (long long)blockIdx.y * 64 * 512;
    const u16* Bl = (const u16*)(Blo + blockIdx.z * sB) + (long long)blockIdx.y * 64 * 512;
    for (int e = tid; e < 128 * 64; e += 256) {
        int r = e >> 6, j = e & 63;
        float s = 0.f;
        for (int k = 0; k < 512; k++)
            s += (bf2f(Ah[r * 512 + k]) + bf2f(Al[r * 512 + k])) *
                 (bf2f(Bh[j * 512 + k]) + bf2f(Bl[j * 512 + k]));
        int m = blockIdx.x * 128 + r;
        long long obase = blockIdx.z * sO + (long long)m * ldo + blockIdx.y * 64 + j;
        if (Ofp) {
            Ofp[obase] = s + (bias ? bias[m] : 0.f);
        } else if (out_half) {
            Ohi[obase] = f2h(s);
        } else {
            float sc = (blockIdx.y * 64 < qcols) ? scale_q : 1.0f;
            s *= sc;
            u16 h = f2bf(s);
            Ohi[obase] = h;
            Olo[obase] = f2bf(s - bf2f(h));
        }
    }
#endif
}

// ---------------- 6) attention: overlapped, P/V fp16, occ 2 ----------------
#define SM_TMEMPTR 0
#define SM_MBAR 8
#define SM_DEN 1024
#define SM_QHI 2048
#define SM_QLO (SM_QHI + 16384)
#define SM_KHI(b) (34816 + (b) * 16384)
#define SM_KLO(b) (34816 + (b) * 16384 + 8192)
#define SM_VH(b)  (67584 + (b) * 8192)
#define ATT_SMEM 83968

#define TM_S(b) ((b) * 64)
#define TM_O 128
#define TM_PH 192
#define ATT_TMCOLS 256

__global__ void __launch_bounds__(256) k_attn(
    const u16* __restrict__ qkthi, const u16* __restrict__ qktlo,
    const u16* __restrict__ vth,
    u16* __restrict__ othi, u16* __restrict__ otlo) {
#if HAS_TC
    extern __shared__ char sm[];
    uint32_t sb = smem_u32(sm);
    int tid = threadIdx.x, wid = tid >> 5;
    int half = wid >> 2;               // 0: S cols 0-31, 1: cols 32-63
    uint32_t lofs = (uint32_t)(wid & 3) << 21;
    int n0 = blockIdx.x * 128;
    int h = blockIdx.y, b = blockIdx.z;
    const uint4* qh4 = (const uint4*)qkthi + (long long)b * NPIX * 128;
    const uint4* ql4 = (const uint4*)qktlo + (long long)b * NPIX * 128;
    const uint4* vh4 = (const uint4*)vth + ((long long)b * CDIM + h * DH) * 512;

    if (wid == 0) {
        asm volatile("tcgen05.alloc.cta_group::1.sync.aligned.shared::cta.b32 [%0], %1;"
                     :: "r"(sb + SM_TMEMPTR), "r"((uint32_t)ATT_TMCOLS) : "memory");
    }
    if (tid == 0) mbar_init1(sb + SM_MBAR);
    __syncthreads();
    uint32_t tb;
    asm volatile("ld.shared.b32 %0, [%1];" : "=r"(tb) : "r"(sb + SM_TMEMPTR));

    // ---- Q tile ----
#pragma unroll
    for (int l = 0; l < 4; l++) {
        int idx = tid + l * 256;
        int r = idx >> 3, j = idx & 7;
        uint32_t off = SWZ((uint32_t)(r * 128 + j * 16));
        *(uint4*)(sm + SM_QHI + off) = qh4[(long long)(n0 + r) * 128 + h * 8 + j];
        *(uint4*)(sm + SM_QLO + off) = ql4[(long long)(n0 + r) * 128 + h * 8 + j];
    }
    // ---- K(0), K(1), V(0) — ALL fully covered (idx 0..511) ----
#pragma unroll
    for (int l = 0; l < 2; l++) {
        int idx = tid + l * 256;
        int r = idx >> 3, j = idx & 7;
        uint32_t off = SWZ((uint32_t)(r * 128 + j * 16));
        *(uint4*)(sm + SM_KHI(0) + off) = qh4[(long long)r * 128 + 64 + h * 8 + j];
        *(uint4*)(sm + SM_KLO(0) + off) = ql4[(long long)r * 128 + 64 + h * 8 + j];
        *(uint4*)(sm + SM_KHI(1) + off) = qh4[(long long)(64 + r) * 128 + 64 + h * 8 + j];
        *(uint4*)(sm + SM_KLO(1) + off) = ql4[(long long)(64 + r) * 128 + 64 + h * 8 + j];
        *(uint4*)(sm + SM_VH(0) + off) = vh4[(long long)r * 512 + j];
    }
    FPROXY();
    __syncthreads();

    u64 aQhi = mkdesc(sb + SM_QHI);
    u64 aQlo = mkdesc(sb + SM_QLO);

    // prologue: S(0)
    if (wid == 0) {
        if (elect1()) {
            u64 bKhi = mkdesc(sb + SM_KHI(0));
            u64 bKlo = mkdesc(sb + SM_KLO(0));
#pragma unroll
            for (int ks = 0; ks < 4; ks++)
                mma_ss(tb + TM_S(0), aQhi + ks * 2, bKhi + ks * 2, IDESC64, ks > 0);
#pragma unroll
            for (int ks = 0; ks < 4; ks++)
                mma_ss(tb + TM_S(0), aQhi + ks * 2, bKlo + ks * 2, IDESC64, 1u);
#pragma unroll
            for (int ks = 0; ks < 4; ks++)
                mma_ss(tb + TM_S(0), aQlo + ks * 2, bKhi + ks * 2, IDESC64, 1u);
            tc_commit(sb + SM_MBAR);
        }
    }

    float den = 0.f;
    uint32_t ph = 0;

#pragma unroll 1
    for (int t = 0; t < 64; t++) {
        mbar_wait(sb + SM_MBAR, ph); ph ^= 1;   // S(t) + AV(t-1) done (in-order)
        TCF_AFTER();

        // issue S(t+1) NOW (overlaps softmax(t)), no commit yet
        if (t < 63 && wid == 0) {
            if (elect1()) {
                int nb = (t + 1) & 1;
                u64 bKhi = mkdesc(sb + SM_KHI(nb));
                u64 bKlo = mkdesc(sb + SM_KLO(nb));
#pragma unroll
                for (int ks = 0; ks < 4; ks++)
                    mma_ss(tb + TM_S(nb), aQhi + ks * 2, bKhi + ks * 2, IDESC64, ks > 0);
#pragma unroll
                for (int ks = 0; ks < 4; ks++)
                    mma_ss(tb + TM_S(nb), aQhi + ks * 2, bKlo + ks * 2, IDESC64, 1u);
#pragma unroll
                for (int ks = 0; ks < 4; ks++)
                    mma_ss(tb + TM_S(nb), aQlo + ks * 2, bKhi + ks * 2, IDESC64, 1u);
            }
        }

        // prefetch K(t+2) into buf t&1
        if (t <= 61) {
            int m2 = (t + 2) * 64;
#pragma unroll
            for (int l = 0; l < 2; l++) {
                int idx = tid + l * 256;
                int r = idx >> 3, j = idx & 7;
                uint32_t off = SWZ((uint32_t)(r * 128 + j * 16));
                *(uint4*)(sm + SM_KHI(t & 1) + off) = qh4[(long long)(m2 + r) * 128 + 64 + h * 8 + j];
                *(uint4*)(sm + SM_KLO(t & 1) + off) = ql4[(long long)(m2 + r) * 128 + 64 + h * 8 + j];
            }
        }
        // prefetch V(t+1) into buf (t+1)&1
        if (t <= 62) {
            int m1 = (t + 1) * 8;
#pragma unroll
            for (int l = 0; l < 2; l++) {
                int idx = tid + l * 256;
                int r = idx >> 3, j = idx & 7;
                uint32_t off = SWZ((uint32_t)(r * 128 + j * 16));
                *(uint4*)(sm + SM_VH((t + 1) & 1) + off) = vh4[(long long)r * 512 + m1 + j];
            }
        }

        // softmax(t): 8 warps; P stored fp16; den summed from quantized p
        {
            uint32_t sr[32];
            LDX32(sr, tb + TM_S(t & 1) + half * 32);
            TC_WAIT_LD();
            uint32_t w[16];
            float dsum = 0.f;
#pragma unroll
            for (int j = 0; j < 16; j++) {
                float p0 = ex2f(__uint_as_float(sr[2 * j]));
                float p1 = ex2f(__uint_as_float(sr[2 * j + 1]));
                u16 h0 = f2h(p0), h1 = f2h(p1);
                w[j] = (uint32_t)h0 | ((uint32_t)h1 << 16);
                dsum += h2f(h0) + h2f(h1);
            }
            den += dsum;
            STX16(tb + TM_PH + half * 16 + lofs, w);
            TC_WAIT_ST();
        }
        TCF_BEFORE();
        FPROXY();
        __syncthreads();

        // issue AV(t): P(fp16) x V(fp16), commit covers S(t+1)+AV(t)
        if (wid == 0) {
            if (elect1()) {
                TCF_AFTER();
                u64 dVh = mkdesc(sb + SM_VH(t & 1));
#pragma unroll
                for (int ks = 0; ks < 4; ks++)
                    mma_ts(tb + TM_O, tb + TM_PH + ks * 8, dVh + ks * 2, IDESC64H,
                           (t > 0 || ks > 0) ? 1u : 0u);
                tc_commit(sb + SM_MBAR);
            }
        }
    }
    mbar_wait(sb + SM_MBAR, ph); ph ^= 1;   // final AV done

    // combine den halves
    *(float*)(sm + SM_DEN + tid * 4) = den;
    __syncthreads();

    // epilogue
    if (tid < 128) {
        TCF_AFTER();
        uint32_t orr[64];
        LDX32(orr, tb + TM_O);
        LDX32(orr + 32, tb + TM_O + 32);
        TC_WAIT_LD();
        float dtot = *(float*)(sm + SM_DEN + tid * 4) +
                     *(float*)(sm + SM_DEN + (tid + 128) * 4);
        float inv = 1.0f / dtot;
        long long obase = ((long long)b * NPIX + n0 + tid) * CDIM + h * DH;
        uint32_t whi[32], wlo[32];
#pragma unroll
        for (int j = 0; j < 32; j++) {
            float a = __uint_as_float(orr[2 * j]) * inv;
            float c = __uint_as_float(orr[2 * j + 1]) * inv;
            u16 ah = f2bf(a), ch = f2bf(c);
            whi[j] = (uint32_t)ah | ((uint32_t)ch << 16);
            u16 al = f2bf(a - bf2f(ah)), cl = f2bf(c - bf2f(ch));
            wlo[j] = (uint32_t)al | ((uint32_t)cl << 16);
        }
#pragma unroll
        for (int j = 0; j < 8; j++) {
            *(uint4*)(othi + obase + 8 * j) = *(uint4*)&whi[4 * j];
            *(uint4*)(otlo + obase + 8 * j) = *(uint4*)&wlo[4 * j];
        }
    }
    __syncthreads();
    if (wid == 0) {
        asm volatile("tcgen05.dealloc.cta_group::1.sync.aligned.b32 %0, %1;"
                     :: "r"(tb), "r"((uint32_t)ATT_TMCOLS));
    }
#else
    // compile-only fallback
    int tid = threadIdx.x;
    if (tid >= 128) return;
    int n0 = blockIdx.x * 128;
    int h = blockIdx.y, b = blockIdx.z;
    long long qb = (long long)b * NPIX * QKD;
    int r = n0 + tid;
    float q[64], o[64], den = 0.f;
#pragma unroll
    for (int d = 0; d < 64; d++) {
        q[d] = bf2f(qkthi[qb + (long long)r * QKD + h * 64 + d]) +
               bf2f(qktlo[qb + (long long)r * QKD + h * 64 + d]);
        o[d] = 0.f;
    }
    for (int key = 0; key < NPIX; key++) {
        float s = 0.f;
        for (int d = 0; d < 64; d++)
            s += q[d] * (bf2f(qkthi[qb + (long long)key * QKD + 512 + h * 64 + d]) +
                         bf2f(qktlo[qb + (long long)key * QKD + 512 + h * 64 + d]));
        float p = h2f(f2h(ex2f(s)));
        den += p;
        for (int d = 0; d < 64; d++) {
            long long vi = ((long long)b * CDIM + h * 64 + d) * NPIX + key;
            o[d] += p * h2f(vth[vi]);
        }
    }
    long long ob = ((long long)b * NPIX + r) * CDIM + h * 64;
    for (int d = 0; d < 64; d++) {
        float v = o[d] / den;
        u16 hh = f2bf(v);
        othi[ob + d] = hh;
        otlo[ob + d] = f2bf(v - bf2f(hh));
    }
#endif
}

// ---------------------------------------------------------------------------
extern "C" void kernel_launch(void* const* d_in, const int* in_sizes, int n_in,
                              void* d_out, int out_size) {
    const float* x      = (const float*)d_in[0];
    const float* dw_w   = (const float*)d_in[1];
    const float* qkv_w  = (const float*)d_in[2];
    const float* proj_w = (const float*)d_in[3];
    const float* proj_b = (const float*)d_in[4];
    float* out = (float*)d_out;

    float* py;
    u16 *pythi, *pytlo, *pwhi, *pwlo, *ppwhi, *ppwlo;
    u16 *pqkthi, *pqktlo, *pvth, *pothi, *potlo;
    cudaGetSymbolAddress((void**)&py,     g_y);
    cudaGetSymbolAddress((void**)&pythi,  g_ythi);
    cudaGetSymbolAddress((void**)&pytlo,  g_ytlo);
    cudaGetSymbolAddress((void**)&pwhi,   g_whi);
    cudaGetSymbolAddress((void**)&pwlo,   g_wlo);
    cudaGetSymbolAddress((void**)&ppwhi,  g_pwhi);
    cudaGetSymbolAddress((void**)&ppwlo,  g_pwlo);
    cudaGetSymbolAddress((void**)&pqkthi, g_qkthi);
    cudaGetSymbolAddress((void**)&pqktlo, g_qktlo);
    cudaGetSymbolAddress((void**)&pvth,   g_vth);
    cudaGetSymbolAddress((void**)&pothi,  g_othi);
    cudaGetSymbolAddress((void**)&potlo,  g_otlo);

    cudaFuncSetAttribute(k_attn, cudaFuncAttributeMaxDynamicSharedMemorySize, ATT_SMEM);
    cudaFuncSetAttribute(k_gemm_tc, cudaFuncAttributeMaxDynamicSharedMemorySize, GM_SMEM);

    k_dwconv<<<(TOTAL + 255) / 256, 256>>>(x, dw_w, py);
    k_cvt<<<(3 * CDIM * CDIM + 255) / 256, 256>>>(qkv_w, pwhi, pwlo, 3 * CDIM * CDIM);
    k_cvt<<<(CDIM * CDIM + 255) / 256, 256>>>(proj_w, ppwhi, ppwlo, CDIM * CDIM);
    {
        dim3 grid(NPIX / 32, CDIM / 32, BATCH);
        k_t2bf<<<grid, dim3(32, 8)>>>(py, pythi, pytlo);
    }

    long long sYT = (long long)NPIX * CDIM / 8;

    // qk GEMM: qkt[n][1024] bf16 hi/lo (q cols pre-scaled)
    {
        dim3 grid(NPIX / 128, QKD / 64, BATCH);
        k_gemm_tc<<<grid, 256, GM_SMEM>>>(
            (const uint4*)pythi, (const uint4*)pytlo, sYT,
            (const uint4*)pwhi, (const uint4*)pwlo, 0,
            pqkthi, pqktlo, nullptr, nullptr,
            (long long)NPIX * QKD, QKD, ATT_SCALE_L2E, 512, 0);
    }
    // V GEMM: vt[c][n] fp16
    {
        dim3 grid(CDIM / 128, NPIX / 64, BATCH);
        k_gemm_tc<<<grid, 256, GM_SMEM>>>(
            (const uint4*)(pwhi + 1024 * CDIM), (const uint4*)(pwlo + 1024 * CDIM), 0,
            (const uint4*)pythi, (const uint4*)pytlo, sYT,
            pvth, nullptr, nullptr, nullptr,
            (long long)CDIM * NPIX, NPIX, 1.0f, 0, 1);
    }
    // attention
    {
        dim3 grid(NPIX / 128, HEADS, BATCH);
        k_attn<<<grid, 256, ATT_SMEM>>>(pqkthi, pqktlo, pvth, pothi, potlo);
    }
    // proj GEMM + bias
    {
        dim3 grid(CDIM / 128, NPIX / 64, BATCH);
        k_gemm_tc<<<grid, 256, GM_SMEM>>>(
            (const uint4*)ppwhi, (const uint4*)ppwlo, 0,
            (const uint4*)pothi, (const uint4*)potlo, sYT,
            nullptr, nullptr, out, proj_b,
            (long long)CDIM * NPIX, NPIX, 1.0f, 0, 0);
    }
}

// round 12
// speedup vs baseline: 1.6731x; 1.0350x over previous
#include <cuda_runtime.h>
#include <cuda_bf16.h>
#include <cuda_fp16.h>
#include <cstdint>

// ---------------------------------------------------------------------------
// LightweightSelfAttention  (B=2, C=512, H=W=64, heads=8, dh=64)
// All-tcgen05. GEMMs: bf16 2-way split inputs. Attention: Q fp16 hi/lo split,
// K fp16 single (R12), P/V fp16 single (R11). Overlapped S/softmax pipeline.
// ---------------------------------------------------------------------------

#if defined(__CUDA_ARCH_FEAT_SM103_ALL) || defined(__CUDA_ARCH_FEAT_SM100_ALL)
#define HAS_TC 1
#else
#define HAS_TC 0
#endif

#define BATCH 2
#define CDIM 512
#define HEADS 8
#define DH 64
#define NPIX 4096
#define TOTAL (BATCH*CDIM*NPIX)
#define QKD 1024

typedef unsigned short u16;
typedef unsigned long long u64;

__device__ float g_y[BATCH * CDIM * NPIX];
__device__ u16 g_ythi[BATCH * NPIX * CDIM];
__device__ u16 g_ytlo[BATCH * NPIX * CDIM];
__device__ u16 g_whi[3 * CDIM * CDIM];
__device__ u16 g_wlo[3 * CDIM * CDIM];
__device__ u16 g_pwhi[CDIM * CDIM];
__device__ u16 g_pwlo[CDIM * CDIM];
__device__ u16 g_qkthi[BATCH * NPIX * QKD];    // fp16: q-hi cols 0..511, k cols 512..1023
__device__ u16 g_qktlo[BATCH * NPIX * QKD];    // fp16: q-lo cols 0..511 (k part unused)
__device__ u16 g_vth[BATCH * CDIM * NPIX];     // fp16 V^T
__device__ u16 g_othi[BATCH * NPIX * CDIM];
__device__ u16 g_otlo[BATCH * NPIX * CDIM];

#define ATT_SCALE_L2E 0.18033688f   /* 0.125 * log2(e) */

// ---------------- helpers --------------------------------------------------
__device__ __forceinline__ uint32_t smem_u32(const void* p) {
    uint32_t a;
    asm("{ .reg .u64 t; cvta.to.shared.u64 t, %1; cvt.u32.u64 %0, t; }"
        : "=r"(a) : "l"(p));
    return a;
}
__device__ __forceinline__ u16 f2bf(float x) {
    return __bfloat16_as_ushort(__float2bfloat16_rn(x));
}
__device__ __forceinline__ float bf2f(u16 u) {
    return __bfloat162float(__ushort_as_bfloat16(u));
}
__device__ __forceinline__ u16 f2h(float x) {
    return __half_as_ushort(__float2half_rn(x));
}
__device__ __forceinline__ float h2f(u16 u) {
    return __half2float(__ushort_as_half(u));
}
__device__ __forceinline__ float ex2f(float x) {
    float y; asm("ex2.approx.ftz.f32 %0, %1;" : "=f"(y) : "f"(x)); return y;
}
#define SWZ(o) ((o) ^ (((o) >> 3) & 0x70))

#if HAS_TC
__device__ __forceinline__ unsigned elect1() {
    unsigned p;
    asm volatile("{\n\t.reg .pred p;\n\telect.sync _|p, 0xFFFFFFFF;\n\t"
                 "selp.b32 %0, 1, 0, p;\n\t}" : "=r"(p));
    return p;
}
__device__ __forceinline__ void mma_ss(uint32_t d, u64 a, u64 b, uint32_t id, uint32_t en) {
    asm volatile("{\n\t.reg .pred p;\n\tsetp.ne.u32 p, %5, 0;\n\t"
        "tcgen05.mma.cta_group::1.kind::f16 [%0], %1, %2, %3, {%4,%4,%4,%4}, p;\n\t}"
        :: "r"(d), "l"(a), "l"(b), "r"(id), "r"(0u), "r"(en) : "memory");
}
__device__ __forceinline__ void mma_ts(uint32_t d, uint32_t a, u64 b, uint32_t id, uint32_t en) {
    asm volatile("{\n\t.reg .pred p;\n\tsetp.ne.u32 p, %5, 0;\n\t"
        "tcgen05.mma.cta_group::1.kind::f16 [%0], [%1], %2, %3, {%4,%4,%4,%4}, p;\n\t}"
        :: "r"(d), "r"(a), "l"(b), "r"(id), "r"(0u), "r"(en) : "memory");
}
__device__ __forceinline__ void tc_commit(uint32_t mbar) {
    asm volatile("tcgen05.commit.cta_group::1.mbarrier::arrive::one.shared::cluster.b64 [%0];"
                 :: "r"(mbar) : "memory");
}
__device__ __forceinline__ void mbar_init1(uint32_t mbar) {
    asm volatile("mbarrier.init.shared.b64 [%0], %1;" :: "r"(mbar), "r"(1u) : "memory");
}
__device__ __forceinline__ void mbar_wait(uint32_t mbar, uint32_t ph) {
    asm volatile("{\n\t.reg .pred P1;\n\tLAB1_%=:\n\t"
        "mbarrier.try_wait.parity.acquire.cta.shared::cta.b64 P1, [%0], %1, 0x989680;\n\t"
        "@P1 bra.uni LAB2_%=;\n\tbra.uni LAB1_%=;\n\tLAB2_%=:\n\t}"
        :: "r"(mbar), "r"(ph) : "memory");
}
#define TCF_AFTER()  asm volatile("tcgen05.fence::after_thread_sync;" ::: "memory")
#define TCF_BEFORE() asm volatile("tcgen05.fence::before_thread_sync;" ::: "memory")
#define FPROXY()     asm volatile("fence.proxy.async.shared::cta;" ::: "memory")
#define TC_WAIT_LD() asm volatile("tcgen05.wait::ld.sync.aligned;" ::: "memory")
#define TC_WAIT_ST() asm volatile("tcgen05.wait::st.sync.aligned;" ::: "memory")

#define LDX32(r, ta) \
    asm volatile("tcgen05.ld.sync.aligned.32x32b.x32.b32 " \
        "{%0, %1, %2, %3, %4, %5, %6, %7, %8, %9, %10, %11, %12, %13, %14, %15, " \
        " %16, %17, %18, %19, %20, %21, %22, %23, %24, %25, %26, %27, %28, %29, %30, %31}, [%32];" \
        : "=r"((r)[0]),  "=r"((r)[1]),  "=r"((r)[2]),  "=r"((r)[3]), \
          "=r"((r)[4]),  "=r"((r)[5]),  "=r"((r)[6]),  "=r"((r)[7]), \
          "=r"((r)[8]),  "=r"((r)[9]),  "=r"((r)[10]), "=r"((r)[11]), \
          "=r"((r)[12]), "=r"((r)[13]), "=r"((r)[14]), "=r"((r)[15]), \
          "=r"((r)[16]), "=r"((r)[17]), "=r"((r)[18]), "=r"((r)[19]), \
          "=r"((r)[20]), "=r"((r)[21]), "=r"((r)[22]), "=r"((r)[23]), \
          "=r"((r)[24]), "=r"((r)[25]), "=r"((r)[26]), "=r"((r)[27]), \
          "=r"((r)[28]), "=r"((r)[29]), "=r"((r)[30]), "=r"((r)[31]) \
        : "r"(ta))

#define STX16(ta, r) \
    asm volatile("tcgen05.st.sync.aligned.32x32b.x16.b32 [%0], " \
        "{%1, %2, %3, %4, %5, %6, %7, %8, %9, %10, %11, %12, %13, %14, %15, %16};" \
        :: "r"(ta), \
           "r"((r)[0]),  "r"((r)[1]),  "r"((r)[2]),  "r"((r)[3]), \
           "r"((r)[4]),  "r"((r)[5]),  "r"((r)[6]),  "r"((r)[7]), \
           "r"((r)[8]),  "r"((r)[9]),  "r"((r)[10]), "r"((r)[11]), \
           "r"((r)[12]), "r"((r)[13]), "r"((r)[14]), "r"((r)[15]) \
        : "memory")

#define DESC_K  ((2ull<<61)|(1ull<<46)|(64ull<<32)|(1ull<<16))
__device__ __forceinline__ u64 mkdesc(uint32_t addr) {
    return DESC_K | ((u64)(addr >> 4) & 0x3FFF);
}
#define IDESC64   ((1u<<4)|(1u<<7)|(1u<<10)|(8u<<17)|(8u<<24))  /* bf16 x bf16 */
#define IDESC64H  ((1u<<4)|(8u<<17)|(8u<<24))                   /* fp16 x fp16 */
#endif  // HAS_TC

// ---------------- 1) depthwise 3x3 ----------------------------------------
__global__ void k_dwconv(const float* __restrict__ x,
                         const float* __restrict__ w,
                         float* __restrict__ y) {
    int idx = blockIdx.x * blockDim.x + threadIdx.x;
    if (idx >= TOTAL) return;
    int n = idx & (NPIX - 1);
    int c = (idx >> 12) & (CDIM - 1);
    int hh = n >> 6, ww = n & 63;
    const float* xb = x + (long long)(idx >> 12) * NPIX;
    const float* wc = w + c * 9;
    float s = 0.f;
#pragma unroll
    for (int i = 0; i < 3; i++) {
        int h2 = hh + i - 1;
        if ((unsigned)h2 < 64u) {
#pragma unroll
            for (int j = 0; j < 3; j++) {
                int w2 = ww + j - 1;
                if ((unsigned)w2 < 64u) s += xb[h2 * 64 + w2] * wc[i * 3 + j];
            }
        }
    }
    y[idx] = s;
}

// ---------------- 2) fp32 -> bf16 hi/lo ------------------------------------
__global__ void k_cvt(const float* __restrict__ src, u16* __restrict__ hi,
                      u16* __restrict__ lo, int n) {
    int i = blockIdx.x * blockDim.x + threadIdx.x;
    if (i >= n) return;
    float v = src[i];
    u16 h = f2bf(v);
    hi[i] = h;
    lo[i] = f2bf(v - bf2f(h));
}

// ---------------- 3) transpose+split ---------------------------------------
__global__ void k_t2bf(const float* __restrict__ y, u16* __restrict__ thi,
                       u16* __restrict__ tlo) {
    __shared__ float t[32][33];
    long long zo = (long long)blockIdx.z * CDIM * NPIX;
    long long zt = (long long)blockIdx.z * NPIX * CDIM;
    int c0 = blockIdx.y * 32, n0 = blockIdx.x * 32;
#pragma unroll
    for (int j = 0; j < 4; j++) {
        int c = c0 + threadIdx.y + j * 8;
        t[threadIdx.y + j * 8][threadIdx.x] = y[zo + (long long)c * NPIX + n0 + threadIdx.x];
    }
    __syncthreads();
#pragma unroll
    for (int j = 0; j < 4; j++) {
        int n = n0 + threadIdx.y + j * 8;
        float v = t[threadIdx.x][threadIdx.y + j * 8];
        u16 h = f2bf(v);
        thi[zt + (long long)n * CDIM + c0 + threadIdx.x] = h;
        tlo[zt + (long long)n * CDIM + c0 + threadIdx.x] = f2bf(v - bf2f(h));
    }
}

// ---------------- 4/5/7) tcgen05 GEMM (128x64, serial commits) -------------
// out_mode: 0 = bf16 hi/lo;  1 = fp16 single;  2 = qk (q: fp16 hi/lo scaled,
// k: fp16 single);  Ofp != 0 overrides -> fp32 + bias.
#define GM_TMEMPTR 0
#define GM_MBAR 8
#define GM_AHI 1024
#define GM_ALO (GM_AHI + 16384)
#define GM_BHI (GM_ALO + 16384)
#define GM_BLO (GM_BHI + 8192)
#define GM_SMEM (GM_BLO + 8192)

__global__ void __launch_bounds__(256) k_gemm_tc(
    const uint4* __restrict__ Ahi, const uint4* __restrict__ Alo, long long sA,
    const uint4* __restrict__ Bhi, const uint4* __restrict__ Blo, long long sB,
    u16* __restrict__ Ohi, u16* __restrict__ Olo,
    float* __restrict__ Ofp, const float* __restrict__ bias,
    long long sO, int ldo, float scale_q, int qcols, int out_mode) {
#if HAS_TC
    extern __shared__ char sm[];
    uint32_t sb = smem_u32(sm);
    int tid = threadIdx.x, wid = tid >> 5;
    int mrow0 = blockIdx.x * 128;
    int brow0 = blockIdx.y * 64;
    const uint4* Ah = Ahi + blockIdx.z * sA + (long long)mrow0 * 64;
    const uint4* Al = Alo + blockIdx.z * sA + (long long)mrow0 * 64;
    const uint4* Bh = Bhi + blockIdx.z * sB + (long long)brow0 * 64;
    const uint4* Bl = Blo + blockIdx.z * sB + (long long)brow0 * 64;

    if (wid == 0) {
        asm volatile("tcgen05.alloc.cta_group::1.sync.aligned.shared::cta.b32 [%0], %1;"
                     :: "r"(sb + GM_TMEMPTR), "r"(128u) : "memory");
    }
    if (tid == 0) mbar_init1(sb + GM_MBAR);
    __syncthreads();
    uint32_t tb;
    asm volatile("ld.shared.b32 %0, [%1];" : "=r"(tb) : "r"(sb + GM_TMEMPTR));

    u64 dAhi = mkdesc(sb + GM_AHI);
    u64 dAlo = mkdesc(sb + GM_ALO);
    u64 dBhi = mkdesc(sb + GM_BHI);
    u64 dBlo = mkdesc(sb + GM_BLO);

    uint32_t ph = 0;
#pragma unroll 1
    for (int kc = 0; kc < 8; kc++) {
        if (kc) { mbar_wait(sb + GM_MBAR, ph); ph ^= 1; }
        int k8 = kc * 8;
#pragma unroll
        for (int l = 0; l < 4; l++) {
            int idx = tid + l * 256;
            int r = idx >> 3, j = idx & 7;
            uint32_t off = SWZ((uint32_t)(r * 128 + j * 16));
            *(uint4*)(sm + GM_AHI + off) = Ah[r * 64 + k8 + j];
            *(uint4*)(sm + GM_ALO + off) = Al[r * 64 + k8 + j];
        }
#pragma unroll
        for (int l = 0; l < 2; l++) {
            int idx = tid + l * 256;
            int r = idx >> 3, j = idx & 7;
            uint32_t off = SWZ((uint32_t)(r * 128 + j * 16));
            *(uint4*)(sm + GM_BHI + off) = Bh[r * 64 + k8 + j];
            *(uint4*)(sm + GM_BLO + off) = Bl[r * 64 + k8 + j];
        }
        FPROXY();
        __syncthreads();
        if (wid == 0) {
            if (elect1()) {
#pragma unroll
                for (int ks = 0; ks < 4; ks++)
                    mma_ss(tb, dAhi + ks * 2, dBhi + ks * 2, IDESC64, !(kc == 0 && ks == 0));
#pragma unroll
                for (int ks = 0; ks < 4; ks++)
                    mma_ss(tb, dAhi + ks * 2, dBlo + ks * 2, IDESC64, 1u);
#pragma unroll
                for (int ks = 0; ks < 4; ks++)
                    mma_ss(tb, dAlo + ks * 2, dBhi + ks * 2, IDESC64, 1u);
                tc_commit(sb + GM_MBAR);
            }
        }
    }
    mbar_wait(sb + GM_MBAR, ph); ph ^= 1;

    if (tid < 128) {
        TCF_AFTER();
        uint32_t d[64];
        LDX32(d, tb);
        LDX32(d + 32, tb + 32);
        TC_WAIT_LD();
        int m = mrow0 + tid;
        long long obase = blockIdx.z * sO + (long long)m * ldo + brow0;
        if (Ofp) {
            float bv = bias ? bias[m] : 0.f;
#pragma unroll
            for (int j = 0; j < 16; j++) {
                float4 v = make_float4(__uint_as_float(d[4 * j]) + bv,
                                       __uint_as_float(d[4 * j + 1]) + bv,
                                       __uint_as_float(d[4 * j + 2]) + bv,
                                       __uint_as_float(d[4 * j + 3]) + bv);
                *(float4*)(Ofp + obase + 4 * j) = v;
            }
        } else if (out_mode == 1) {
            uint32_t w[32];
#pragma unroll
            for (int j = 0; j < 32; j++) {
                u16 a = f2h(__uint_as_float(d[2 * j]));
                u16 c = f2h(__uint_as_float(d[2 * j + 1]));
                w[j] = (uint32_t)a | ((uint32_t)c << 16);
            }
#pragma unroll
            for (int j = 0; j < 8; j++)
                *(uint4*)(Ohi + obase + 8 * j) = *(uint4*)&w[4 * j];
        } else if (out_mode == 2) {
            if (brow0 < qcols) {
                // q columns: scaled fp16 hi + residual lo
                uint32_t whi[32], wlo[32];
#pragma unroll
                for (int j = 0; j < 32; j++) {
                    float a = __uint_as_float(d[2 * j]) * scale_q;
                    float c = __uint_as_float(d[2 * j + 1]) * scale_q;
                    u16 ah = f2h(a), ch = f2h(c);
                    whi[j] = (uint32_t)ah | ((uint32_t)ch << 16);
                    u16 al = f2h(a - h2f(ah)), cl = f2h(c - h2f(ch));
                    wlo[j] = (uint32_t)al | ((uint32_t)cl << 16);
                }
#pragma unroll
                for (int j = 0; j < 8; j++) {
                    *(uint4*)(Ohi + obase + 8 * j) = *(uint4*)&whi[4 * j];
                    *(uint4*)(Olo + obase + 8 * j) = *(uint4*)&wlo[4 * j];
                }
            } else {
                // k columns: fp16 single
                uint32_t w[32];
#pragma unroll
                for (int j = 0; j < 32; j++) {
                    u16 a = f2h(__uint_as_float(d[2 * j]));
                    u16 c = f2h(__uint_as_float(d[2 * j + 1]));
                    w[j] = (uint32_t)a | ((uint32_t)c << 16);
                }
#pragma unroll
                for (int j = 0; j < 8; j++)
                    *(uint4*)(Ohi + obase + 8 * j) = *(uint4*)&w[4 * j];
            }
        } else {
            uint32_t whi[32], wlo[32];
#pragma unroll
            for (int j = 0; j < 32; j++) {
                float a = __uint_as_float(d[2 * j]);
                float b = __uint_as_float(d[2 * j + 1]);
                u16 ah = f2bf(a), bh = f2bf(b);
                whi[j] = (uint32_t)ah | ((uint32_t)bh << 16);
                u16 al = f2bf(a - bf2f(ah)), bl = f2bf(b - bf2f(bh));
                wlo[j] = (uint32_t)al | ((uint32_t)bl << 16);
            }
#pragma unroll
            for (int j = 0; j < 8; j++) {
                *(uint4*)(Ohi + obase + 8 * j) = *(uint4*)&whi[4 * j];
                *(uint4*)(Olo + obase + 8 * j) = *(uint4*)&wlo[4 * j];
            }
        }
    }
    __syncthreads();
    if (wid == 0) {
        asm volatile("tcgen05.dealloc.cta_group::1.sync.aligned.b32 %0, %1;"
                     :: "r"(tb), "r"(128u));
    }
#else
    // compile-only fallback
    int tid = threadIdx.x;
    const u16* Ah = (const u16*)(Ahi + blockIdx.z * sA) + (long long)blockIdx.x * 128 * 512;
    const u16* Al = (const u16*)(Alo + blockIdx.z * sA) + (long long)blockIdx.x * 128 * 512;
    const u16* Bh = (const u16*)(Bhi + blockIdx.z * sB) + (long long)blockIdx.y * 64 * 512;
    const u16* Bl = (const u16*)(Blo + blockIdx.z * sB) + (long long)blockIdx.y * 64 * 512;
    for (int e = tid; e < 128 * 64; e += 256) {
        int r = e >> 6, j = e & 63;
        float s = 0.f;
        for (int k = 0; k < 512; k++)
            s += (bf2f(Ah[r * 512 + k]) + bf2f(Al[r * 512 + k])) *
                 (bf2f(Bh[j * 512 + k]) + bf2f(Bl[j * 512 + k]));
        int m = blockIdx.x * 128 + r;
        long long obase = blockIdx.z * sO + (long long)m * ldo + blockIdx.y * 64 + j;
        if (Ofp) {
            Ofp[obase] = s + (bias ? bias[m] : 0.f);
        } else if (out_mode == 1) {
            Ohi[obase] = f2h(s);
        } else if (out_mode == 2) {
            if (blockIdx.y * 64 < qcols) {
                s *= scale_q;
                u16 hh = f2h(s);
                Ohi[obase] = hh;
                Olo[obase] = f2h(s - h2f(hh));
            } else {
                Ohi[obase] = f2h(s);
            }
        } else {
            u16 h = f2bf(s);
            Ohi[obase] = h;
            Olo[obase] = f2bf(s - bf2f(h));
        }
    }
#endif
}

// ---------------- 6) attention: Q fp16 split, K/V/P fp16, occ 2 ------------
#define SM_TMEMPTR 0
#define SM_MBAR 8
#define SM_DEN 1024
#define SM_QHI 2048
#define SM_QLO (SM_QHI + 16384)
#define SM_KH(b) (34816 + (b) * 8192)
#define SM_VH(b) (51200 + (b) * 8192)
#define ATT_SMEM 67584

#define TM_S(b) ((b) * 64)
#define TM_O 128
#define TM_PH 192
#define ATT_TMCOLS 256

__global__ void __launch_bounds__(256) k_attn(
    const u16* __restrict__ qkthi, const u16* __restrict__ qktlo,
    const u16* __restrict__ vth,
    u16* __restrict__ othi, u16* __restrict__ otlo) {
#if HAS_TC
    extern __shared__ char sm[];
    uint32_t sb = smem_u32(sm);
    int tid = threadIdx.x, wid = tid >> 5;
    int half = wid >> 2;               // 0: S cols 0-31, 1: cols 32-63
    uint32_t lofs = (uint32_t)(wid & 3) << 21;
    int n0 = blockIdx.x * 128;
    int h = blockIdx.y, b = blockIdx.z;
    const uint4* qh4 = (const uint4*)qkthi + (long long)b * NPIX * 128;
    const uint4* ql4 = (const uint4*)qktlo + (long long)b * NPIX * 128;
    const uint4* vh4 = (const uint4*)vth + ((long long)b * CDIM + h * DH) * 512;

    if (wid == 0) {
        asm volatile("tcgen05.alloc.cta_group::1.sync.aligned.shared::cta.b32 [%0], %1;"
                     :: "r"(sb + SM_TMEMPTR), "r"((uint32_t)ATT_TMCOLS) : "memory");
    }
    if (tid == 0) mbar_init1(sb + SM_MBAR);
    __syncthreads();
    uint32_t tb;
    asm volatile("ld.shared.b32 %0, [%1];" : "=r"(tb) : "r"(sb + SM_TMEMPTR));

    // ---- Q tile (fp16 hi/lo) ----
#pragma unroll
    for (int l = 0; l < 4; l++) {
        int idx = tid + l * 256;
        int r = idx >> 3, j = idx & 7;
        uint32_t off = SWZ((uint32_t)(r * 128 + j * 16));
        *(uint4*)(sm + SM_QHI + off) = qh4[(long long)(n0 + r) * 128 + h * 8 + j];
        *(uint4*)(sm + SM_QLO + off) = ql4[(long long)(n0 + r) * 128 + h * 8 + j];
    }
    // ---- K(0), K(1), V(0) — fp16 single, full coverage (idx 0..511) ----
#pragma unroll
    for (int l = 0; l < 2; l++) {
        int idx = tid + l * 256;
        int r = idx >> 3, j = idx & 7;
        uint32_t off = SWZ((uint32_t)(r * 128 + j * 16));
        *(uint4*)(sm + SM_KH(0) + off) = qh4[(long long)r * 128 + 64 + h * 8 + j];
        *(uint4*)(sm + SM_KH(1) + off) = qh4[(long long)(64 + r) * 128 + 64 + h * 8 + j];
        *(uint4*)(sm + SM_VH(0) + off) = vh4[(long long)r * 512 + j];
    }
    FPROXY();
    __syncthreads();

    u64 aQhi = mkdesc(sb + SM_QHI);
    u64 aQlo = mkdesc(sb + SM_QLO);

    // prologue: S(0) = (Qhi + Qlo) x K(0)
    if (wid == 0) {
        if (elect1()) {
            u64 dK = mkdesc(sb + SM_KH(0));
#pragma unroll
            for (int ks = 0; ks < 4; ks++)
                mma_ss(tb + TM_S(0), aQhi + ks * 2, dK + ks * 2, IDESC64H, ks > 0);
#pragma unroll
            for (int ks = 0; ks < 4; ks++)
                mma_ss(tb + TM_S(0), aQlo + ks * 2, dK + ks * 2, IDESC64H, 1u);
            tc_commit(sb + SM_MBAR);
        }
    }

    float den = 0.f;
    uint32_t ph = 0;

#pragma unroll 1
    for (int t = 0; t < 64; t++) {
        mbar_wait(sb + SM_MBAR, ph); ph ^= 1;   // S(t) + AV(t-1) done (in-order)
        TCF_AFTER();

        // issue S(t+1) NOW (overlaps softmax(t)), no commit yet
        if (t < 63 && wid == 0) {
            if (elect1()) {
                int nb = (t + 1) & 1;
                u64 dK = mkdesc(sb + SM_KH(nb));
#pragma unroll
                for (int ks = 0; ks < 4; ks++)
                    mma_ss(tb + TM_S(nb), aQhi + ks * 2, dK + ks * 2, IDESC64H, ks > 0);
#pragma unroll
                for (int ks = 0; ks < 4; ks++)
                    mma_ss(tb + TM_S(nb), aQlo + ks * 2, dK + ks * 2, IDESC64H, 1u);
            }
        }

        // prefetch K(t+2) into buf t&1
        if (t <= 61) {
            int m2 = (t + 2) * 64;
#pragma unroll
            for (int l = 0; l < 2; l++) {
                int idx = tid + l * 256;
                int r = idx >> 3, j = idx & 7;
                uint32_t off = SWZ((uint32_t)(r * 128 + j * 16));
                *(uint4*)(sm + SM_KH(t & 1) + off) = qh4[(long long)(m2 + r) * 128 + 64 + h * 8 + j];
            }
        }
        // prefetch V(t+1) into buf (t+1)&1
        if (t <= 62) {
            int m1 = (t + 1) * 8;
#pragma unroll
            for (int l = 0; l < 2; l++) {
                int idx = tid + l * 256;
                int r = idx >> 3, j = idx & 7;
                uint32_t off = SWZ((uint32_t)(r * 128 + j * 16));
                *(uint4*)(sm + SM_VH((t + 1) & 1) + off) = vh4[(long long)r * 512 + m1 + j];
            }
        }

        // softmax(t): 8 warps; P stored fp16; den summed from quantized p
        {
            uint32_t sr[32];
            LDX32(sr, tb + TM_S(t & 1) + half * 32);
            TC_WAIT_LD();
            uint32_t w[16];
            float dsum = 0.f;
#pragma unroll
            for (int j = 0; j < 16; j++) {
                float p0 = ex2f(__uint_as_float(sr[2 * j]));
                float p1 = ex2f(__uint_as_float(sr[2 * j + 1]));
                u16 h0 = f2h(p0), h1 = f2h(p1);
                w[j] = (uint32_t)h0 | ((uint32_t)h1 << 16);
                dsum += h2f(h0) + h2f(h1);
            }
            den += dsum;
            STX16(tb + TM_PH + half * 16 + lofs, w);
            TC_WAIT_ST();
        }
        TCF_BEFORE();
        FPROXY();
        __syncthreads();

        // issue AV(t): P(fp16) x V(fp16), commit covers S(t+1)+AV(t)
        if (wid == 0) {
            if (elect1()) {
                TCF_AFTER();
                u64 dVh = mkdesc(sb + SM_VH(t & 1));
#pragma unroll
                for (int ks = 0; ks < 4; ks++)
                    mma_ts(tb + TM_O, tb + TM_PH + ks * 8, dVh + ks * 2, IDESC64H,
                           (t > 0 || ks > 0) ? 1u : 0u);
                tc_commit(sb + SM_MBAR);
            }
        }
    }
    mbar_wait(sb + SM_MBAR, ph); ph ^= 1;   // final AV done

    // combine den halves
    *(float*)(sm + SM_DEN + tid * 4) = den;
    __syncthreads();

    // epilogue
    if (tid < 128) {
        TCF_AFTER();
        uint32_t orr[64];
        LDX32(orr, tb + TM_O);
        LDX32(orr + 32, tb + TM_O + 32);
        TC_WAIT_LD();
        float dtot = *(float*)(sm + SM_DEN + tid * 4) +
                     *(float*)(sm + SM_DEN + (tid + 128) * 4);
        float inv = 1.0f / dtot;
        long long obase = ((long long)b * NPIX + n0 + tid) * CDIM + h * DH;
        uint32_t whi[32], wlo[32];
#pragma unroll
        for (int j = 0; j < 32; j++) {
            float a = __uint_as_float(orr[2 * j]) * inv;
            float c = __uint_as_float(orr[2 * j + 1]) * inv;
            u16 ah = f2bf(a), ch = f2bf(c);
            whi[j] = (uint32_t)ah | ((uint32_t)ch << 16);
            u16 al = f2bf(a - bf2f(ah)), cl = f2bf(c - bf2f(ch));
            wlo[j] = (uint32_t)al | ((uint32_t)cl << 16);
        }
#pragma unroll
        for (int j = 0; j < 8; j++) {
            *(uint4*)(othi + obase + 8 * j) = *(uint4*)&whi[4 * j];
            *(uint4*)(otlo + obase + 8 * j) = *(uint4*)&wlo[4 * j];
        }
    }
    __syncthreads();
    if (wid == 0) {
        asm volatile("tcgen05.dealloc.cta_group::1.sync.aligned.b32 %0, %1;"
                     :: "r"(tb), "r"((uint32_t)ATT_TMCOLS));
    }
#else
    // compile-only fallback
    int tid = threadIdx.x;
    if (tid >= 128) return;
    int n0 = blockIdx.x * 128;
    int h = blockIdx.y, b = blockIdx.z;
    long long qb = (long long)b * NPIX * QKD;
    int r = n0 + tid;
    float q[64], o[64], den = 0.f;
#pragma unroll
    for (int d = 0; d < 64; d++) {
        q[d] = h2f(qkthi[qb + (long long)r * QKD + h * 64 + d]) +
               h2f(qktlo[qb + (long long)r * QKD + h * 64 + d]);
        o[d] = 0.f;
    }
    for (int key = 0; key < NPIX; key++) {
        float s = 0.f;
        for (int d = 0; d < 64; d++)
            s += q[d] * h2f(qkthi[qb + (long long)key * QKD + 512 + h * 64 + d]);
        float p = h2f(f2h(ex2f(s)));
        den += p;
        for (int d = 0; d < 64; d++) {
            long long vi = ((long long)b * CDIM + h * 64 + d) * NPIX + key;
            o[d] += p * h2f(vth[vi]);
        }
    }
    long long ob = ((long long)b * NPIX + r) * CDIM + h * 64;
    for (int d = 0; d < 64; d++) {
        float v = o[d] / den;
        u16 hh = f2bf(v);
        othi[ob + d] = hh;
        otlo[ob + d] = f2bf(v - bf2f(hh));
    }
#endif
}

// ---------------------------------------------------------------------------
extern "C" void kernel_launch(void* const* d_in, const int* in_sizes, int n_in,
                              void* d_out, int out_size) {
    const float* x      = (const float*)d_in[0];
    const float* dw_w   = (const float*)d_in[1];
    const float* qkv_w  = (const float*)d_in[2];
    const float* proj_w = (const float*)d_in[3];
    const float* proj_b = (const float*)d_in[4];
    float* out = (float*)d_out;

    float* py;
    u16 *pythi, *pytlo, *pwhi, *pwlo, *ppwhi, *ppwlo;
    u16 *pqkthi, *pqktlo, *pvth, *pothi, *potlo;
    cudaGetSymbolAddress((void**)&py,     g_y);
    cudaGetSymbolAddress((void**)&pythi,  g_ythi);
    cudaGetSymbolAddress((void**)&pytlo,  g_ytlo);
    cudaGetSymbolAddress((void**)&pwhi,   g_whi);
    cudaGetSymbolAddress((void**)&pwlo,   g_wlo);
    cudaGetSymbolAddress((void**)&ppwhi,  g_pwhi);
    cudaGetSymbolAddress((void**)&ppwlo,  g_pwlo);
    cudaGetSymbolAddress((void**)&pqkthi, g_qkthi);
    cudaGetSymbolAddress((void**)&pqktlo, g_qktlo);
    cudaGetSymbolAddress((void**)&pvth,   g_vth);
    cudaGetSymbolAddress((void**)&pothi,  g_othi);
    cudaGetSymbolAddress((void**)&potlo,  g_otlo);

    cudaFuncSetAttribute(k_attn, cudaFuncAttributeMaxDynamicSharedMemorySize, ATT_SMEM);
    cudaFuncSetAttribute(k_gemm_tc, cudaFuncAttributeMaxDynamicSharedMemorySize, GM_SMEM);

    k_dwconv<<<(TOTAL + 255) / 256, 256>>>(x, dw_w, py);
    k_cvt<<<(3 * CDIM * CDIM + 255) / 256, 256>>>(qkv_w, pwhi, pwlo, 3 * CDIM * CDIM);
    k_cvt<<<(CDIM * CDIM + 255) / 256, 256>>>(proj_w, ppwhi, ppwlo, CDIM * CDIM);
    {
        dim3 grid(NPIX / 32, CDIM / 32, BATCH);
        k_t2bf<<<grid, dim3(32, 8)>>>(py, pythi, pytlo);
    }

    long long sYT = (long long)NPIX * CDIM / 8;

    // qk GEMM: qkt[n][1024] — q: fp16 hi/lo scaled; k: fp16 single
    {
        dim3 grid(NPIX / 128, QKD / 64, BATCH);
        k_gemm_tc<<<grid, 256, GM_SMEM>>>(
            (const uint4*)pythi, (const uint4*)pytlo, sYT,
            (const uint4*)pwhi, (const uint4*)pwlo, 0,
            pqkthi, pqktlo, nullptr, nullptr,
            (long long)NPIX * QKD, QKD, ATT_SCALE_L2E, 512, 2);
    }
    // V GEMM: vt[c][n] fp16
    {
        dim3 grid(CDIM / 128, NPIX / 64, BATCH);
        k_gemm_tc<<<grid, 256, GM_SMEM>>>(
            (const uint4*)(pwhi + 1024 * CDIM), (const uint4*)(pwlo + 1024 * CDIM), 0,
            (const uint4*)pythi, (const uint4*)pytlo, sYT,
            pvth, nullptr, nullptr, nullptr,
            (long long)CDIM * NPIX, NPIX, 1.0f, 0, 1);
    }
    // attention
    {
        dim3 grid(NPIX / 128, HEADS, BATCH);
        k_attn<<<grid, 256, ATT_SMEM>>>(pqkthi, pqktlo, pvth, pothi, potlo);
    }
    // proj GEMM + bias
    {
        dim3 grid(CDIM / 128, NPIX / 64, BATCH);
        k_gemm_tc<<<grid, 256, GM_SMEM>>>(
            (const uint4*)ppwhi, (const uint4*)ppwlo, 0,
            (const uint4*)pothi, (const uint4*)potlo, sYT,
            nullptr, nullptr, out, proj_b,
            (long long)CDIM * NPIX, NPIX, 1.0f, 0, 0);
    }
}

// round 13
// speedup vs baseline: 2.0562x; 1.2290x over previous
#include <cuda_runtime.h>
#include <cuda_bf16.h>
#include <cuda_fp16.h>
#include <cstdint>

// ---------------------------------------------------------------------------
// LightweightSelfAttention  (B=2, C=512, H=W=64, heads=8, dh=64)
// All-tcgen05, all-fp16 data plane (R13):
//   GEMMs: A = fp16 hi/lo split, B = fp16 single, 128x128 tiles, 2 products.
//   Attention: Q fp16 hi/lo, K/V/P fp16 single, overlapped S/softmax pipeline.
//   ot = fp16 single.
// ---------------------------------------------------------------------------

#if defined(__CUDA_ARCH_FEAT_SM103_ALL) || defined(__CUDA_ARCH_FEAT_SM100_ALL)
#define HAS_TC 1
#else
#define HAS_TC 0
#endif

#define BATCH 2
#define CDIM 512
#define HEADS 8
#define DH 64
#define NPIX 4096
#define TOTAL (BATCH*CDIM*NPIX)
#define QKD 1024

typedef unsigned short u16;
typedef unsigned long long u64;

__device__ float g_y[BATCH * CDIM * NPIX];
__device__ u16 g_ythi[BATCH * NPIX * CDIM];    // fp16 hi
__device__ u16 g_ytlo[BATCH * NPIX * CDIM];    // fp16 lo
__device__ u16 g_whi[3 * CDIM * CDIM];         // fp16 hi (also used as B single)
__device__ u16 g_wlo[3 * CDIM * CDIM];         // fp16 lo
__device__ u16 g_pwhi[CDIM * CDIM];
__device__ u16 g_pwlo[CDIM * CDIM];
__device__ u16 g_qkthi[BATCH * NPIX * QKD];    // fp16: q-hi cols 0..511, k cols 512..1023
__device__ u16 g_qktlo[BATCH * NPIX * QKD];    // fp16: q-lo cols 0..511
__device__ u16 g_vth[BATCH * CDIM * NPIX];     // fp16 V^T
__device__ u16 g_oth[BATCH * NPIX * CDIM];     // fp16 attention out

#define ATT_SCALE_L2E 0.18033688f   /* 0.125 * log2(e) */

// ---------------- helpers --------------------------------------------------
__device__ __forceinline__ uint32_t smem_u32(const void* p) {
    uint32_t a;
    asm("{ .reg .u64 t; cvta.to.shared.u64 t, %1; cvt.u32.u64 %0, t; }"
        : "=r"(a) : "l"(p));
    return a;
}
__device__ __forceinline__ u16 f2h(float x) {
    return __half_as_ushort(__float2half_rn(x));
}
__device__ __forceinline__ float h2f(u16 u) {
    return __half2float(__ushort_as_half(u));
}
__device__ __forceinline__ float ex2f(float x) {
    float y; asm("ex2.approx.ftz.f32 %0, %1;" : "=f"(y) : "f"(x)); return y;
}
#define SWZ(o) ((o) ^ (((o) >> 3) & 0x70))

#if HAS_TC
__device__ __forceinline__ unsigned elect1() {
    unsigned p;
    asm volatile("{\n\t.reg .pred p;\n\telect.sync _|p, 0xFFFFFFFF;\n\t"
                 "selp.b32 %0, 1, 0, p;\n\t}" : "=r"(p));
    return p;
}
__device__ __forceinline__ void mma_ss(uint32_t d, u64 a, u64 b, uint32_t id, uint32_t en) {
    asm volatile("{\n\t.reg .pred p;\n\tsetp.ne.u32 p, %5, 0;\n\t"
        "tcgen05.mma.cta_group::1.kind::f16 [%0], %1, %2, %3, {%4,%4,%4,%4}, p;\n\t}"
        :: "r"(d), "l"(a), "l"(b), "r"(id), "r"(0u), "r"(en) : "memory");
}
__device__ __forceinline__ void mma_ts(uint32_t d, uint32_t a, u64 b, uint32_t id, uint32_t en) {
    asm volatile("{\n\t.reg .pred p;\n\tsetp.ne.u32 p, %5, 0;\n\t"
        "tcgen05.mma.cta_group::1.kind::f16 [%0], [%1], %2, %3, {%4,%4,%4,%4}, p;\n\t}"
        :: "r"(d), "r"(a), "l"(b), "r"(id), "r"(0u), "r"(en) : "memory");
}
__device__ __forceinline__ void tc_commit(uint32_t mbar) {
    asm volatile("tcgen05.commit.cta_group::1.mbarrier::arrive::one.shared::cluster.b64 [%0];"
                 :: "r"(mbar) : "memory");
}
__device__ __forceinline__ void mbar_init1(uint32_t mbar) {
    asm volatile("mbarrier.init.shared.b64 [%0], %1;" :: "r"(mbar), "r"(1u) : "memory");
}
__device__ __forceinline__ void mbar_wait(uint32_t mbar, uint32_t ph) {
    asm volatile("{\n\t.reg .pred P1;\n\tLAB1_%=:\n\t"
        "mbarrier.try_wait.parity.acquire.cta.shared::cta.b64 P1, [%0], %1, 0x989680;\n\t"
        "@P1 bra.uni LAB2_%=;\n\tbra.uni LAB1_%=;\n\tLAB2_%=:\n\t}"
        :: "r"(mbar), "r"(ph) : "memory");
}
#define TCF_AFTER()  asm volatile("tcgen05.fence::after_thread_sync;" ::: "memory")
#define TCF_BEFORE() asm volatile("tcgen05.fence::before_thread_sync;" ::: "memory")
#define FPROXY()     asm volatile("fence.proxy.async.shared::cta;" ::: "memory")
#define TC_WAIT_LD() asm volatile("tcgen05.wait::ld.sync.aligned;" ::: "memory")
#define TC_WAIT_ST() asm volatile("tcgen05.wait::st.sync.aligned;" ::: "memory")

#define LDX32(r, ta) \
    asm volatile("tcgen05.ld.sync.aligned.32x32b.x32.b32 " \
        "{%0, %1, %2, %3, %4, %5, %6, %7, %8, %9, %10, %11, %12, %13, %14, %15, " \
        " %16, %17, %18, %19, %20, %21, %22, %23, %24, %25, %26, %27, %28, %29, %30, %31}, [%32];" \
        : "=r"((r)[0]),  "=r"((r)[1]),  "=r"((r)[2]),  "=r"((r)[3]), \
          "=r"((r)[4]),  "=r"((r)[5]),  "=r"((r)[6]),  "=r"((r)[7]), \
          "=r"((r)[8]),  "=r"((r)[9]),  "=r"((r)[10]), "=r"((r)[11]), \
          "=r"((r)[12]), "=r"((r)[13]), "=r"((r)[14]), "=r"((r)[15]), \
          "=r"((r)[16]), "=r"((r)[17]), "=r"((r)[18]), "=r"((r)[19]), \
          "=r"((r)[20]), "=r"((r)[21]), "=r"((r)[22]), "=r"((r)[23]), \
          "=r"((r)[24]), "=r"((r)[25]), "=r"((r)[26]), "=r"((r)[27]), \
          "=r"((r)[28]), "=r"((r)[29]), "=r"((r)[30]), "=r"((r)[31]) \
        : "r"(ta))

#define STX16(ta, r) \
    asm volatile("tcgen05.st.sync.aligned.32x32b.x16.b32 [%0], " \
        "{%1, %2, %3, %4, %5, %6, %7, %8, %9, %10, %11, %12, %13, %14, %15, %16};" \
        :: "r"(ta), \
           "r"((r)[0]),  "r"((r)[1]),  "r"((r)[2]),  "r"((r)[3]), \
           "r"((r)[4]),  "r"((r)[5]),  "r"((r)[6]),  "r"((r)[7]), \
           "r"((r)[8]),  "r"((r)[9]),  "r"((r)[10]), "r"((r)[11]), \
           "r"((r)[12]), "r"((r)[13]), "r"((r)[14]), "r"((r)[15]) \
        : "memory")

#define DESC_K  ((2ull<<61)|(1ull<<46)|(64ull<<32)|(1ull<<16))
__device__ __forceinline__ u64 mkdesc(uint32_t addr) {
    return DESC_K | ((u64)(addr >> 4) & 0x3FFF);
}
#define IDESC64H   ((1u<<4)|(8u<<17)|(8u<<24))    /* fp16, M=128 N=64 */
#define IDESC128H  ((1u<<4)|(16u<<17)|(8u<<24))   /* fp16, M=128 N=128 */
#endif  // HAS_TC

// ---------------- 1) depthwise 3x3 ----------------------------------------
__global__ void k_dwconv(const float* __restrict__ x,
                         const float* __restrict__ w,
                         float* __restrict__ y) {
    int idx = blockIdx.x * blockDim.x + threadIdx.x;
    if (idx >= TOTAL) return;
    int n = idx & (NPIX - 1);
    int c = (idx >> 12) & (CDIM - 1);
    int hh = n >> 6, ww = n & 63;
    const float* xb = x + (long long)(idx >> 12) * NPIX;
    const float* wc = w + c * 9;
    float s = 0.f;
#pragma unroll
    for (int i = 0; i < 3; i++) {
        int h2 = hh + i - 1;
        if ((unsigned)h2 < 64u) {
#pragma unroll
            for (int j = 0; j < 3; j++) {
                int w2 = ww + j - 1;
                if ((unsigned)w2 < 64u) s += xb[h2 * 64 + w2] * wc[i * 3 + j];
            }
        }
    }
    y[idx] = s;
}

// ---------------- 2) fp32 -> fp16 hi/lo ------------------------------------
__global__ void k_cvt(const float* __restrict__ src, u16* __restrict__ hi,
                      u16* __restrict__ lo, int n) {
    int i = blockIdx.x * blockDim.x + threadIdx.x;
    if (i >= n) return;
    float v = src[i];
    u16 h = f2h(v);
    hi[i] = h;
    lo[i] = f2h(v - h2f(h));
}

// ---------------- 3) transpose + fp16 split --------------------------------
__global__ void k_t2bf(const float* __restrict__ y, u16* __restrict__ thi,
                       u16* __restrict__ tlo) {
    __shared__ float t[32][33];
    long long zo = (long long)blockIdx.z * CDIM * NPIX;
    long long zt = (long long)blockIdx.z * NPIX * CDIM;
    int c0 = blockIdx.y * 32, n0 = blockIdx.x * 32;
#pragma unroll
    for (int j = 0; j < 4; j++) {
        int c = c0 + threadIdx.y + j * 8;
        t[threadIdx.y + j * 8][threadIdx.x] = y[zo + (long long)c * NPIX + n0 + threadIdx.x];
    }
    __syncthreads();
#pragma unroll
    for (int j = 0; j < 4; j++) {
        int n = n0 + threadIdx.y + j * 8;
        float v = t[threadIdx.x][threadIdx.y + j * 8];
        u16 h = f2h(v);
        thi[zt + (long long)n * CDIM + c0 + threadIdx.x] = h;
        tlo[zt + (long long)n * CDIM + c0 + threadIdx.x] = f2h(v - h2f(h));
    }
}

// ---------------- 4/5/7) tcgen05 GEMM: 128x128, A split, B single ----------
// out_mode: 1 = fp16 single;  2 = qk (q cols: scaled fp16 hi/lo, k: single);
// Ofp != 0 -> fp32 + bias.
#define GM_TMEMPTR 0
#define GM_MBAR 8
#define GM_AHI 1024
#define GM_ALO (GM_AHI + 16384)
#define GM_B   (GM_ALO + 16384)
#define GM_SMEM (GM_B + 16384)

__global__ void __launch_bounds__(256) k_gemm_tc(
    const uint4* __restrict__ Ahi, const uint4* __restrict__ Alo, long long sA,
    const uint4* __restrict__ B, long long sB,
    u16* __restrict__ Ohi, u16* __restrict__ Olo,
    float* __restrict__ Ofp, const float* __restrict__ bias,
    long long sO, int ldo, float scale_q, int qcols, int out_mode) {
#if HAS_TC
    extern __shared__ char sm[];
    uint32_t sb = smem_u32(sm);
    int tid = threadIdx.x, wid = tid >> 5;
    int mrow0 = blockIdx.x * 128;
    int brow0 = blockIdx.y * 128;
    const uint4* Ah = Ahi + blockIdx.z * sA + (long long)mrow0 * 64;
    const uint4* Al = Alo + blockIdx.z * sA + (long long)mrow0 * 64;
    const uint4* Bb = B + blockIdx.z * sB + (long long)brow0 * 64;

    if (wid == 0) {
        asm volatile("tcgen05.alloc.cta_group::1.sync.aligned.shared::cta.b32 [%0], %1;"
                     :: "r"(sb + GM_TMEMPTR), "r"(128u) : "memory");
    }
    if (tid == 0) mbar_init1(sb + GM_MBAR);
    __syncthreads();
    uint32_t tb;
    asm volatile("ld.shared.b32 %0, [%1];" : "=r"(tb) : "r"(sb + GM_TMEMPTR));

    u64 dAhi = mkdesc(sb + GM_AHI);
    u64 dAlo = mkdesc(sb + GM_ALO);
    u64 dB   = mkdesc(sb + GM_B);

    uint32_t ph = 0;
#pragma unroll 1
    for (int kc = 0; kc < 8; kc++) {
        if (kc) { mbar_wait(sb + GM_MBAR, ph); ph ^= 1; }
        int k8 = kc * 8;
#pragma unroll
        for (int l = 0; l < 4; l++) {
            int idx = tid + l * 256;
            int r = idx >> 3, j = idx & 7;
            uint32_t off = SWZ((uint32_t)(r * 128 + j * 16));
            *(uint4*)(sm + GM_AHI + off) = Ah[r * 64 + k8 + j];
            *(uint4*)(sm + GM_ALO + off) = Al[r * 64 + k8 + j];
            *(uint4*)(sm + GM_B + off)   = Bb[r * 64 + k8 + j];
        }
        FPROXY();
        __syncthreads();
        if (wid == 0) {
            if (elect1()) {
#pragma unroll
                for (int ks = 0; ks < 4; ks++)
                    mma_ss(tb, dAhi + ks * 2, dB + ks * 2, IDESC128H, !(kc == 0 && ks == 0));
#pragma unroll
                for (int ks = 0; ks < 4; ks++)
                    mma_ss(tb, dAlo + ks * 2, dB + ks * 2, IDESC128H, 1u);
                tc_commit(sb + GM_MBAR);
            }
        }
    }
    mbar_wait(sb + GM_MBAR, ph); ph ^= 1;

    if (tid < 128) {
        TCF_AFTER();
        uint32_t d[128];
        LDX32(d, tb);
        LDX32(d + 32, tb + 32);
        LDX32(d + 64, tb + 64);
        LDX32(d + 96, tb + 96);
        TC_WAIT_LD();
        int m = mrow0 + tid;
        long long obase = blockIdx.z * sO + (long long)m * ldo + brow0;
        if (Ofp) {
            float bv = bias ? bias[m] : 0.f;
#pragma unroll
            for (int j = 0; j < 32; j++) {
                float4 v = make_float4(__uint_as_float(d[4 * j]) + bv,
                                       __uint_as_float(d[4 * j + 1]) + bv,
                                       __uint_as_float(d[4 * j + 2]) + bv,
                                       __uint_as_float(d[4 * j + 3]) + bv);
                *(float4*)(Ofp + obase + 4 * j) = v;
            }
        } else if (out_mode == 2 && brow0 < qcols) {
            // q columns: scaled fp16 hi + residual lo
            uint32_t whi[64], wlo[64];
#pragma unroll
            for (int j = 0; j < 64; j++) {
                float a = __uint_as_float(d[2 * j]) * scale_q;
                float c = __uint_as_float(d[2 * j + 1]) * scale_q;
                u16 ah = f2h(a), ch = f2h(c);
                whi[j] = (uint32_t)ah | ((uint32_t)ch << 16);
                u16 al = f2h(a - h2f(ah)), cl = f2h(c - h2f(ch));
                wlo[j] = (uint32_t)al | ((uint32_t)cl << 16);
            }
#pragma unroll
            for (int j = 0; j < 16; j++) {
                *(uint4*)(Ohi + obase + 8 * j) = *(uint4*)&whi[4 * j];
                *(uint4*)(Olo + obase + 8 * j) = *(uint4*)&wlo[4 * j];
            }
        } else {
            // fp16 single
            uint32_t w[64];
#pragma unroll
            for (int j = 0; j < 64; j++) {
                u16 a = f2h(__uint_as_float(d[2 * j]));
                u16 c = f2h(__uint_as_float(d[2 * j + 1]));
                w[j] = (uint32_t)a | ((uint32_t)c << 16);
            }
#pragma unroll
            for (int j = 0; j < 16; j++)
                *(uint4*)(Ohi + obase + 8 * j) = *(uint4*)&w[4 * j];
        }
    }
    __syncthreads();
    if (wid == 0) {
        asm volatile("tcgen05.dealloc.cta_group::1.sync.aligned.b32 %0, %1;"
                     :: "r"(tb), "r"(128u));
    }
#else
    // compile-only fallback
    int tid = threadIdx.x;
    const u16* Ah = (const u16*)(Ahi + blockIdx.z * sA) + (long long)blockIdx.x * 128 * 512;
    const u16* Al = (const u16*)(Alo + blockIdx.z * sA) + (long long)blockIdx.x * 128 * 512;
    const u16* Bb = (const u16*)(B + blockIdx.z * sB) + (long long)blockIdx.y * 128 * 512;
    for (int e = tid; e < 128 * 128; e += 256) {
        int r = e >> 7, j = e & 127;
        float s = 0.f;
        for (int k = 0; k < 512; k++)
            s += (h2f(Ah[r * 512 + k]) + h2f(Al[r * 512 + k])) * h2f(Bb[j * 512 + k]);
        int m = blockIdx.x * 128 + r;
        long long obase = blockIdx.z * sO + (long long)m * ldo + blockIdx.y * 128 + j;
        if (Ofp) {
            Ofp[obase] = s + (bias ? bias[m] : 0.f);
        } else if (out_mode == 2 && blockIdx.y * 128 < qcols) {
            s *= scale_q;
            u16 hh = f2h(s);
            Ohi[obase] = hh;
            Olo[obase] = f2h(s - h2f(hh));
        } else {
            Ohi[obase] = f2h(s);
        }
    }
#endif
}

// ---------------- 6) attention: Q fp16 split, K/V/P fp16, occ 2 ------------
#define SM_TMEMPTR 0
#define SM_MBAR 8
#define SM_DEN 1024
#define SM_QHI 2048
#define SM_QLO (SM_QHI + 16384)
#define SM_KH(b) (34816 + (b) * 8192)
#define SM_VH(b) (51200 + (b) * 8192)
#define ATT_SMEM 67584

#define TM_S(b) ((b) * 64)
#define TM_O 128
#define TM_PH 192
#define ATT_TMCOLS 256

__global__ void __launch_bounds__(256) k_attn(
    const u16* __restrict__ qkthi, const u16* __restrict__ qktlo,
    const u16* __restrict__ vth, u16* __restrict__ oth) {
#if HAS_TC
    extern __shared__ char sm[];
    uint32_t sb = smem_u32(sm);
    int tid = threadIdx.x, wid = tid >> 5;
    int half = wid >> 2;
    uint32_t lofs = (uint32_t)(wid & 3) << 21;
    int n0 = blockIdx.x * 128;
    int h = blockIdx.y, b = blockIdx.z;
    const uint4* qh4 = (const uint4*)qkthi + (long long)b * NPIX * 128;
    const uint4* ql4 = (const uint4*)qktlo + (long long)b * NPIX * 128;
    const uint4* vh4 = (const uint4*)vth + ((long long)b * CDIM + h * DH) * 512;

    if (wid == 0) {
        asm volatile("tcgen05.alloc.cta_group::1.sync.aligned.shared::cta.b32 [%0], %1;"
                     :: "r"(sb + SM_TMEMPTR), "r"((uint32_t)ATT_TMCOLS) : "memory");
    }
    if (tid == 0) mbar_init1(sb + SM_MBAR);
    __syncthreads();
    uint32_t tb;
    asm volatile("ld.shared.b32 %0, [%1];" : "=r"(tb) : "r"(sb + SM_TMEMPTR));

    // ---- Q tile (fp16 hi/lo) ----
#pragma unroll
    for (int l = 0; l < 4; l++) {
        int idx = tid + l * 256;
        int r = idx >> 3, j = idx & 7;
        uint32_t off = SWZ((uint32_t)(r * 128 + j * 16));
        *(uint4*)(sm + SM_QHI + off) = qh4[(long long)(n0 + r) * 128 + h * 8 + j];
        *(uint4*)(sm + SM_QLO + off) = ql4[(long long)(n0 + r) * 128 + h * 8 + j];
    }
    // ---- K(0), K(1), V(0) — full coverage ----
#pragma unroll
    for (int l = 0; l < 2; l++) {
        int idx = tid + l * 256;
        int r = idx >> 3, j = idx & 7;
        uint32_t off = SWZ((uint32_t)(r * 128 + j * 16));
        *(uint4*)(sm + SM_KH(0) + off) = qh4[(long long)r * 128 + 64 + h * 8 + j];
        *(uint4*)(sm + SM_KH(1) + off) = qh4[(long long)(64 + r) * 128 + 64 + h * 8 + j];
        *(uint4*)(sm + SM_VH(0) + off) = vh4[(long long)r * 512 + j];
    }
    FPROXY();
    __syncthreads();

    u64 aQhi = mkdesc(sb + SM_QHI);
    u64 aQlo = mkdesc(sb + SM_QLO);

    // prologue: S(0)
    if (wid == 0) {
        if (elect1()) {
            u64 dK = mkdesc(sb + SM_KH(0));
#pragma unroll
            for (int ks = 0; ks < 4; ks++)
                mma_ss(tb + TM_S(0), aQhi + ks * 2, dK + ks * 2, IDESC64H, ks > 0);
#pragma unroll
            for (int ks = 0; ks < 4; ks++)
                mma_ss(tb + TM_S(0), aQlo + ks * 2, dK + ks * 2, IDESC64H, 1u);
            tc_commit(sb + SM_MBAR);
        }
    }

    float den = 0.f;
    uint32_t ph = 0;

#pragma unroll 1
    for (int t = 0; t < 64; t++) {
        mbar_wait(sb + SM_MBAR, ph); ph ^= 1;
        TCF_AFTER();

        // issue S(t+1) (overlaps softmax(t))
        if (t < 63 && wid == 0) {
            if (elect1()) {
                int nb = (t + 1) & 1;
                u64 dK = mkdesc(sb + SM_KH(nb));
#pragma unroll
                for (int ks = 0; ks < 4; ks++)
                    mma_ss(tb + TM_S(nb), aQhi + ks * 2, dK + ks * 2, IDESC64H, ks > 0);
#pragma unroll
                for (int ks = 0; ks < 4; ks++)
                    mma_ss(tb + TM_S(nb), aQlo + ks * 2, dK + ks * 2, IDESC64H, 1u);
            }
        }

        // prefetch K(t+2), V(t+1)
        if (t <= 61) {
            int m2 = (t + 2) * 64;
#pragma unroll
            for (int l = 0; l < 2; l++) {
                int idx = tid + l * 256;
                int r = idx >> 3, j = idx & 7;
                uint32_t off = SWZ((uint32_t)(r * 128 + j * 16));
                *(uint4*)(sm + SM_KH(t & 1) + off) = qh4[(long long)(m2 + r) * 128 + 64 + h * 8 + j];
            }
        }
        if (t <= 62) {
            int m1 = (t + 1) * 8;
#pragma unroll
            for (int l = 0; l < 2; l++) {
                int idx = tid + l * 256;
                int r = idx >> 3, j = idx & 7;
                uint32_t off = SWZ((uint32_t)(r * 128 + j * 16));
                *(uint4*)(sm + SM_VH((t + 1) & 1) + off) = vh4[(long long)r * 512 + m1 + j];
            }
        }

        // softmax(t)
        {
            uint32_t sr[32];
            LDX32(sr, tb + TM_S(t & 1) + half * 32);
            TC_WAIT_LD();
            uint32_t w[16];
            float dsum = 0.f;
#pragma unroll
            for (int j = 0; j < 16; j++) {
                float p0 = ex2f(__uint_as_float(sr[2 * j]));
                float p1 = ex2f(__uint_as_float(sr[2 * j + 1]));
                u16 h0 = f2h(p0), h1 = f2h(p1);
                w[j] = (uint32_t)h0 | ((uint32_t)h1 << 16);
                dsum += h2f(h0) + h2f(h1);
            }
            den += dsum;
            STX16(tb + TM_PH + half * 16 + lofs, w);
            TC_WAIT_ST();
        }
        TCF_BEFORE();
        FPROXY();
        __syncthreads();

        // issue AV(t), single commit covers S(t+1)+AV(t)
        if (wid == 0) {
            if (elect1()) {
                TCF_AFTER();
                u64 dVh = mkdesc(sb + SM_VH(t & 1));
#pragma unroll
                for (int ks = 0; ks < 4; ks++)
                    mma_ts(tb + TM_O, tb + TM_PH + ks * 8, dVh + ks * 2, IDESC64H,
                           (t > 0 || ks > 0) ? 1u : 0u);
                tc_commit(sb + SM_MBAR);
            }
        }
    }
    mbar_wait(sb + SM_MBAR, ph); ph ^= 1;

    // combine den halves
    *(float*)(sm + SM_DEN + tid * 4) = den;
    __syncthreads();

    // epilogue: O / den -> fp16 oth[n][512]
    if (tid < 128) {
        TCF_AFTER();
        uint32_t orr[64];
        LDX32(orr, tb + TM_O);
        LDX32(orr + 32, tb + TM_O + 32);
        TC_WAIT_LD();
        float dtot = *(float*)(sm + SM_DEN + tid * 4) +
                     *(float*)(sm + SM_DEN + (tid + 128) * 4);
        float inv = 1.0f / dtot;
        long long obase = ((long long)b * NPIX + n0 + tid) * CDIM + h * DH;
        uint32_t w[32];
#pragma unroll
        for (int j = 0; j < 32; j++) {
            u16 a = f2h(__uint_as_float(orr[2 * j]) * inv);
            u16 c = f2h(__uint_as_float(orr[2 * j + 1]) * inv);
            w[j] = (uint32_t)a | ((uint32_t)c << 16);
        }
#pragma unroll
        for (int j = 0; j < 8; j++)
            *(uint4*)(oth + obase + 8 * j) = *(uint4*)&w[4 * j];
    }
    __syncthreads();
    if (wid == 0) {
        asm volatile("tcgen05.dealloc.cta_group::1.sync.aligned.b32 %0, %1;"
                     :: "r"(tb), "r"((uint32_t)ATT_TMCOLS));
    }
#else
    // compile-only fallback
    int tid = threadIdx.x;
    if (tid >= 128) return;
    int n0 = blockIdx.x * 128;
    int h = blockIdx.y, b = blockIdx.z;
    long long qb = (long long)b * NPIX * QKD;
    int r = n0 + tid;
    float q[64], o[64], den = 0.f;
#pragma unroll
    for (int d = 0; d < 64; d++) {
        q[d] = h2f(qkthi[qb + (long long)r * QKD + h * 64 + d]) +
               h2f(qktlo[qb + (long long)r * QKD + h * 64 + d]);
        o[d] = 0.f;
    }
    for (int key = 0; key < NPIX; key++) {
        float s = 0.f;
        for (int d = 0; d < 64; d++)
            s += q[d] * h2f(qkthi[qb + (long long)key * QKD + 512 + h * 64 + d]);
        float p = h2f(f2h(ex2f(s)));
        den += p;
        for (int d = 0; d < 64; d++) {
            long long vi = ((long long)b * CDIM + h * 64 + d) * NPIX + key;
            o[d] += p * h2f(vth[vi]);
        }
    }
    long long ob = ((long long)b * NPIX + r) * CDIM + h * 64;
    for (int d = 0; d < 64; d++) oth[ob + d] = f2h(o[d] / den);
#endif
}

// ---------------------------------------------------------------------------
extern "C" void kernel_launch(void* const* d_in, const int* in_sizes, int n_in,
                              void* d_out, int out_size) {
    const float* x      = (const float*)d_in[0];
    const float* dw_w   = (const float*)d_in[1];
    const float* qkv_w  = (const float*)d_in[2];
    const float* proj_w = (const float*)d_in[3];
    const float* proj_b = (const float*)d_in[4];
    float* out = (float*)d_out;

    float* py;
    u16 *pythi, *pytlo, *pwhi, *pwlo, *ppwhi, *ppwlo;
    u16 *pqkthi, *pqktlo, *pvth, *poth;
    cudaGetSymbolAddress((void**)&py,     g_y);
    cudaGetSymbolAddress((void**)&pythi,  g_ythi);
    cudaGetSymbolAddress((void**)&pytlo,  g_ytlo);
    cudaGetSymbolAddress((void**)&pwhi,   g_whi);
    cudaGetSymbolAddress((void**)&pwlo,   g_wlo);
    cudaGetSymbolAddress((void**)&ppwhi,  g_pwhi);
    cudaGetSymbolAddress((void**)&ppwlo,  g_pwlo);
    cudaGetSymbolAddress((void**)&pqkthi, g_qkthi);
    cudaGetSymbolAddress((void**)&pqktlo, g_qktlo);
    cudaGetSymbolAddress((void**)&pvth,   g_vth);
    cudaGetSymbolAddress((void**)&poth,   g_oth);

    cudaFuncSetAttribute(k_attn, cudaFuncAttributeMaxDynamicSharedMemorySize, ATT_SMEM);
    cudaFuncSetAttribute(k_gemm_tc, cudaFuncAttributeMaxDynamicSharedMemorySize, GM_SMEM);

    k_dwconv<<<(TOTAL + 255) / 256, 256>>>(x, dw_w, py);
    k_cvt<<<(3 * CDIM * CDIM + 255) / 256, 256>>>(qkv_w, pwhi, pwlo, 3 * CDIM * CDIM);
    k_cvt<<<(CDIM * CDIM + 255) / 256, 256>>>(proj_w, ppwhi, ppwlo, CDIM * CDIM);
    {
        dim3 grid(NPIX / 32, CDIM / 32, BATCH);
        k_t2bf<<<grid, dim3(32, 8)>>>(py, pythi, pytlo);
    }

    long long sYT = (long long)NPIX * CDIM / 8;

    // qk GEMM: A = yT hi/lo, B = w_qk single  ->  qkt[n][1024]
    {
        dim3 grid(NPIX / 128, QKD / 128, BATCH);
        k_gemm_tc<<<grid, 256, GM_SMEM>>>(
            (const uint4*)pythi, (const uint4*)pytlo, sYT,
            (const uint4*)pwhi, 0,
            pqkthi, pqktlo, nullptr, nullptr,
            (long long)NPIX * QKD, QKD, ATT_SCALE_L2E, 512, 2);
    }
    // V GEMM: A = w_v hi/lo, B = yT single  ->  vt[c][n] fp16
    {
        dim3 grid(CDIM / 128, NPIX / 128, BATCH);
        k_gemm_tc<<<grid, 256, GM_SMEM>>>(
            (const uint4*)(pwhi + 1024 * CDIM / 8 * 8), (const uint4*)(pwlo + 1024 * CDIM / 8 * 8), 0,
            (const uint4*)pythi, sYT,
            pvth, nullptr, nullptr, nullptr,
            (long long)CDIM * NPIX, NPIX, 1.0f, 0, 1);
    }
    // attention -> oth[n][512] fp16
    {
        dim3 grid(NPIX / 128, HEADS, BATCH);
        k_attn<<<grid, 256, ATT_SMEM>>>(pqkthi, pqktlo, pvth, poth);
    }
    // proj GEMM: A = pw hi/lo, B = oth single -> out[c][n] fp32 + bias
    {
        dim3 grid(CDIM / 128, NPIX / 128, BATCH);
        k_gemm_tc<<<grid, 256, GM_SMEM>>>(
            (const uint4*)ppwhi, (const uint4*)ppwlo, 0,
            (const uint4*)poth, sYT,
            nullptr, nullptr, out, proj_b,
            (long long)CDIM * NPIX, NPIX, 1.0f, 0, 0);
    }
}

// round 14
// speedup vs baseline: 2.4392x; 1.1863x over previous
#include <cuda_runtime.h>
#include <cuda_bf16.h>
#include <cuda_fp16.h>
#include <cstdint>

// ---------------------------------------------------------------------------
// LightweightSelfAttention  (B=2, C=512, H=W=64, heads=8, dh=64)
// All-tcgen05, fp16 data plane.
// R14: f16x2 softmax (ex2.approx.f16x2), fused dwconv+transpose+split,
//      register-staged K/V prefetch in attention.
// ---------------------------------------------------------------------------

#if defined(__CUDA_ARCH_FEAT_SM103_ALL) || defined(__CUDA_ARCH_FEAT_SM100_ALL)
#define HAS_TC 1
#else
#define HAS_TC 0
#endif

#define BATCH 2
#define CDIM 512
#define HEADS 8
#define DH 64
#define NPIX 4096
#define TOTAL (BATCH*CDIM*NPIX)
#define QKD 1024

typedef unsigned short u16;
typedef unsigned long long u64;

__device__ u16 g_ythi[BATCH * NPIX * CDIM];    // fp16 hi (y transposed)
__device__ u16 g_ytlo[BATCH * NPIX * CDIM];    // fp16 lo
__device__ u16 g_whi[3 * CDIM * CDIM];         // fp16 hi (also B single)
__device__ u16 g_wlo[3 * CDIM * CDIM];
__device__ u16 g_pwhi[CDIM * CDIM];
__device__ u16 g_pwlo[CDIM * CDIM];
__device__ u16 g_qkthi[BATCH * NPIX * QKD];    // fp16: q-hi 0..511, k 512..1023
__device__ u16 g_qktlo[BATCH * NPIX * QKD];    // fp16: q-lo 0..511
__device__ u16 g_vth[BATCH * CDIM * NPIX];     // fp16 V^T
__device__ u16 g_oth[BATCH * NPIX * CDIM];     // fp16 attention out

#define ATT_SCALE_L2E 0.18033688f   /* 0.125 * log2(e) */

// ---------------- helpers --------------------------------------------------
__device__ __forceinline__ uint32_t smem_u32(const void* p) {
    uint32_t a;
    asm("{ .reg .u64 t; cvta.to.shared.u64 t, %1; cvt.u32.u64 %0, t; }"
        : "=r"(a) : "l"(p));
    return a;
}
__device__ __forceinline__ u16 f2h(float x) {
    return __half_as_ushort(__float2half_rn(x));
}
__device__ __forceinline__ float h2f(u16 u) {
    return __half2float(__ushort_as_half(u));
}
#define SWZ(o) ((o) ^ (((o) >> 3) & 0x70))

#if HAS_TC
__device__ __forceinline__ unsigned elect1() {
    unsigned p;
    asm volatile("{\n\t.reg .pred p;\n\telect.sync _|p, 0xFFFFFFFF;\n\t"
                 "selp.b32 %0, 1, 0, p;\n\t}" : "=r"(p));
    return p;
}
__device__ __forceinline__ void mma_ss(uint32_t d, u64 a, u64 b, uint32_t id, uint32_t en) {
    asm volatile("{\n\t.reg .pred p;\n\tsetp.ne.u32 p, %5, 0;\n\t"
        "tcgen05.mma.cta_group::1.kind::f16 [%0], %1, %2, %3, {%4,%4,%4,%4}, p;\n\t}"
        :: "r"(d), "l"(a), "l"(b), "r"(id), "r"(0u), "r"(en) : "memory");
}
__device__ __forceinline__ void mma_ts(uint32_t d, uint32_t a, u64 b, uint32_t id, uint32_t en) {
    asm volatile("{\n\t.reg .pred p;\n\tsetp.ne.u32 p, %5, 0;\n\t"
        "tcgen05.mma.cta_group::1.kind::f16 [%0], [%1], %2, %3, {%4,%4,%4,%4}, p;\n\t}"
        :: "r"(d), "r"(a), "l"(b), "r"(id), "r"(0u), "r"(en) : "memory");
}
__device__ __forceinline__ void tc_commit(uint32_t mbar) {
    asm volatile("tcgen05.commit.cta_group::1.mbarrier::arrive::one.shared::cluster.b64 [%0];"
                 :: "r"(mbar) : "memory");
}
__device__ __forceinline__ void mbar_init1(uint32_t mbar) {
    asm volatile("mbarrier.init.shared.b64 [%0], %1;" :: "r"(mbar), "r"(1u) : "memory");
}
__device__ __forceinline__ void mbar_wait(uint32_t mbar, uint32_t ph) {
    asm volatile("{\n\t.reg .pred P1;\n\tLAB1_%=:\n\t"
        "mbarrier.try_wait.parity.acquire.cta.shared::cta.b64 P1, [%0], %1, 0x989680;\n\t"
        "@P1 bra.uni LAB2_%=;\n\tbra.uni LAB1_%=;\n\tLAB2_%=:\n\t}"
        :: "r"(mbar), "r"(ph) : "memory");
}
#define TCF_AFTER()  asm volatile("tcgen05.fence::after_thread_sync;" ::: "memory")
#define TCF_BEFORE() asm volatile("tcgen05.fence::before_thread_sync;" ::: "memory")
#define FPROXY()     asm volatile("fence.proxy.async.shared::cta;" ::: "memory")
#define TC_WAIT_LD() asm volatile("tcgen05.wait::ld.sync.aligned;" ::: "memory")
#define TC_WAIT_ST() asm volatile("tcgen05.wait::st.sync.aligned;" ::: "memory")

#define LDX32(r, ta) \
    asm volatile("tcgen05.ld.sync.aligned.32x32b.x32.b32 " \
        "{%0, %1, %2, %3, %4, %5, %6, %7, %8, %9, %10, %11, %12, %13, %14, %15, " \
        " %16, %17, %18, %19, %20, %21, %22, %23, %24, %25, %26, %27, %28, %29, %30, %31}, [%32];" \
        : "=r"((r)[0]),  "=r"((r)[1]),  "=r"((r)[2]),  "=r"((r)[3]), \
          "=r"((r)[4]),  "=r"((r)[5]),  "=r"((r)[6]),  "=r"((r)[7]), \
          "=r"((r)[8]),  "=r"((r)[9]),  "=r"((r)[10]), "=r"((r)[11]), \
          "=r"((r)[12]), "=r"((r)[13]), "=r"((r)[14]), "=r"((r)[15]), \
          "=r"((r)[16]), "=r"((r)[17]), "=r"((r)[18]), "=r"((r)[19]), \
          "=r"((r)[20]), "=r"((r)[21]), "=r"((r)[22]), "=r"((r)[23]), \
          "=r"((r)[24]), "=r"((r)[25]), "=r"((r)[26]), "=r"((r)[27]), \
          "=r"((r)[28]), "=r"((r)[29]), "=r"((r)[30]), "=r"((r)[31]) \
        : "r"(ta))

#define STX16(ta, r) \
    asm volatile("tcgen05.st.sync.aligned.32x32b.x16.b32 [%0], " \
        "{%1, %2, %3, %4, %5, %6, %7, %8, %9, %10, %11, %12, %13, %14, %15, %16};" \
        :: "r"(ta), \
           "r"((r)[0]),  "r"((r)[1]),  "r"((r)[2]),  "r"((r)[3]), \
           "r"((r)[4]),  "r"((r)[5]),  "r"((r)[6]),  "r"((r)[7]), \
           "r"((r)[8]),  "r"((r)[9]),  "r"((r)[10]), "r"((r)[11]), \
           "r"((r)[12]), "r"((r)[13]), "r"((r)[14]), "r"((r)[15]) \
        : "memory")

#define DESC_K  ((2ull<<61)|(1ull<<46)|(64ull<<32)|(1ull<<16))
__device__ __forceinline__ u64 mkdesc(uint32_t addr) {
    return DESC_K | ((u64)(addr >> 4) & 0x3FFF);
}
#define IDESC64H   ((1u<<4)|(8u<<17)|(8u<<24))    /* fp16, M=128 N=64 */
#define IDESC128H  ((1u<<4)|(16u<<17)|(8u<<24))   /* fp16, M=128 N=128 */
#endif  // HAS_TC

// ---------------- 1) fused dwconv + transpose + fp16 split -----------------
// 32n x 32c tile; n-tile never crosses an image row (32 | 64).
__global__ void k_dwt(const float* __restrict__ x, const float* __restrict__ w,
                      u16* __restrict__ thi, u16* __restrict__ tlo) {
    __shared__ float t[32][33];
    int b = blockIdx.z;
    int c0 = blockIdx.y * 32, n0 = blockIdx.x * 32;
    int hh = n0 >> 6, w0 = n0 & 63;
    int tx = threadIdx.x, ty = threadIdx.y;
#pragma unroll
    for (int j = 0; j < 4; j++) {
        int c = c0 + ty + j * 8;
        const float* xb = x + ((long long)(b * CDIM + c)) * NPIX;
        const float* wc = w + c * 9;
        int ww = w0 + tx;
        float s = 0.f;
#pragma unroll
        for (int i = 0; i < 3; i++) {
            int h2 = hh + i - 1;
            if ((unsigned)h2 < 64u) {
#pragma unroll
                for (int jj = 0; jj < 3; jj++) {
                    int w2 = ww + jj - 1;
                    if ((unsigned)w2 < 64u) s += xb[h2 * 64 + w2] * wc[i * 3 + jj];
                }
            }
        }
        t[ty + j * 8][tx] = s;
    }
    __syncthreads();
    long long zt = (long long)b * NPIX * CDIM;
#pragma unroll
    for (int j = 0; j < 4; j++) {
        int n = n0 + ty + j * 8;
        float v = t[tx][ty + j * 8];
        u16 h = f2h(v);
        thi[zt + (long long)n * CDIM + c0 + tx] = h;
        tlo[zt + (long long)n * CDIM + c0 + tx] = f2h(v - h2f(h));
    }
}

// ---------------- 2) fp32 -> fp16 hi/lo (weights) --------------------------
__global__ void k_cvt(const float* __restrict__ src, u16* __restrict__ hi,
                      u16* __restrict__ lo, int n) {
    int i = blockIdx.x * blockDim.x + threadIdx.x;
    if (i >= n) return;
    float v = src[i];
    u16 h = f2h(v);
    hi[i] = h;
    lo[i] = f2h(v - h2f(h));
}

// ---------------- 4/5/7) tcgen05 GEMM: 128x128, A split, B single ----------
#define GM_TMEMPTR 0
#define GM_MBAR 8
#define GM_AHI 1024
#define GM_ALO (GM_AHI + 16384)
#define GM_B   (GM_ALO + 16384)
#define GM_SMEM (GM_B + 16384)

__global__ void __launch_bounds__(256) k_gemm_tc(
    const uint4* __restrict__ Ahi, const uint4* __restrict__ Alo, long long sA,
    const uint4* __restrict__ B, long long sB,
    u16* __restrict__ Ohi, u16* __restrict__ Olo,
    float* __restrict__ Ofp, const float* __restrict__ bias,
    long long sO, int ldo, float scale_q, int qcols, int out_mode) {
#if HAS_TC
    extern __shared__ char sm[];
    uint32_t sb = smem_u32(sm);
    int tid = threadIdx.x, wid = tid >> 5;
    int mrow0 = blockIdx.x * 128;
    int brow0 = blockIdx.y * 128;
    const uint4* Ah = Ahi + blockIdx.z * sA + (long long)mrow0 * 64;
    const uint4* Al = Alo + blockIdx.z * sA + (long long)mrow0 * 64;
    const uint4* Bb = B + blockIdx.z * sB + (long long)brow0 * 64;

    if (wid == 0) {
        asm volatile("tcgen05.alloc.cta_group::1.sync.aligned.shared::cta.b32 [%0], %1;"
                     :: "r"(sb + GM_TMEMPTR), "r"(128u) : "memory");
    }
    if (tid == 0) mbar_init1(sb + GM_MBAR);
    __syncthreads();
    uint32_t tb;
    asm volatile("ld.shared.b32 %0, [%1];" : "=r"(tb) : "r"(sb + GM_TMEMPTR));

    u64 dAhi = mkdesc(sb + GM_AHI);
    u64 dAlo = mkdesc(sb + GM_ALO);
    u64 dB   = mkdesc(sb + GM_B);

    uint32_t ph = 0;
#pragma unroll 1
    for (int kc = 0; kc < 8; kc++) {
        if (kc) { mbar_wait(sb + GM_MBAR, ph); ph ^= 1; }
        int k8 = kc * 8;
#pragma unroll
        for (int l = 0; l < 4; l++) {
            int idx = tid + l * 256;
            int r = idx >> 3, j = idx & 7;
            uint32_t off = SWZ((uint32_t)(r * 128 + j * 16));
            *(uint4*)(sm + GM_AHI + off) = Ah[r * 64 + k8 + j];
            *(uint4*)(sm + GM_ALO + off) = Al[r * 64 + k8 + j];
            *(uint4*)(sm + GM_B + off)   = Bb[r * 64 + k8 + j];
        }
        FPROXY();
        __syncthreads();
        if (wid == 0) {
            if (elect1()) {
#pragma unroll
                for (int ks = 0; ks < 4; ks++)
                    mma_ss(tb, dAhi + ks * 2, dB + ks * 2, IDESC128H, !(kc == 0 && ks == 0));
#pragma unroll
                for (int ks = 0; ks < 4; ks++)
                    mma_ss(tb, dAlo + ks * 2, dB + ks * 2, IDESC128H, 1u);
                tc_commit(sb + GM_MBAR);
            }
        }
    }
    mbar_wait(sb + GM_MBAR, ph); ph ^= 1;

    if (tid < 128) {
        TCF_AFTER();
        uint32_t d[128];
        LDX32(d, tb);
        LDX32(d + 32, tb + 32);
        LDX32(d + 64, tb + 64);
        LDX32(d + 96, tb + 96);
        TC_WAIT_LD();
        int m = mrow0 + tid;
        long long obase = blockIdx.z * sO + (long long)m * ldo + brow0;
        if (Ofp) {
            float bv = bias ? bias[m] : 0.f;
#pragma unroll
            for (int j = 0; j < 32; j++) {
                float4 v = make_float4(__uint_as_float(d[4 * j]) + bv,
                                       __uint_as_float(d[4 * j + 1]) + bv,
                                       __uint_as_float(d[4 * j + 2]) + bv,
                                       __uint_as_float(d[4 * j + 3]) + bv);
                *(float4*)(Ofp + obase + 4 * j) = v;
            }
        } else if (out_mode == 2 && brow0 < qcols) {
            uint32_t whi[64], wlo[64];
#pragma unroll
            for (int j = 0; j < 64; j++) {
                float a = __uint_as_float(d[2 * j]) * scale_q;
                float c = __uint_as_float(d[2 * j + 1]) * scale_q;
                u16 ah = f2h(a), ch = f2h(c);
                whi[j] = (uint32_t)ah | ((uint32_t)ch << 16);
                u16 al = f2h(a - h2f(ah)), cl = f2h(c - h2f(ch));
                wlo[j] = (uint32_t)al | ((uint32_t)cl << 16);
            }
#pragma unroll
            for (int j = 0; j < 16; j++) {
                *(uint4*)(Ohi + obase + 8 * j) = *(uint4*)&whi[4 * j];
                *(uint4*)(Olo + obase + 8 * j) = *(uint4*)&wlo[4 * j];
            }
        } else {
            uint32_t w[64];
#pragma unroll
            for (int j = 0; j < 64; j++) {
                u16 a = f2h(__uint_as_float(d[2 * j]));
                u16 c = f2h(__uint_as_float(d[2 * j + 1]));
                w[j] = (uint32_t)a | ((uint32_t)c << 16);
            }
#pragma unroll
            for (int j = 0; j < 16; j++)
                *(uint4*)(Ohi + obase + 8 * j) = *(uint4*)&w[4 * j];
        }
    }
    __syncthreads();
    if (wid == 0) {
        asm volatile("tcgen05.dealloc.cta_group::1.sync.aligned.b32 %0, %1;"
                     :: "r"(tb), "r"(128u));
    }
#else
    // compile-only fallback
    int tid = threadIdx.x;
    const u16* Ah = (const u16*)(Ahi + blockIdx.z * sA) + (long long)blockIdx.x * 128 * 512;
    const u16* Al = (const u16*)(Alo + blockIdx.z * sA) + (long long)blockIdx.x * 128 * 512;
    const u16* Bb = (const u16*)(B + blockIdx.z * sB) + (long long)blockIdx.y * 128 * 512;
    for (int e = tid; e < 128 * 128; e += 256) {
        int r = e >> 7, j = e & 127;
        float s = 0.f;
        for (int k = 0; k < 512; k++)
            s += (h2f(Ah[r * 512 + k]) + h2f(Al[r * 512 + k])) * h2f(Bb[j * 512 + k]);
        int m = blockIdx.x * 128 + r;
        long long obase = blockIdx.z * sO + (long long)m * ldo + blockIdx.y * 128 + j;
        if (Ofp) {
            Ofp[obase] = s + (bias ? bias[m] : 0.f);
        } else if (out_mode == 2 && blockIdx.y * 128 < qcols) {
            s *= scale_q;
            u16 hh = f2h(s);
            Ohi[obase] = hh;
            Olo[obase] = f2h(s - h2f(hh));
        } else {
            Ohi[obase] = f2h(s);
        }
    }
#endif
}

// ---------------- 6) attention: f16x2 softmax, staged prefetch -------------
#define SM_TMEMPTR 0
#define SM_MBAR 8
#define SM_DEN 1024
#define SM_QHI 2048
#define SM_QLO (SM_QHI + 16384)
#define SM_KH(b) (34816 + (b) * 8192)
#define SM_VH(b) (51200 + (b) * 8192)
#define ATT_SMEM 67584

#define TM_S(b) ((b) * 64)
#define TM_O 128
#define TM_PH 192
#define ATT_TMCOLS 256

__global__ void __launch_bounds__(256) k_attn(
    const u16* __restrict__ qkthi, const u16* __restrict__ qktlo,
    const u16* __restrict__ vth, u16* __restrict__ oth) {
#if HAS_TC
    extern __shared__ char sm[];
    uint32_t sb = smem_u32(sm);
    int tid = threadIdx.x, wid = tid >> 5;
    int half = wid >> 2;
    uint32_t lofs = (uint32_t)(wid & 3) << 21;
    int n0 = blockIdx.x * 128;
    int h = blockIdx.y, b = blockIdx.z;
    const uint4* qh4 = (const uint4*)qkthi + (long long)b * NPIX * 128;
    const uint4* ql4 = (const uint4*)qktlo + (long long)b * NPIX * 128;
    const uint4* vh4 = (const uint4*)vth + ((long long)b * CDIM + h * DH) * 512;

    if (wid == 0) {
        asm volatile("tcgen05.alloc.cta_group::1.sync.aligned.shared::cta.b32 [%0], %1;"
                     :: "r"(sb + SM_TMEMPTR), "r"((uint32_t)ATT_TMCOLS) : "memory");
    }
    if (tid == 0) mbar_init1(sb + SM_MBAR);
    __syncthreads();
    uint32_t tb;
    asm volatile("ld.shared.b32 %0, [%1];" : "=r"(tb) : "r"(sb + SM_TMEMPTR));

    // thread's fixed (r, j) for 2-pass tile loads
    int r0a = tid >> 3, ja = tid & 7;
    int r0b = (tid + 256) >> 3, jb = (tid + 256) & 7;
    uint32_t offa = SWZ((uint32_t)(r0a * 128 + ja * 16));
    uint32_t offb = SWZ((uint32_t)(r0b * 128 + jb * 16));

    // ---- Q tile (fp16 hi/lo) ----
#pragma unroll
    for (int l = 0; l < 4; l++) {
        int idx = tid + l * 256;
        int r = idx >> 3, j = idx & 7;
        uint32_t off = SWZ((uint32_t)(r * 128 + j * 16));
        *(uint4*)(sm + SM_QHI + off) = qh4[(long long)(n0 + r) * 128 + h * 8 + j];
        *(uint4*)(sm + SM_QLO + off) = ql4[(long long)(n0 + r) * 128 + h * 8 + j];
    }
    // ---- K(0), K(1), V(0) ----
#pragma unroll
    for (int l = 0; l < 2; l++) {
        int idx = tid + l * 256;
        int r = idx >> 3, j = idx & 7;
        uint32_t off = SWZ((uint32_t)(r * 128 + j * 16));
        *(uint4*)(sm + SM_KH(0) + off) = qh4[(long long)r * 128 + 64 + h * 8 + j];
        *(uint4*)(sm + SM_KH(1) + off) = qh4[(long long)(64 + r) * 128 + 64 + h * 8 + j];
        *(uint4*)(sm + SM_VH(0) + off) = vh4[(long long)r * 512 + j];
    }
    FPROXY();
    __syncthreads();

    u64 aQhi = mkdesc(sb + SM_QHI);
    u64 aQlo = mkdesc(sb + SM_QLO);

    // prologue: S(0)
    if (wid == 0) {
        if (elect1()) {
            u64 dK = mkdesc(sb + SM_KH(0));
#pragma unroll
            for (int ks = 0; ks < 4; ks++)
                mma_ss(tb + TM_S(0), aQhi + ks * 2, dK + ks * 2, IDESC64H, ks > 0);
#pragma unroll
            for (int ks = 0; ks < 4; ks++)
                mma_ss(tb + TM_S(0), aQlo + ks * 2, dK + ks * 2, IDESC64H, 1u);
            tc_commit(sb + SM_MBAR);
        }
    }

    float den = 0.f;
    uint32_t ph = 0;

#pragma unroll 1
    for (int t = 0; t < 64; t++) {
        mbar_wait(sb + SM_MBAR, ph); ph ^= 1;
        TCF_AFTER();

        // issue S(t+1) (overlaps softmax(t))
        if (t < 63 && wid == 0) {
            if (elect1()) {
                int nb = (t + 1) & 1;
                u64 dK = mkdesc(sb + SM_KH(nb));
#pragma unroll
                for (int ks = 0; ks < 4; ks++)
                    mma_ss(tb + TM_S(nb), aQhi + ks * 2, dK + ks * 2, IDESC64H, ks > 0);
#pragma unroll
                for (int ks = 0; ks < 4; ks++)
                    mma_ss(tb + TM_S(nb), aQlo + ks * 2, dK + ks * 2, IDESC64H, 1u);
            }
        }

        // stage K(t+2), V(t+1) loads into registers (LDGs in flight over softmax)
        uint4 kra, krb, vra, vrb;
        bool hask = (t <= 61), hasv = (t <= 62);
        if (hask) {
            int m2 = (t + 2) * 64;
            kra = qh4[(long long)(m2 + r0a) * 128 + 64 + h * 8 + ja];
            krb = qh4[(long long)(m2 + r0b) * 128 + 64 + h * 8 + jb];
        }
        if (hasv) {
            int m1 = (t + 1) * 8;
            vra = vh4[(long long)r0a * 512 + m1 + ja];
            vrb = vh4[(long long)r0b * 512 + m1 + jb];
        }

        // softmax(t): f16x2 path
        {
            uint32_t sr[32];
            LDX32(sr, tb + TM_S(t & 1) + half * 32);
            TC_WAIT_LD();
            uint32_t w[16];
            float dsum = 0.f;
#pragma unroll
            for (int j = 0; j < 16; j++) {
                uint32_t s2, p2;
                // low half = col 2j (first MMA col), high = col 2j+1
                asm("cvt.rn.f16x2.f32 %0, %1, %2;" : "=r"(s2)
                    : "f"(__uint_as_float(sr[2 * j + 1])), "f"(__uint_as_float(sr[2 * j])));
                asm("ex2.approx.f16x2 %0, %1;" : "=r"(p2) : "r"(s2));
                w[j] = p2;
                dsum += h2f((u16)(p2 & 0xFFFF)) + h2f((u16)(p2 >> 16));
            }
            den += dsum;
            STX16(tb + TM_PH + half * 16 + lofs, w);
            TC_WAIT_ST();
        }

        // store staged K/V to smem (buffers are free: K(t)/V(t-1) consumed)
        if (hask) {
            *(uint4*)(sm + SM_KH(t & 1) + offa) = kra;
            *(uint4*)(sm + SM_KH(t & 1) + offb) = krb;
        }
        if (hasv) {
            *(uint4*)(sm + SM_VH((t + 1) & 1) + offa) = vra;
            *(uint4*)(sm + SM_VH((t + 1) & 1) + offb) = vrb;
        }
        TCF_BEFORE();
        FPROXY();
        __syncthreads();

        // issue AV(t), single commit covers S(t+1)+AV(t)
        if (wid == 0) {
            if (elect1()) {
                TCF_AFTER();
                u64 dVh = mkdesc(sb + SM_VH(t & 1));
#pragma unroll
                for (int ks = 0; ks < 4; ks++)
                    mma_ts(tb + TM_O, tb + TM_PH + ks * 8, dVh + ks * 2, IDESC64H,
                           (t > 0 || ks > 0) ? 1u : 0u);
                tc_commit(sb + SM_MBAR);
            }
        }
    }
    mbar_wait(sb + SM_MBAR, ph); ph ^= 1;

    // combine den halves
    *(float*)(sm + SM_DEN + tid * 4) = den;
    __syncthreads();

    // epilogue: O / den -> fp16 oth[n][512]
    if (tid < 128) {
        TCF_AFTER();
        uint32_t orr[64];
        LDX32(orr, tb + TM_O);
        LDX32(orr + 32, tb + TM_O + 32);
        TC_WAIT_LD();
        float dtot = *(float*)(sm + SM_DEN + tid * 4) +
                     *(float*)(sm + SM_DEN + (tid + 128) * 4);
        float inv = 1.0f / dtot;
        long long obase = ((long long)b * NPIX + n0 + tid) * CDIM + h * DH;
        uint32_t w[32];
#pragma unroll
        for (int j = 0; j < 32; j++) {
            u16 a = f2h(__uint_as_float(orr[2 * j]) * inv);
            u16 c = f2h(__uint_as_float(orr[2 * j + 1]) * inv);
            w[j] = (uint32_t)a | ((uint32_t)c << 16);
        }
#pragma unroll
        for (int j = 0; j < 8; j++)
            *(uint4*)(oth + obase + 8 * j) = *(uint4*)&w[4 * j];
    }
    __syncthreads();
    if (wid == 0) {
        asm volatile("tcgen05.dealloc.cta_group::1.sync.aligned.b32 %0, %1;"
                     :: "r"(tb), "r"((uint32_t)ATT_TMCOLS));
    }
#else
    // compile-only fallback
    int tid = threadIdx.x;
    if (tid >= 128) return;
    int n0 = blockIdx.x * 128;
    int h = blockIdx.y, b = blockIdx.z;
    long long qb = (long long)b * NPIX * QKD;
    int r = n0 + tid;
    float q[64], o[64], den = 0.f;
#pragma unroll
    for (int d = 0; d < 64; d++) {
        q[d] = h2f(qkthi[qb + (long long)r * QKD + h * 64 + d]) +
               h2f(qktlo[qb + (long long)r * QKD + h * 64 + d]);
        o[d] = 0.f;
    }
    for (int key = 0; key < NPIX; key++) {
        float s = 0.f;
        for (int d = 0; d < 64; d++)
            s += q[d] * h2f(qkthi[qb + (long long)key * QKD + 512 + h * 64 + d]);
        float p = h2f(f2h(exp2f(h2f(f2h(s)))));
        den += p;
        for (int d = 0; d < 64; d++) {
            long long vi = ((long long)b * CDIM + h * 64 + d) * NPIX + key;
            o[d] += p * h2f(vth[vi]);
        }
    }
    long long ob = ((long long)b * NPIX + r) * CDIM + h * 64;
    for (int d = 0; d < 64; d++) oth[ob + d] = f2h(o[d] / den);
#endif
}

// ---------------------------------------------------------------------------
extern "C" void kernel_launch(void* const* d_in, const int* in_sizes, int n_in,
                              void* d_out, int out_size) {
    const float* x      = (const float*)d_in[0];
    const float* dw_w   = (const float*)d_in[1];
    const float* qkv_w  = (const float*)d_in[2];
    const float* proj_w = (const float*)d_in[3];
    const float* proj_b = (const float*)d_in[4];
    float* out = (float*)d_out;

    u16 *pythi, *pytlo, *pwhi, *pwlo, *ppwhi, *ppwlo;
    u16 *pqkthi, *pqktlo, *pvth, *poth;
    cudaGetSymbolAddress((void**)&pythi,  g_ythi);
    cudaGetSymbolAddress((void**)&pytlo,  g_ytlo);
    cudaGetSymbolAddress((void**)&pwhi,   g_whi);
    cudaGetSymbolAddress((void**)&pwlo,   g_wlo);
    cudaGetSymbolAddress((void**)&ppwhi,  g_pwhi);
    cudaGetSymbolAddress((void**)&ppwlo,  g_pwlo);
    cudaGetSymbolAddress((void**)&pqkthi, g_qkthi);
    cudaGetSymbolAddress((void**)&pqktlo, g_qktlo);
    cudaGetSymbolAddress((void**)&pvth,   g_vth);
    cudaGetSymbolAddress((void**)&poth,   g_oth);

    cudaFuncSetAttribute(k_attn, cudaFuncAttributeMaxDynamicSharedMemorySize, ATT_SMEM);
    cudaFuncSetAttribute(k_gemm_tc, cudaFuncAttributeMaxDynamicSharedMemorySize, GM_SMEM);

    // 1) fused dwconv + transpose + split -> yT fp16 hi/lo
    {
        dim3 grid(NPIX / 32, CDIM / 32, BATCH);
        k_dwt<<<grid, dim3(32, 8)>>>(x, dw_w, pythi, pytlo);
    }
    // 2) weight conversions
    k_cvt<<<(3 * CDIM * CDIM + 255) / 256, 256>>>(qkv_w, pwhi, pwlo, 3 * CDIM * CDIM);
    k_cvt<<<(CDIM * CDIM + 255) / 256, 256>>>(proj_w, ppwhi, ppwlo, CDIM * CDIM);

    long long sYT = (long long)NPIX * CDIM / 8;

    // qk GEMM: A = yT hi/lo, B = w_qk single  ->  qkt[n][1024]
    {
        dim3 grid(NPIX / 128, QKD / 128, BATCH);
        k_gemm_tc<<<grid, 256, GM_SMEM>>>(
            (const uint4*)pythi, (const uint4*)pytlo, sYT,
            (const uint4*)pwhi, 0,
            pqkthi, pqktlo, nullptr, nullptr,
            (long long)NPIX * QKD, QKD, ATT_SCALE_L2E, 512, 2);
    }
    // V GEMM: A = w_v hi/lo, B = yT single  ->  vt[c][n] fp16
    {
        dim3 grid(CDIM / 128, NPIX / 128, BATCH);
        k_gemm_tc<<<grid, 256, GM_SMEM>>>(
            (const uint4*)(pwhi + 1024 * CDIM), (const uint4*)(pwlo + 1024 * CDIM), 0,
            (const uint4*)pythi, sYT,
            pvth, nullptr, nullptr, nullptr,
            (long long)CDIM * NPIX, NPIX, 1.0f, 0, 1);
    }
    // attention -> oth[n][512] fp16
    {
        dim3 grid(NPIX / 128, HEADS, BATCH);
        k_attn<<<grid, 256, ATT_SMEM>>>(pqkthi, pqktlo, pvth, poth);
    }
    // proj GEMM: A = pw hi/lo, B = oth single -> out[c][n] fp32 + bias
    {
        dim3 grid(CDIM / 128, NPIX / 128, BATCH);
        k_gemm_tc<<<grid, 256, GM_SMEM>>>(
            (const uint4*)ppwhi, (const uint4*)ppwlo, 0,
            (const uint4*)poth, sYT,
            nullptr, nullptr, out, proj_b,
            (long long)CDIM * NPIX, NPIX, 1.0f, 0, 0);
    }
}

// round 15
// speedup vs baseline: 2.4455x; 1.0026x over previous
#include <cuda_runtime.h>
#include <cuda_bf16.h>
#include <cuda_fp16.h>
#include <cstdint>

// ---------------------------------------------------------------------------
// LightweightSelfAttention  (B=2, C=512, H=W=64, heads=8, dh=64)
// All-tcgen05, fp16 data plane.
// R15: GEMM double-buffered (two-mbarrier scheme), chunked epilogue,
//      __launch_bounds__(256,2) -> occ 2. Attention unchanged from R14.
// ---------------------------------------------------------------------------

#if defined(__CUDA_ARCH_FEAT_SM103_ALL) || defined(__CUDA_ARCH_FEAT_SM100_ALL)
#define HAS_TC 1
#else
#define HAS_TC 0
#endif

#define BATCH 2
#define CDIM 512
#define HEADS 8
#define DH 64
#define NPIX 4096
#define TOTAL (BATCH*CDIM*NPIX)
#define QKD 1024

typedef unsigned short u16;
typedef unsigned long long u64;

__device__ u16 g_ythi[BATCH * NPIX * CDIM];
__device__ u16 g_ytlo[BATCH * NPIX * CDIM];
__device__ u16 g_whi[3 * CDIM * CDIM];
__device__ u16 g_wlo[3 * CDIM * CDIM];
__device__ u16 g_pwhi[CDIM * CDIM];
__device__ u16 g_pwlo[CDIM * CDIM];
__device__ u16 g_qkthi[BATCH * NPIX * QKD];
__device__ u16 g_qktlo[BATCH * NPIX * QKD];
__device__ u16 g_vth[BATCH * CDIM * NPIX];
__device__ u16 g_oth[BATCH * NPIX * CDIM];

#define ATT_SCALE_L2E 0.18033688f

// ---------------- helpers --------------------------------------------------
__device__ __forceinline__ uint32_t smem_u32(const void* p) {
    uint32_t a;
    asm("{ .reg .u64 t; cvta.to.shared.u64 t, %1; cvt.u32.u64 %0, t; }"
        : "=r"(a) : "l"(p));
    return a;
}
__device__ __forceinline__ u16 f2h(float x) {
    return __half_as_ushort(__float2half_rn(x));
}
__device__ __forceinline__ float h2f(u16 u) {
    return __half2float(__ushort_as_half(u));
}
#define SWZ(o) ((o) ^ (((o) >> 3) & 0x70))

#if HAS_TC
__device__ __forceinline__ unsigned elect1() {
    unsigned p;
    asm volatile("{\n\t.reg .pred p;\n\telect.sync _|p, 0xFFFFFFFF;\n\t"
                 "selp.b32 %0, 1, 0, p;\n\t}" : "=r"(p));
    return p;
}
__device__ __forceinline__ void mma_ss(uint32_t d, u64 a, u64 b, uint32_t id, uint32_t en) {
    asm volatile("{\n\t.reg .pred p;\n\tsetp.ne.u32 p, %5, 0;\n\t"
        "tcgen05.mma.cta_group::1.kind::f16 [%0], %1, %2, %3, {%4,%4,%4,%4}, p;\n\t}"
        :: "r"(d), "l"(a), "l"(b), "r"(id), "r"(0u), "r"(en) : "memory");
}
__device__ __forceinline__ void mma_ts(uint32_t d, uint32_t a, u64 b, uint32_t id, uint32_t en) {
    asm volatile("{\n\t.reg .pred p;\n\tsetp.ne.u32 p, %5, 0;\n\t"
        "tcgen05.mma.cta_group::1.kind::f16 [%0], [%1], %2, %3, {%4,%4,%4,%4}, p;\n\t}"
        :: "r"(d), "r"(a), "l"(b), "r"(id), "r"(0u), "r"(en) : "memory");
}
__device__ __forceinline__ void tc_commit(uint32_t mbar) {
    asm volatile("tcgen05.commit.cta_group::1.mbarrier::arrive::one.shared::cluster.b64 [%0];"
                 :: "r"(mbar) : "memory");
}
__device__ __forceinline__ void mbar_init1(uint32_t mbar) {
    asm volatile("mbarrier.init.shared.b64 [%0], %1;" :: "r"(mbar), "r"(1u) : "memory");
}
__device__ __forceinline__ void mbar_wait(uint32_t mbar, uint32_t ph) {
    asm volatile("{\n\t.reg .pred P1;\n\tLAB1_%=:\n\t"
        "mbarrier.try_wait.parity.acquire.cta.shared::cta.b64 P1, [%0], %1, 0x989680;\n\t"
        "@P1 bra.uni LAB2_%=;\n\tbra.uni LAB1_%=;\n\tLAB2_%=:\n\t}"
        :: "r"(mbar), "r"(ph) : "memory");
}
#define TCF_AFTER()  asm volatile("tcgen05.fence::after_thread_sync;" ::: "memory")
#define TCF_BEFORE() asm volatile("tcgen05.fence::before_thread_sync;" ::: "memory")
#define FPROXY()     asm volatile("fence.proxy.async.shared::cta;" ::: "memory")
#define TC_WAIT_LD() asm volatile("tcgen05.wait::ld.sync.aligned;" ::: "memory")
#define TC_WAIT_ST() asm volatile("tcgen05.wait::st.sync.aligned;" ::: "memory")

#define LDX32(r, ta) \
    asm volatile("tcgen05.ld.sync.aligned.32x32b.x32.b32 " \
        "{%0, %1, %2, %3, %4, %5, %6, %7, %8, %9, %10, %11, %12, %13, %14, %15, " \
        " %16, %17, %18, %19, %20, %21, %22, %23, %24, %25, %26, %27, %28, %29, %30, %31}, [%32];" \
        : "=r"((r)[0]),  "=r"((r)[1]),  "=r"((r)[2]),  "=r"((r)[3]), \
          "=r"((r)[4]),  "=r"((r)[5]),  "=r"((r)[6]),  "=r"((r)[7]), \
          "=r"((r)[8]),  "=r"((r)[9]),  "=r"((r)[10]), "=r"((r)[11]), \
          "=r"((r)[12]), "=r"((r)[13]), "=r"((r)[14]), "=r"((r)[15]), \
          "=r"((r)[16]), "=r"((r)[17]), "=r"((r)[18]), "=r"((r)[19]), \
          "=r"((r)[20]), "=r"((r)[21]), "=r"((r)[22]), "=r"((r)[23]), \
          "=r"((r)[24]), "=r"((r)[25]), "=r"((r)[26]), "=r"((r)[27]), \
          "=r"((r)[28]), "=r"((r)[29]), "=r"((r)[30]), "=r"((r)[31]) \
        : "r"(ta))

#define STX16(ta, r) \
    asm volatile("tcgen05.st.sync.aligned.32x32b.x16.b32 [%0], " \
        "{%1, %2, %3, %4, %5, %6, %7, %8, %9, %10, %11, %12, %13, %14, %15, %16};" \
        :: "r"(ta), \
           "r"((r)[0]),  "r"((r)[1]),  "r"((r)[2]),  "r"((r)[3]), \
           "r"((r)[4]),  "r"((r)[5]),  "r"((r)[6]),  "r"((r)[7]), \
           "r"((r)[8]),  "r"((r)[9]),  "r"((r)[10]), "r"((r)[11]), \
           "r"((r)[12]), "r"((r)[13]), "r"((r)[14]), "r"((r)[15]) \
        : "memory")

#define DESC_K  ((2ull<<61)|(1ull<<46)|(64ull<<32)|(1ull<<16))
__device__ __forceinline__ u64 mkdesc(uint32_t addr) {
    return DESC_K | ((u64)(addr >> 4) & 0x3FFF);
}
#define IDESC64H   ((1u<<4)|(8u<<17)|(8u<<24))
#define IDESC128H  ((1u<<4)|(16u<<17)|(8u<<24))
#endif  // HAS_TC

// ---------------- 1) fused dwconv + transpose + fp16 split -----------------
__global__ void k_dwt(const float* __restrict__ x, const float* __restrict__ w,
                      u16* __restrict__ thi, u16* __restrict__ tlo) {
    __shared__ float t[32][33];
    int b = blockIdx.z;
    int c0 = blockIdx.y * 32, n0 = blockIdx.x * 32;
    int hh = n0 >> 6, w0 = n0 & 63;
    int tx = threadIdx.x, ty = threadIdx.y;
#pragma unroll
    for (int j = 0; j < 4; j++) {
        int c = c0 + ty + j * 8;
        const float* xb = x + ((long long)(b * CDIM + c)) * NPIX;
        const float* wc = w + c * 9;
        int ww = w0 + tx;
        float s = 0.f;
#pragma unroll
        for (int i = 0; i < 3; i++) {
            int h2 = hh + i - 1;
            if ((unsigned)h2 < 64u) {
#pragma unroll
                for (int jj = 0; jj < 3; jj++) {
                    int w2 = ww + jj - 1;
                    if ((unsigned)w2 < 64u) s += xb[h2 * 64 + w2] * wc[i * 3 + jj];
                }
            }
        }
        t[ty + j * 8][tx] = s;
    }
    __syncthreads();
    long long zt = (long long)b * NPIX * CDIM;
#pragma unroll
    for (int j = 0; j < 4; j++) {
        int n = n0 + ty + j * 8;
        float v = t[tx][ty + j * 8];
        u16 h = f2h(v);
        thi[zt + (long long)n * CDIM + c0 + tx] = h;
        tlo[zt + (long long)n * CDIM + c0 + tx] = f2h(v - h2f(h));
    }
}

// ---------------- 2) fp32 -> fp16 hi/lo (weights) --------------------------
__global__ void k_cvt(const float* __restrict__ src, u16* __restrict__ hi,
                      u16* __restrict__ lo, int n) {
    int i = blockIdx.x * blockDim.x + threadIdx.x;
    if (i >= n) return;
    float v = src[i];
    u16 h = f2h(v);
    hi[i] = h;
    lo[i] = f2h(v - h2f(h));
}

// ---------------- 4/5/7) tcgen05 GEMM: 128x128, double-buffered ------------
// Two mbarriers (R7 scheme): commit(kc)->mbar[kc&1]; wait commit(kc-2) at
// per-barrier parity ((kc-2)>>1)&1; drain = parity 1 on both.
#define GM_TMEMPTR 0
#define GM_MBAR0 8
#define GM_MBAR1 16
#define GM_BUF(b) (1024 + (b) * 49152)
#define GM_AHI 0
#define GM_ALO 16384
#define GM_B   32768
#define GM_SMEM (1024 + 2 * 49152)

__global__ void __launch_bounds__(256, 2) k_gemm_tc(
    const uint4* __restrict__ Ahi, const uint4* __restrict__ Alo, long long sA,
    const uint4* __restrict__ B, long long sB,
    u16* __restrict__ Ohi, u16* __restrict__ Olo,
    float* __restrict__ Ofp, const float* __restrict__ bias,
    long long sO, int ldo, float scale_q, int qcols, int out_mode) {
#if HAS_TC
    extern __shared__ char sm[];
    uint32_t sb = smem_u32(sm);
    int tid = threadIdx.x, wid = tid >> 5;
    int mrow0 = blockIdx.x * 128;
    int brow0 = blockIdx.y * 128;
    const uint4* Ah = Ahi + blockIdx.z * sA + (long long)mrow0 * 64;
    const uint4* Al = Alo + blockIdx.z * sA + (long long)mrow0 * 64;
    const uint4* Bb = B + blockIdx.z * sB + (long long)brow0 * 64;

    if (wid == 0) {
        asm volatile("tcgen05.alloc.cta_group::1.sync.aligned.shared::cta.b32 [%0], %1;"
                     :: "r"(sb + GM_TMEMPTR), "r"(128u) : "memory");
    }
    if (tid == 0) { mbar_init1(sb + GM_MBAR0); mbar_init1(sb + GM_MBAR1); }
    __syncthreads();
    uint32_t tb;
    asm volatile("ld.shared.b32 %0, [%1];" : "=r"(tb) : "r"(sb + GM_TMEMPTR));

#pragma unroll 1
    for (int kc = 0; kc < 8; kc++) {
        int buf = kc & 1;
        uint32_t mb = sb + (buf ? GM_MBAR1 : GM_MBAR0);
        if (kc >= 2) mbar_wait(mb, ((kc - 2) >> 1) & 1);   // buffer free
        uint32_t base = GM_BUF(buf);
        int k8 = kc * 8;
#pragma unroll
        for (int l = 0; l < 4; l++) {
            int idx = tid + l * 256;
            int r = idx >> 3, j = idx & 7;
            uint32_t off = SWZ((uint32_t)(r * 128 + j * 16));
            *(uint4*)(sm + base + GM_AHI + off) = Ah[r * 64 + k8 + j];
            *(uint4*)(sm + base + GM_ALO + off) = Al[r * 64 + k8 + j];
            *(uint4*)(sm + base + GM_B + off)   = Bb[r * 64 + k8 + j];
        }
        FPROXY();
        __syncthreads();
        if (wid == 0) {
            if (elect1()) {
                u64 dAhi = mkdesc(sb + base + GM_AHI);
                u64 dAlo = mkdesc(sb + base + GM_ALO);
                u64 dB   = mkdesc(sb + base + GM_B);
#pragma unroll
                for (int ks = 0; ks < 4; ks++)
                    mma_ss(tb, dAhi + ks * 2, dB + ks * 2, IDESC128H, !(kc == 0 && ks == 0));
#pragma unroll
                for (int ks = 0; ks < 4; ks++)
                    mma_ss(tb, dAlo + ks * 2, dB + ks * 2, IDESC128H, 1u);
                tc_commit(mb);
            }
        }
    }
    mbar_wait(sb + GM_MBAR0, 1);   // commit kc=6 (phase 3)
    mbar_wait(sb + GM_MBAR1, 1);   // commit kc=7 (phase 3)

    if (tid < 128) {
        TCF_AFTER();
        int m = mrow0 + tid;
        long long obase0 = blockIdx.z * sO + (long long)m * ldo + brow0;
        // chunked epilogue: 4 x 32 columns, bounded register footprint
#pragma unroll 1
        for (int ch = 0; ch < 4; ch++) {
            uint32_t d[32];
            LDX32(d, tb + ch * 32);
            TC_WAIT_LD();
            long long obase = obase0 + ch * 32;
            if (Ofp) {
                float bv = bias ? bias[m] : 0.f;
#pragma unroll
                for (int j = 0; j < 8; j++) {
                    float4 v = make_float4(__uint_as_float(d[4 * j]) + bv,
                                           __uint_as_float(d[4 * j + 1]) + bv,
                                           __uint_as_float(d[4 * j + 2]) + bv,
                                           __uint_as_float(d[4 * j + 3]) + bv);
                    *(float4*)(Ofp + obase + 4 * j) = v;
                }
            } else if (out_mode == 2 && brow0 < qcols) {
                uint32_t whi[16], wlo[16];
#pragma unroll
                for (int j = 0; j < 16; j++) {
                    float a = __uint_as_float(d[2 * j]) * scale_q;
                    float c = __uint_as_float(d[2 * j + 1]) * scale_q;
                    u16 ah = f2h(a), chh = f2h(c);
                    whi[j] = (uint32_t)ah | ((uint32_t)chh << 16);
                    u16 al = f2h(a - h2f(ah)), cl = f2h(c - h2f(chh));
                    wlo[j] = (uint32_t)al | ((uint32_t)cl << 16);
                }
#pragma unroll
                for (int j = 0; j < 4; j++) {
                    *(uint4*)(Ohi + obase + 8 * j) = *(uint4*)&whi[4 * j];
                    *(uint4*)(Olo + obase + 8 * j) = *(uint4*)&wlo[4 * j];
                }
            } else {
                uint32_t w[16];
#pragma unroll
                for (int j = 0; j < 16; j++) {
                    u16 a = f2h(__uint_as_float(d[2 * j]));
                    u16 c = f2h(__uint_as_float(d[2 * j + 1]));
                    w[j] = (uint32_t)a | ((uint32_t)c << 16);
                }
#pragma unroll
                for (int j = 0; j < 4; j++)
                    *(uint4*)(Ohi + obase + 8 * j) = *(uint4*)&w[4 * j];
            }
        }
    }
    __syncthreads();
    if (wid == 0) {
        asm volatile("tcgen05.dealloc.cta_group::1.sync.aligned.b32 %0, %1;"
                     :: "r"(tb), "r"(128u));
    }
#else
    // compile-only fallback
    int tid = threadIdx.x;
    const u16* Ah = (const u16*)(Ahi + blockIdx.z * sA) + (long long)blockIdx.x * 128 * 512;
    const u16* Al = (const u16*)(Alo + blockIdx.z * sA) + (long long)blockIdx.x * 128 * 512;
    const u16* Bb = (const u16*)(B + blockIdx.z * sB) + (long long)blockIdx.y * 128 * 512;
    for (int e = tid; e < 128 * 128; e += 256) {
        int r = e >> 7, j = e & 127;
        float s = 0.f;
        for (int k = 0; k < 512; k++)
            s += (h2f(Ah[r * 512 + k]) + h2f(Al[r * 512 + k])) * h2f(Bb[j * 512 + k]);
        int m = blockIdx.x * 128 + r;
        long long obase = blockIdx.z * sO + (long long)m * ldo + blockIdx.y * 128 + j;
        if (Ofp) {
            Ofp[obase] = s + (bias ? bias[m] : 0.f);
        } else if (out_mode == 2 && blockIdx.y * 128 < qcols) {
            s *= scale_q;
            u16 hh = f2h(s);
            Ohi[obase] = hh;
            Olo[obase] = f2h(s - h2f(hh));
        } else {
            Ohi[obase] = f2h(s);
        }
    }
#endif
}

// ---------------- 6) attention (R14-exact) ---------------------------------
#define SM_TMEMPTR 0
#define SM_MBAR 8
#define SM_DEN 1024
#define SM_QHI 2048
#define SM_QLO (SM_QHI + 16384)
#define SM_KH(b) (34816 + (b) * 8192)
#define SM_VH(b) (51200 + (b) * 8192)
#define ATT_SMEM 67584

#define TM_S(b) ((b) * 64)
#define TM_O 128
#define TM_PH 192
#define ATT_TMCOLS 256

__global__ void __launch_bounds__(256) k_attn(
    const u16* __restrict__ qkthi, const u16* __restrict__ qktlo,
    const u16* __restrict__ vth, u16* __restrict__ oth) {
#if HAS_TC
    extern __shared__ char sm[];
    uint32_t sb = smem_u32(sm);
    int tid = threadIdx.x, wid = tid >> 5;
    int half = wid >> 2;
    uint32_t lofs = (uint32_t)(wid & 3) << 21;
    int n0 = blockIdx.x * 128;
    int h = blockIdx.y, b = blockIdx.z;
    const uint4* qh4 = (const uint4*)qkthi + (long long)b * NPIX * 128;
    const uint4* ql4 = (const uint4*)qktlo + (long long)b * NPIX * 128;
    const uint4* vh4 = (const uint4*)vth + ((long long)b * CDIM + h * DH) * 512;

    if (wid == 0) {
        asm volatile("tcgen05.alloc.cta_group::1.sync.aligned.shared::cta.b32 [%0], %1;"
                     :: "r"(sb + SM_TMEMPTR), "r"((uint32_t)ATT_TMCOLS) : "memory");
    }
    if (tid == 0) mbar_init1(sb + SM_MBAR);
    __syncthreads();
    uint32_t tb;
    asm volatile("ld.shared.b32 %0, [%1];" : "=r"(tb) : "r"(sb + SM_TMEMPTR));

    int r0a = tid >> 3, ja = tid & 7;
    int r0b = (tid + 256) >> 3, jb = (tid + 256) & 7;
    uint32_t offa = SWZ((uint32_t)(r0a * 128 + ja * 16));
    uint32_t offb = SWZ((uint32_t)(r0b * 128 + jb * 16));

#pragma unroll
    for (int l = 0; l < 4; l++) {
        int idx = tid + l * 256;
        int r = idx >> 3, j = idx & 7;
        uint32_t off = SWZ((uint32_t)(r * 128 + j * 16));
        *(uint4*)(sm + SM_QHI + off) = qh4[(long long)(n0 + r) * 128 + h * 8 + j];
        *(uint4*)(sm + SM_QLO + off) = ql4[(long long)(n0 + r) * 128 + h * 8 + j];
    }
#pragma unroll
    for (int l = 0; l < 2; l++) {
        int idx = tid + l * 256;
        int r = idx >> 3, j = idx & 7;
        uint32_t off = SWZ((uint32_t)(r * 128 + j * 16));
        *(uint4*)(sm + SM_KH(0) + off) = qh4[(long long)r * 128 + 64 + h * 8 + j];
        *(uint4*)(sm + SM_KH(1) + off) = qh4[(long long)(64 + r) * 128 + 64 + h * 8 + j];
        *(uint4*)(sm + SM_VH(0) + off) = vh4[(long long)r * 512 + j];
    }
    FPROXY();
    __syncthreads();

    u64 aQhi = mkdesc(sb + SM_QHI);
    u64 aQlo = mkdesc(sb + SM_QLO);

    if (wid == 0) {
        if (elect1()) {
            u64 dK = mkdesc(sb + SM_KH(0));
#pragma unroll
            for (int ks = 0; ks < 4; ks++)
                mma_ss(tb + TM_S(0), aQhi + ks * 2, dK + ks * 2, IDESC64H, ks > 0);
#pragma unroll
            for (int ks = 0; ks < 4; ks++)
                mma_ss(tb + TM_S(0), aQlo + ks * 2, dK + ks * 2, IDESC64H, 1u);
            tc_commit(sb + SM_MBAR);
        }
    }

    float den = 0.f;
    uint32_t ph = 0;

#pragma unroll 1
    for (int t = 0; t < 64; t++) {
        mbar_wait(sb + SM_MBAR, ph); ph ^= 1;
        TCF_AFTER();

        if (t < 63 && wid == 0) {
            if (elect1()) {
                int nb = (t + 1) & 1;
                u64 dK = mkdesc(sb + SM_KH(nb));
#pragma unroll
                for (int ks = 0; ks < 4; ks++)
                    mma_ss(tb + TM_S(nb), aQhi + ks * 2, dK + ks * 2, IDESC64H, ks > 0);
#pragma unroll
                for (int ks = 0; ks < 4; ks++)
                    mma_ss(tb + TM_S(nb), aQlo + ks * 2, dK + ks * 2, IDESC64H, 1u);
            }
        }

        uint4 kra, krb, vra, vrb;
        bool hask = (t <= 61), hasv = (t <= 62);
        if (hask) {
            int m2 = (t + 2) * 64;
            kra = qh4[(long long)(m2 + r0a) * 128 + 64 + h * 8 + ja];
            krb = qh4[(long long)(m2 + r0b) * 128 + 64 + h * 8 + jb];
        }
        if (hasv) {
            int m1 = (t + 1) * 8;
            vra = vh4[(long long)r0a * 512 + m1 + ja];
            vrb = vh4[(long long)r0b * 512 + m1 + jb];
        }

        {
            uint32_t sr[32];
            LDX32(sr, tb + TM_S(t & 1) + half * 32);
            TC_WAIT_LD();
            uint32_t w[16];
            float dsum = 0.f;
#pragma unroll
            for (int j = 0; j < 16; j++) {
                uint32_t s2, p2;
                asm("cvt.rn.f16x2.f32 %0, %1, %2;" : "=r"(s2)
                    : "f"(__uint_as_float(sr[2 * j + 1])), "f"(__uint_as_float(sr[2 * j])));
                asm("ex2.approx.f16x2 %0, %1;" : "=r"(p2) : "r"(s2));
                w[j] = p2;
                dsum += h2f((u16)(p2 & 0xFFFF)) + h2f((u16)(p2 >> 16));
            }
            den += dsum;
            STX16(tb + TM_PH + half * 16 + lofs, w);
            TC_WAIT_ST();
        }

        if (hask) {
            *(uint4*)(sm + SM_KH(t & 1) + offa) = kra;
            *(uint4*)(sm + SM_KH(t & 1) + offb) = krb;
        }
        if (hasv) {
            *(uint4*)(sm + SM_VH((t + 1) & 1) + offa) = vra;
            *(uint4*)(sm + SM_VH((t + 1) & 1) + offb) = vrb;
        }
        TCF_BEFORE();
        FPROXY();
        __syncthreads();

        if (wid == 0) {
            if (elect1()) {
                TCF_AFTER();
                u64 dVh = mkdesc(sb + SM_VH(t & 1));
#pragma unroll
                for (int ks = 0; ks < 4; ks++)
                    mma_ts(tb + TM_O, tb + TM_PH + ks * 8, dVh + ks * 2, IDESC64H,
                           (t > 0 || ks > 0) ? 1u : 0u);
                tc_commit(sb + SM_MBAR);
            }
        }
    }
    mbar_wait(sb + SM_MBAR, ph); ph ^= 1;

    *(float*)(sm + SM_DEN + tid * 4) = den;
    __syncthreads();

    if (tid < 128) {
        TCF_AFTER();
        uint32_t orr[64];
        LDX32(orr, tb + TM_O);
        LDX32(orr + 32, tb + TM_O + 32);
        TC_WAIT_LD();
        float dtot = *(float*)(sm + SM_DEN + tid * 4) +
                     *(float*)(sm + SM_DEN + (tid + 128) * 4);
        float inv = 1.0f / dtot;
        long long obase = ((long long)b * NPIX + n0 + tid) * CDIM + h * DH;
        uint32_t w[32];
#pragma unroll
        for (int j = 0; j < 32; j++) {
            u16 a = f2h(__uint_as_float(orr[2 * j]) * inv);
            u16 c = f2h(__uint_as_float(orr[2 * j + 1]) * inv);
            w[j] = (uint32_t)a | ((uint32_t)c << 16);
        }
#pragma unroll
        for (int j = 0; j < 8; j++)
            *(uint4*)(oth + obase + 8 * j) = *(uint4*)&w[4 * j];
    }
    __syncthreads();
    if (wid == 0) {
        asm volatile("tcgen05.dealloc.cta_group::1.sync.aligned.b32 %0, %1;"
                     :: "r"(tb), "r"((uint32_t)ATT_TMCOLS));
    }
#else
    // compile-only fallback
    int tid = threadIdx.x;
    if (tid >= 128) return;
    int n0 = blockIdx.x * 128;
    int h = blockIdx.y, b = blockIdx.z;
    long long qb = (long long)b * NPIX * QKD;
    int r = n0 + tid;
    float q[64], o[64], den = 0.f;
#pragma unroll
    for (int d = 0; d < 64; d++) {
        q[d] = h2f(qkthi[qb + (long long)r * QKD + h * 64 + d]) +
               h2f(qktlo[qb + (long long)r * QKD + h * 64 + d]);
        o[d] = 0.f;
    }
    for (int key = 0; key < NPIX; key++) {
        float s = 0.f;
        for (int d = 0; d < 64; d++)
            s += q[d] * h2f(qkthi[qb + (long long)key * QKD + 512 + h * 64 + d]);
        float p = h2f(f2h(exp2f(h2f(f2h(s)))));
        den += p;
        for (int d = 0; d < 64; d++) {
            long long vi = ((long long)b * CDIM + h * 64 + d) * NPIX + key;
            o[d] += p * h2f(vth[vi]);
        }
    }
    long long ob = ((long long)b * NPIX + r) * CDIM + h * 64;
    for (int d = 0; d < 64; d++) oth[ob + d] = f2h(o[d] / den);
#endif
}

// ---------------------------------------------------------------------------
extern "C" void kernel_launch(void* const* d_in, const int* in_sizes, int n_in,
                              void* d_out, int out_size) {
    const float* x      = (const float*)d_in[0];
    const float* dw_w   = (const float*)d_in[1];
    const float* qkv_w  = (const float*)d_in[2];
    const float* proj_w = (const float*)d_in[3];
    const float* proj_b = (const float*)d_in[4];
    float* out = (float*)d_out;

    u16 *pythi, *pytlo, *pwhi, *pwlo, *ppwhi, *ppwlo;
    u16 *pqkthi, *pqktlo, *pvth, *poth;
    cudaGetSymbolAddress((void**)&pythi,  g_ythi);
    cudaGetSymbolAddress((void**)&pytlo,  g_ytlo);
    cudaGetSymbolAddress((void**)&pwhi,   g_whi);
    cudaGetSymbolAddress((void**)&pwlo,   g_wlo);
    cudaGetSymbolAddress((void**)&ppwhi,  g_pwhi);
    cudaGetSymbolAddress((void**)&ppwlo,  g_pwlo);
    cudaGetSymbolAddress((void**)&pqkthi, g_qkthi);
    cudaGetSymbolAddress((void**)&pqktlo, g_qktlo);
    cudaGetSymbolAddress((void**)&pvth,   g_vth);
    cudaGetSymbolAddress((void**)&poth,   g_oth);

    cudaFuncSetAttribute(k_attn, cudaFuncAttributeMaxDynamicSharedMemorySize, ATT_SMEM);
    cudaFuncSetAttribute(k_gemm_tc, cudaFuncAttributeMaxDynamicSharedMemorySize, GM_SMEM);

    // 1) fused dwconv + transpose + split
    {
        dim3 grid(NPIX / 32, CDIM / 32, BATCH);
        k_dwt<<<grid, dim3(32, 8)>>>(x, dw_w, pythi, pytlo);
    }
    // 2) weight conversions
    k_cvt<<<(3 * CDIM * CDIM + 255) / 256, 256>>>(qkv_w, pwhi, pwlo, 3 * CDIM * CDIM);
    k_cvt<<<(CDIM * CDIM + 255) / 256, 256>>>(proj_w, ppwhi, ppwlo, CDIM * CDIM);

    long long sYT = (long long)NPIX * CDIM / 8;

    // qk GEMM
    {
        dim3 grid(NPIX / 128, QKD / 128, BATCH);
        k_gemm_tc<<<grid, 256, GM_SMEM>>>(
            (const uint4*)pythi, (const uint4*)pytlo, sYT,
            (const uint4*)pwhi, 0,
            pqkthi, pqktlo, nullptr, nullptr,
            (long long)NPIX * QKD, QKD, ATT_SCALE_L2E, 512, 2);
    }
    // V GEMM
    {
        dim3 grid(CDIM / 128, NPIX / 128, BATCH);
        k_gemm_tc<<<grid, 256, GM_SMEM>>>(
            (const uint4*)(pwhi + 1024 * CDIM), (const uint4*)(pwlo + 1024 * CDIM), 0,
            (const uint4*)pythi, sYT,
            pvth, nullptr, nullptr, nullptr,
            (long long)CDIM * NPIX, NPIX, 1.0f, 0, 1);
    }
    // attention
    {
        dim3 grid(NPIX / 128, HEADS, BATCH);
        k_attn<<<grid, 256, ATT_SMEM>>>(pqkthi, pqktlo, pvth, poth);
    }
    // proj GEMM
    {
        dim3 grid(CDIM / 128, NPIX / 128, BATCH);
        k_gemm_tc<<<grid, 256, GM_SMEM>>>(
            (const uint4*)ppwhi, (const uint4*)ppwlo, 0,
            (const uint4*)poth, sYT,
            nullptr, nullptr, out, proj_b,
            (long long)CDIM * NPIX, NPIX, 1.0f, 0, 0);
    }
}